// round 5
// baseline (speedup 1.0000x reference)
#include <cuda_runtime.h>
#include <cuda_bf16.h>
#include <stdint.h>
#include <math.h>

#define N_NODES 50000
#define N_EDGES 200000
#define D_IN    128
#define DD      256
#define N_LAYERS 4
#define N_RELS  4
#define NUM_M   1024
#define NUM_R   64
#define N_ALL   (NUM_R + NUM_M)
#define GW      1280
#define MPAD    (N_NODES + 128)

__device__ float g_featsB[N_NODES * DD];
__device__ float g_G[(size_t)N_NODES * GW];
__device__ __nv_bfloat16 g_Wh[N_LAYERS * GW * 256];
__device__ __nv_bfloat16 g_Wl[N_LAYERS * GW * 256];
__device__ __nv_bfloat16 g_nWh[256 * D_IN];
__device__ __nv_bfloat16 g_nWl[256 * D_IN];
__device__ __nv_bfloat16 g_xh[(size_t)MPAD * D_IN];
__device__ __nv_bfloat16 g_xl[(size_t)MPAD * D_IN];
__device__ __nv_bfloat16 g_Ah[(size_t)MPAD * DD];
__device__ __nv_bfloat16 g_Al[(size_t)MPAD * DD];
__device__ int   g_cnt[N_RELS * N_NODES];
__device__ int   g_deg[N_NODES];
__device__ int   g_off[N_NODES + 1];
__device__ int   g_cursor[N_NODES];
__device__ uint2 g_epack[N_EDGES];   // {offset into g_G, inv_cnt bits}
__device__ int   g_start[NUM_M + 1];
__device__ float g_Hall[N_ALL * DD];
__device__ float g_pu[N_ALL * 512];
__device__ float g_qz[N_ALL * 512];
__device__ float g_u[N_ALL * DD];
__device__ float g_zM[NUM_M * DD];
__device__ float g_zR[NUM_R * DD];
__device__ float g_An[NUM_M * NUM_R];
__device__ float g_repM[NUM_M * 512];
__device__ float g_repR[NUM_R * 512];
__device__ float g_hidM[NUM_M * 256];
__device__ float g_hidR[NUM_R * 256];
__device__ float g_acc[4];

__host__ __device__ __forceinline__ uint32_t rotl32(uint32_t x, int d) {
    return (x << d) | (x >> (32 - d));
}
__host__ __device__ __forceinline__ void tf2x32(uint32_t k0, uint32_t k1,
                                                uint32_t x0, uint32_t x1,
                                                uint32_t& o0, uint32_t& o1) {
    uint32_t ks2 = k0 ^ k1 ^ 0x1BD11BDAu;
    x0 += k0; x1 += k1;
#define TF_RND(R) { x0 += x1; x1 = rotl32(x1, R); x1 ^= x0; }
    TF_RND(13) TF_RND(15) TF_RND(26) TF_RND(6)
    x0 += k1;  x1 += ks2 + 1u;
    TF_RND(17) TF_RND(29) TF_RND(16) TF_RND(24)
    x0 += ks2; x1 += k0 + 2u;
    TF_RND(13) TF_RND(15) TF_RND(26) TF_RND(6)
    x0 += k0;  x1 += k1 + 3u;
    TF_RND(17) TF_RND(29) TF_RND(16) TF_RND(24)
    x0 += k1;  x1 += ks2 + 4u;
    TF_RND(13) TF_RND(15) TF_RND(26) TF_RND(6)
    x0 += ks2; x1 += k0 + 5u;
#undef TF_RND
    o0 = x0; o1 = x1;
}
__device__ __forceinline__ uint32_t rbits(uint32_t k0, uint32_t k1, uint32_t i) {
    uint32_t o0, o1; tf2x32(k0, k1, 0u, i, o0, o1); return o0 ^ o1;
}
__device__ __forceinline__ float erfinv_xla(float x) {
    float w = -log1pf(-x * x), p;
    if (w < 5.0f) {
        w -= 2.5f;
        p = 2.81022636e-08f;
        p = fmaf(p, w, 3.43273939e-07f);  p = fmaf(p, w, -3.5233877e-06f);
        p = fmaf(p, w, -4.39150654e-06f); p = fmaf(p, w, 0.00021858087f);
        p = fmaf(p, w, -0.00125372503f);  p = fmaf(p, w, -0.00417768164f);
        p = fmaf(p, w, 0.246640727f);     p = fmaf(p, w, 1.50140941f);
    } else {
        w = sqrtf(w) - 3.0f;
        p = -0.000200214257f;
        p = fmaf(p, w, 0.000100950558f);  p = fmaf(p, w, 0.00134934322f);
        p = fmaf(p, w, -0.00367342844f);  p = fmaf(p, w, 0.00573950773f);
        p = fmaf(p, w, -0.0076224613f);   p = fmaf(p, w, 0.00943887047f);
        p = fmaf(p, w, 1.00167406f);      p = fmaf(p, w, 2.83297682f);
    }
    return p * x;
}
__device__ __forceinline__ float u01(uint32_t b) {
    return __uint_as_float((b >> 9) | 0x3f800000u) - 1.0f;
}
__device__ __forceinline__ float nrm(uint32_t b) {
    const float LO = -0.99999994f;
    float v = u01(b) * 2.0f + LO;
    v = fmaxf(LO, v);
    return 1.41421356f * erfinv_xla(v);
}
__device__ __forceinline__ float unif(uint32_t b) {
    const float MN = 1e-06f;
    float v = u01(b) * (0.999999f - MN) + MN;
    return fmaxf(MN, v);
}

__global__ void k_zero_init() {
    int i = blockIdx.x * blockDim.x + threadIdx.x;
    if (i < N_RELS * N_NODES) g_cnt[i] = 0;
    if (i < N_NODES) g_deg[i] = 0;
    if (i < 4) g_acc[i] = 0.0f;
}
__global__ void k_count(const int* __restrict__ ei, const int* __restrict__ et) {
    int e = blockIdx.x * blockDim.x + threadIdx.x;
    if (e >= N_EDGES) return;
    int d = ei[N_EDGES + e];
    atomicAdd(&g_cnt[et[e] * N_NODES + d], 1);
    atomicAdd(&g_deg[d], 1);
}
__global__ void k_scan() {
    __shared__ int part[1024];
    int tid = threadIdx.x;
    const int chunk = (N_NODES + 1023) / 1024;
    int lo = tid * chunk, hi = min(lo + chunk, N_NODES);
    int s = 0;
    for (int i = lo; i < hi; i++) s += g_deg[i];
    part[tid] = s;
    __syncthreads();
    for (int o = 1; o < 1024; o <<= 1) {
        int v = (tid >= o) ? part[tid - o] : 0;
        __syncthreads(); part[tid] += v; __syncthreads();
    }
    int run = part[tid] - s;
    for (int i = lo; i < hi; i++) { g_off[i] = run; g_cursor[i] = run; run += g_deg[i]; }
    if (tid == 1023) g_off[N_NODES] = run;
}
__global__ void k_scatter(const int* __restrict__ ei, const int* __restrict__ et) {
    int e = blockIdx.x * blockDim.x + threadIdx.x;
    if (e >= N_EDGES) return;
    int sn = ei[e], d = ei[N_EDGES + e], r = et[e];
    int p = atomicAdd(&g_cursor[d], 1);
    float inv = 1.0f / (float)g_cnt[r * N_NODES + d];
    g_epack[p] = make_uint2((uint32_t)(sn * GW + 256 + (r << 8)), __float_as_uint(inv));
}
__global__ void k_wsplit(const float* __restrict__ Wroot, const float* __restrict__ Wr) {
    int idx = blockIdx.x * blockDim.x + threadIdx.x;
    if (idx >= N_LAYERS * GW * 256) return;
    int l = idx / (GW * 256), rem = idx % (GW * 256);
    int n = rem / 256, k = rem % 256;
    float v;
    if (n < 256) v = Wroot[((size_t)l * 256 + k) * 256 + n];
    else {
        int r = (n >> 8) - 1, h = n & 255;
        v = Wr[(((size_t)l * 4 + r) * 256 + k) * 256 + h];
    }
    __nv_bfloat16 hi = __float2bfloat16(v);
    g_Wh[idx] = hi;
    g_Wl[idx] = __float2bfloat16(v - __bfloat162float(hi));
}
__global__ void k_wsplitN(const float* __restrict__ nodeW) {
    int idx = blockIdx.x * blockDim.x + threadIdx.x;
    if (idx >= 256 * D_IN) return;
    int n = idx / D_IN, k = idx % D_IN;
    float v = nodeW[k * 256 + n];
    __nv_bfloat16 hi = __float2bfloat16(v);
    g_nWh[idx] = hi;
    g_nWl[idx] = __float2bfloat16(v - __bfloat162float(hi));
}
__global__ void k_asplit(const float* __restrict__ src, __nv_bfloat16* __restrict__ h,
                         __nv_bfloat16* __restrict__ l, int n) {
    int i = blockIdx.x * blockDim.x + threadIdx.x;
    if (i >= n) return;
    float v = src[i];
    __nv_bfloat16 hi = __float2bfloat16(v);
    h[i] = hi;
    l[i] = __float2bfloat16(v - __bfloat162float(hi));
}

// ---------------- pipelined bf16 tensor-core GEMM, BM=BN=128, BK=32, 2 stages ----------------
__device__ __forceinline__ void ldm4(uint32_t a, uint32_t& r0, uint32_t& r1,
                                     uint32_t& r2, uint32_t& r3) {
    asm volatile("ldmatrix.sync.aligned.m8n8.x4.shared.b16 {%0,%1,%2,%3}, [%4];"
                 : "=r"(r0), "=r"(r1), "=r"(r2), "=r"(r3) : "r"(a));
}
__device__ __forceinline__ void mma16816(float* c, const uint32_t* a, const uint32_t* b) {
    asm volatile("mma.sync.aligned.m16n8k16.row.col.f32.bf16.bf16.f32 "
                 "{%0,%1,%2,%3},{%4,%5,%6,%7},{%8,%9},{%0,%1,%2,%3};"
                 : "+f"(c[0]), "+f"(c[1]), "+f"(c[2]), "+f"(c[3])
                 : "r"(a[0]), "r"(a[1]), "r"(a[2]), "r"(a[3]), "r"(b[0]), "r"(b[1]));
}
__device__ __forceinline__ void cp16(uint32_t dst, const void* src) {
    asm volatile("cp.async.cg.shared.global [%0], [%1], 16;" :: "r"(dst), "l"(src));
}
// stage layout (elements): Ah 0, Al 5120, Bh 10240, Bl 15360; stage stride 20480 (40960 B)
#define LOAD_STAGE(s, kq)                                              \
    do {                                                               \
        uint32_t st_ = sm + (s) * 40960;                               \
        _Pragma("unroll")                                              \
        for (int q_ = 0; q_ < 2; q_++) {                               \
            int col_ = (c0 + q_) * 8;                                  \
            uint32_t dd_ = st_ + (row * 40 + col_) * 2;                \
            cp16(dd_,         Agh + (kq) + col_);                      \
            cp16(dd_ + 10240, Agl + (kq) + col_);                      \
            cp16(dd_ + 20480, Bgh + (kq) + col_);                      \
            cp16(dd_ + 30720, Bgl + (kq) + col_);                      \
        }                                                              \
    } while (0)

__global__ void __launch_bounds__(256, 2)
k_bmma(const __nv_bfloat16* __restrict__ Ah, const __nv_bfloat16* __restrict__ Al,
       const __nv_bfloat16* __restrict__ Bh, const __nv_bfloat16* __restrict__ Bl,
       const float* __restrict__ bias, float* __restrict__ C,
       __nv_bfloat16* __restrict__ oh, __nv_bfloat16* __restrict__ ol,
       int M, int N, int K, int relu_out) {
    extern __shared__ __align__(16) __nv_bfloat16 dsm[];
    uint32_t sm = (uint32_t)__cvta_generic_to_shared(dsm);
    int tid = threadIdx.x, lane = tid & 31, wid = tid >> 5;
    int wm = (wid >> 2) * 64, wn = (wid & 3) * 32;
    int bm = blockIdx.y * 128, bn = blockIdx.x * 128;
    int row = tid >> 1, c0 = (tid & 1) * 2;
    const __nv_bfloat16* Agh = Ah + (size_t)(bm + row) * K;
    const __nv_bfloat16* Agl = Al + (size_t)(bm + row) * K;
    const __nv_bfloat16* Bgh = Bh + (size_t)(bn + row) * K;
    const __nv_bfloat16* Bgl = Bl + (size_t)(bn + row) * K;

    float acc[4][4][4];
#pragma unroll
    for (int i = 0; i < 4; i++)
#pragma unroll
        for (int j = 0; j < 4; j++)
#pragma unroll
            for (int q = 0; q < 4; q++) acc[i][j][q] = 0.f;

    LOAD_STAGE(0, 0);
    asm volatile("cp.async.commit_group;");

    int cur = 0;
    for (int k0 = 0; k0 < K; k0 += 32) {
        int nxt = k0 + 32;
        if (nxt < K) LOAD_STAGE(cur ^ 1, nxt);
        asm volatile("cp.async.commit_group;");
        asm volatile("cp.async.wait_group 1;");
        __syncthreads();
        uint32_t st = sm + cur * 40960;
#pragma unroll
        for (int kk = 0; kk < 32; kk += 16) {
            // B fragments first (16 regs live)
            uint32_t bh[4][2], bl[4][2];
            int brow = wn + (lane & 7) + ((lane >> 4) & 1) * 8;
            int bcol = kk + ((lane >> 3) & 1) * 8;
#pragma unroll
            for (int nb = 0; nb < 2; nb++) {
                uint32_t off = ((brow + nb * 16) * 40 + bcol) * 2;
                ldm4(st + 20480 + off, bh[2 * nb][0], bh[2 * nb][1], bh[2 * nb + 1][0], bh[2 * nb + 1][1]);
                ldm4(st + 30720 + off, bl[2 * nb][0], bl[2 * nb][1], bl[2 * nb + 1][0], bl[2 * nb + 1][1]);
            }
            int arow = wm + (lane & 7) + ((lane >> 3) & 1) * 8;
            int acol = kk + ((lane >> 4) & 1) * 8;
#pragma unroll
            for (int mf = 0; mf < 4; mf++) {
                uint32_t ah[4], al[4];
                uint32_t off = ((arow + mf * 16) * 40 + acol) * 2;
                ldm4(st + off, ah[0], ah[1], ah[2], ah[3]);
                ldm4(st + 10240 + off, al[0], al[1], al[2], al[3]);
#pragma unroll
                for (int nf = 0; nf < 4; nf++) {
                    mma16816(acc[mf][nf], ah, bh[nf]);
                    mma16816(acc[mf][nf], ah, bl[nf]);
                    mma16816(acc[mf][nf], al, bh[nf]);
                }
            }
        }
        __syncthreads();
        cur ^= 1;
    }
#pragma unroll
    for (int mf = 0; mf < 4; mf++)
#pragma unroll
        for (int nf = 0; nf < 4; nf++) {
            int r0 = bm + wm + mf * 16 + (lane >> 2);
            int c0o = bn + wn + nf * 8 + (lane & 3) * 2;
#pragma unroll
            for (int h = 0; h < 2; h++) {
                int r = r0 + h * 8;
                if (r >= M) continue;
                float v0 = acc[mf][nf][2 * h], v1 = acc[mf][nf][2 * h + 1];
                if (bias) { v0 += bias[c0o]; v1 += bias[c0o + 1]; }
                if (relu_out) { v0 = fmaxf(v0, 0.f); v1 = fmaxf(v1, 0.f); }
                if (oh) {
                    __nv_bfloat16 h0 = __float2bfloat16(v0), h1 = __float2bfloat16(v1);
                    __nv_bfloat162 hp; hp.x = h0; hp.y = h1;
                    __nv_bfloat162 lp;
                    lp.x = __float2bfloat16(v0 - __bfloat162float(h0));
                    lp.y = __float2bfloat16(v1 - __bfloat162float(h1));
                    *(__nv_bfloat162*)(oh + (size_t)r * N + c0o) = hp;
                    *(__nv_bfloat162*)(ol + (size_t)r * N + c0o) = lp;
                } else {
                    *(float2*)(C + (size_t)r * N + c0o) = make_float2(v0, v1);
                }
            }
        }
}

__global__ void __launch_bounds__(256)
k_sgemm(const float* __restrict__ A, const float* __restrict__ B,
        const float* __restrict__ bias, float* __restrict__ C,
        int M, int N, int K, int relu_in, int relu_out) {
    __shared__ float As[8][128];
    __shared__ float Bs[8][128];
    int bm = blockIdx.y * 128, bn = blockIdx.x * 128;
    int tid = threadIdx.x, tr = tid >> 4, tc = tid & 15;
    float acc[8][8];
#pragma unroll
    for (int i = 0; i < 8; i++)
#pragma unroll
        for (int j = 0; j < 8; j++) acc[i][j] = 0.f;
    int aRow = tid >> 1, aCol = (tid & 1) * 4;
    int bRow = tid >> 5, bCol = (tid & 31) * 4;
    for (int k0 = 0; k0 < K; k0 += 8) {
        float4 av = make_float4(0.f, 0.f, 0.f, 0.f);
        if (bm + aRow < M)
            av = *(const float4*)(A + (size_t)(bm + aRow) * K + k0 + aCol);
        if (relu_in) {
            av.x = fmaxf(av.x, 0.f); av.y = fmaxf(av.y, 0.f);
            av.z = fmaxf(av.z, 0.f); av.w = fmaxf(av.w, 0.f);
        }
        As[aCol + 0][aRow] = av.x; As[aCol + 1][aRow] = av.y;
        As[aCol + 2][aRow] = av.z; As[aCol + 3][aRow] = av.w;
        float4 bv = make_float4(0.f, 0.f, 0.f, 0.f);
        if (bn + bCol < N)
            bv = *(const float4*)(B + (size_t)(k0 + bRow) * N + bn + bCol);
        *(float4*)&Bs[bRow][bCol] = bv;
        __syncthreads();
#pragma unroll
        for (int kk = 0; kk < 8; kk++) {
            float a[8], b[8];
            *(float4*)(a)     = *(const float4*)&As[kk][tr * 8];
            *(float4*)(a + 4) = *(const float4*)&As[kk][tr * 8 + 4];
            *(float4*)(b)     = *(const float4*)&Bs[kk][tc * 8];
            *(float4*)(b + 4) = *(const float4*)&Bs[kk][tc * 8 + 4];
#pragma unroll
            for (int i = 0; i < 8; i++)
#pragma unroll
                for (int j = 0; j < 8; j++) acc[i][j] = fmaf(a[i], b[j], acc[i][j]);
        }
        __syncthreads();
    }
#pragma unroll
    for (int i = 0; i < 8; i++) {
        int row = bm + tr * 8 + i;
        if (row >= M) continue;
#pragma unroll
        for (int j = 0; j < 8; j++) {
            int col = bn + tc * 8 + j;
            if (col >= N) continue;
            float v = acc[i][j];
            if (bias) v += bias[col];
            if (relu_out) v = fmaxf(v, 0.f);
            C[(size_t)row * N + col] = v;
        }
    }
}

// aggregation with packed edges; hidden layers emit bf16 hi/lo (relu), last emits fp32
__global__ void k_agg(const float* __restrict__ bias,
                      __nv_bfloat16* __restrict__ oh, __nv_bfloat16* __restrict__ ol,
                      float* __restrict__ out32, int relu) {
    int d = (blockIdx.x * blockDim.x + threadIdx.x) >> 5;
    int lane = threadIdx.x & 31;
    if (d >= N_NODES) return;
    float acc[8];
    const float* g0 = g_G + (size_t)d * GW;
#pragma unroll
    for (int j = 0; j < 8; j++) acc[j] = g0[lane + 32 * j] + bias[lane + 32 * j];
    int s = g_off[d], e = g_off[d + 1];
    int i = s;
    for (; i + 2 <= e; i += 2) {
        uint2 p0 = g_epack[i], p1 = g_epack[i + 1];
        const float* gp0 = g_G + p0.x;
        const float* gp1 = g_G + p1.x;
        float inv0 = __uint_as_float(p0.y), inv1 = __uint_as_float(p1.y);
#pragma unroll
        for (int j = 0; j < 8; j++) {
            float a = gp0[lane + 32 * j];
            float b = gp1[lane + 32 * j];
            acc[j] = fmaf(a, inv0, acc[j]);
            acc[j] = fmaf(b, inv1, acc[j]);
        }
    }
    if (i < e) {
        uint2 p0 = g_epack[i];
        const float* gp0 = g_G + p0.x;
        float inv0 = __uint_as_float(p0.y);
#pragma unroll
        for (int j = 0; j < 8; j++) acc[j] = fmaf(gp0[lane + 32 * j], inv0, acc[j]);
    }
    if (relu) {
#pragma unroll
        for (int j = 0; j < 8; j++) {
            float v = fmaxf(acc[j], 0.f);
            __nv_bfloat16 hi = __float2bfloat16(v);
            size_t idx = (size_t)d * DD + lane + 32 * j;
            oh[idx] = hi;
            ol[idx] = __float2bfloat16(v - __bfloat162float(hi));
        }
    } else {
#pragma unroll
        for (int j = 0; j < 8; j++)
            out32[(size_t)d * DD + lane + 32 * j] = acc[j];
    }
}

__global__ void k_starts(const int* __restrict__ batch) {
    int m = blockIdx.x * blockDim.x + threadIdx.x;
    if (m > NUM_M) return;
    int lo = 0, hi = N_NODES;
    while (lo < hi) { int mid = (lo + hi) >> 1; if (batch[mid] < m) lo = mid + 1; else hi = mid; }
    g_start[m] = lo;
}
__global__ void k_copyHR(const float* __restrict__ HR) {
    int i = blockIdx.x * blockDim.x + threadIdx.x;
    if (i < NUM_R * DD) g_Hall[i] = HR[i];
}
__global__ void k_gmean(const float* __restrict__ feats) {
    int m = blockIdx.x, c = threadIdx.x;
    int s = g_start[m], e = g_start[m + 1];
    float acc = 0.f;
    for (int n = s; n < e; n++) acc += feats[(size_t)n * DD + c];
    g_Hall[(size_t)(NUM_R + m) * DD + c] = acc / fmaxf((float)(e - s), 1.0f);
}

__global__ void k_sample_u(unsigned k0, unsigned k1) {
    int i = blockIdx.x * blockDim.x + threadIdx.x;
    if (i >= N_ALL * DD) return;
    int row = i >> 8, col = i & 255;
    g_u[i] = g_pu[row * 512 + col] + expf(g_pu[row * 512 + 256 + col]) * nrm(rbits(k0, k1, i));
}
__global__ void k_sample_zM(unsigned k0, unsigned k1) {
    int i = blockIdx.x * blockDim.x + threadIdx.x;
    if (i >= NUM_M * DD) return;
    int m = i >> 8, col = i & 255;
    int r = (NUM_R + m) * 512;
    g_zM[i] = g_qz[r + col] + expf(g_qz[r + 256 + col]) * nrm(rbits(k0, k1, i));
}
__global__ void k_sample_zR(unsigned k0, unsigned k1) {
    int i = blockIdx.x * blockDim.x + threadIdx.x;
    if (i >= NUM_R * DD) return;
    int r = i >> 8, col = i & 255;
    g_zR[i] = g_qz[r * 512 + col] + expf(g_qz[r * 512 + 256 + col]) * nrm(rbits(k0, k1, i));
}

__global__ void k_attn(const float* __restrict__ pg, const int* __restrict__ yM,
                       unsigned k0, unsigned k1) {
    int m = blockIdx.x, r = threadIdx.x;
    __shared__ float um[DD];
    __shared__ float d2s[NUM_R];
    __shared__ float red[NUM_R];
    for (int i = r; i < DD; i += 64) um[i] = g_u[(size_t)(NUM_R + m) * DD + i];
    __syncthreads();
    float d2 = 0.f;
    const float* ur = g_u + (size_t)r * DD;
    for (int dd = 0; dd < DD; dd++) {
        float t = um[dd] - ur[dd];
        d2 = fmaf(t, t, d2);
    }
    d2s[r] = d2;
    float logp = -0.5f * d2 / expf(pg[0]);
    float logit = logp - logf(fmaxf(-expm1f(logp), 1e-20f));
    float U = unif(rbits(k0, k1, (uint32_t)(m * NUM_R + r)));
    float gn = logf(U) - log1pf(-U);
    float A = 1.0f / (1.0f + expf(-(logit + gn) / 0.3f));
    red[r] = A;
    __syncthreads();
    for (int o = 32; o >= 1; o >>= 1) {
        if (r < o) red[r] += red[r + o];
        __syncthreads();
    }
    g_An[m * NUM_R + r] = A / (red[0] + 1e-8f);
    if (r < 32) {
        int idx = r + (1 - yM[m]) * 32;
        float t = sqrtf(fmaxf(d2s[idx], 1e-12f));
        for (int o = 16; o >= 1; o >>= 1) t += __shfl_down_sync(0xffffffffu, t, o);
        if (r == 0) atomicAdd(&g_acc[3], t);
    }
}

// merged pz + pqz
__global__ void k_pzq() {
    int m = blockIdx.x, c = threadIdx.x;
    __shared__ float an[NUM_R];
    if (c < NUM_R) an[c] = g_An[m * NUM_R + c];
    __syncthreads();
    float pm = 0.f, pl = 0.f;
    for (int r = 0; r < NUM_R; r++) {
        float a = an[r];
        pm = fmaf(a, g_qz[r * 512 + c], pm);
        pl = fmaf(a, g_qz[r * 512 + 256 + c], pl);
    }
    float z = g_zM[m * DD + c];
    float qm = g_qz[(NUM_R + m) * 512 + c], ql = g_qz[(NUM_R + m) * 512 + 256 + c];
    float t1 = (z - pm) * expf(-pl);
    float t2 = (z - qm) * expf(-ql);
    float v = (-pl - 0.5f * t1 * t1) - (-ql - 0.5f * t2 * t2);
    __shared__ float red[256];
    red[c] = v;
    __syncthreads();
    for (int o = 128; o >= 1; o >>= 1) {
        if (c < o) red[c] += red[c + o];
        __syncthreads();
    }
    if (c == 0) atomicAdd(&g_acc[1], red[0]);
}

__global__ void k_repM() {
    int i = blockIdx.x * blockDim.x + threadIdx.x;
    if (i >= NUM_M * 512) return;
    int m = i >> 9, c = i & 511;
    g_repM[i] = (c < 256) ? g_zM[m * DD + c] : g_u[(size_t)(NUM_R + m) * DD + (c - 256)];
}
__global__ void k_repR() {
    int i = blockIdx.x * blockDim.x + threadIdx.x;
    if (i >= NUM_R * 512) return;
    int r = i >> 9, c = i & 511;
    g_repR[i] = (c < 256) ? g_zR[r * DD + c] : g_u[(size_t)r * DD + (c - 256)];
}

__global__ void k_head(const float* __restrict__ hid, const float* __restrict__ W2,
                       const float* __restrict__ b2, const int* __restrict__ y,
                       int rows, int accIdx) {
    int gw = (blockIdx.x * blockDim.x + threadIdx.x) >> 5;
    int lane = threadIdx.x & 31;
    if (gw >= rows) return;
    float p0 = 0.f, p1 = 0.f;
#pragma unroll
    for (int j = 0; j < 8; j++) {
        int k = lane + 32 * j;
        float h = hid[(size_t)gw * 256 + k];
        p0 = fmaf(h, W2[k * 2], p0);
        p1 = fmaf(h, W2[k * 2 + 1], p1);
    }
    for (int o = 16; o >= 1; o >>= 1) {
        p0 += __shfl_down_sync(0xffffffffu, p0, o);
        p1 += __shfl_down_sync(0xffffffffu, p1, o);
    }
    if (lane == 0) {
        float l0 = p0 + b2[0], l1 = p1 + b2[1];
        float mx = fmaxf(l0, l1);
        float lse = mx + logf(expf(l0 - mx) + expf(l1 - mx));
        atomicAdd(&g_acc[accIdx], ((y[gw] != 0) ? l1 : l0) - lse);
    }
}

__global__ void k_final(float* __restrict__ out) {
    float pred = -(g_acc[0] + 0.1f * g_acc[1]) / 1024.0f;
    float rat  = -g_acc[2] / 64.0f;
    float reg  = g_acc[3] / 32768.0f;
    out[0] = pred + rat - 0.1f * reg;
}

extern "C" void kernel_launch(void* const* d_in, const int* in_sizes, int n_in,
                              void* d_out, int out_size) {
    (void)in_sizes; (void)n_in; (void)out_size;
    const float* x     = (const float*)d_in[0];
    const int*   ei    = (const int*)  d_in[1];
    const int*   et    = (const int*)  d_in[2];
    const int*   batch = (const int*)  d_in[3];
    const int*   yM    = (const int*)  d_in[4];
    const int*   yR    = (const int*)  d_in[5];
    const float* HR    = (const float*)d_in[6];
    const float* nodeW = (const float*)d_in[7];
    const float* nodeB = (const float*)d_in[8];
    const float* Wr    = (const float*)d_in[9];
    const float* Wroot = (const float*)d_in[10];
    const float* gcnB  = (const float*)d_in[11];
    const float* pg    = (const float*)d_in[12];
    const float* puW   = (const float*)d_in[13];
    const float* puB   = (const float*)d_in[14];
    const float* qzW   = (const float*)d_in[15];
    const float* qzB   = (const float*)d_in[16];
    const float* W1    = (const float*)d_in[17];
    const float* b1    = (const float*)d_in[18];
    const float* W2    = (const float*)d_in[19];
    const float* b2    = (const float*)d_in[20];
    float* out = (float*)d_out;

    uint32_t ku0, ku1, ka0, ka1, kzm0, kzm1, kzr0, kzr1;
    tf2x32(0u, 42u, 0u, 0u, ku0, ku1);
    tf2x32(0u, 42u, 0u, 1u, ka0, ka1);
    tf2x32(0u, 42u, 0u, 2u, kzm0, kzm1);
    tf2x32(0u, 42u, 0u, 3u, kzr0, kzr1);

    void* p;
    cudaGetSymbolAddress(&p, g_featsB); float* featsB = (float*)p;
    cudaGetSymbolAddress(&p, g_G);      float* G      = (float*)p;
    cudaGetSymbolAddress(&p, g_Wh);     __nv_bfloat16* Wh  = (__nv_bfloat16*)p;
    cudaGetSymbolAddress(&p, g_Wl);     __nv_bfloat16* Wl  = (__nv_bfloat16*)p;
    cudaGetSymbolAddress(&p, g_nWh);    __nv_bfloat16* nWh = (__nv_bfloat16*)p;
    cudaGetSymbolAddress(&p, g_nWl);    __nv_bfloat16* nWl = (__nv_bfloat16*)p;
    cudaGetSymbolAddress(&p, g_xh);     __nv_bfloat16* xh  = (__nv_bfloat16*)p;
    cudaGetSymbolAddress(&p, g_xl);     __nv_bfloat16* xl  = (__nv_bfloat16*)p;
    cudaGetSymbolAddress(&p, g_Ah);     __nv_bfloat16* Ahp = (__nv_bfloat16*)p;
    cudaGetSymbolAddress(&p, g_Al);     __nv_bfloat16* Alp = (__nv_bfloat16*)p;
    cudaGetSymbolAddress(&p, g_Hall);   float* Hall   = (float*)p;
    cudaGetSymbolAddress(&p, g_pu);     float* pu     = (float*)p;
    cudaGetSymbolAddress(&p, g_qz);     float* qz     = (float*)p;
    cudaGetSymbolAddress(&p, g_repM);   float* repM   = (float*)p;
    cudaGetSymbolAddress(&p, g_repR);   float* repR   = (float*)p;
    cudaGetSymbolAddress(&p, g_hidM);   float* hidM   = (float*)p;
    cudaGetSymbolAddress(&p, g_hidR);   float* hidR   = (float*)p;

    static int smem_set = 0;
    if (!smem_set) {
        cudaFuncSetAttribute(k_bmma, cudaFuncAttributeMaxDynamicSharedMemorySize, 81920);
        smem_set = 1;
    }

    k_zero_init<<<(N_RELS * N_NODES + 255) / 256, 256>>>();
    k_count<<<(N_EDGES + 255) / 256, 256>>>(ei, et);
    k_scan<<<1, 1024>>>();
    k_scatter<<<(N_EDGES + 255) / 256, 256>>>(ei, et);
    k_wsplit<<<(N_LAYERS * GW * 256 + 255) / 256, 256>>>(Wroot, Wr);
    k_wsplitN<<<(256 * D_IN + 255) / 256, 256>>>(nodeW);
    k_asplit<<<(N_NODES * D_IN + 255) / 256, 256>>>(x, xh, xl, N_NODES * D_IN);

    // node encoder on tensor cores, split output fused
    k_bmma<<<dim3(2, (N_NODES + 127) / 128), 256, 81920>>>(
        xh, xl, nWh, nWl, nodeB, nullptr, Ahp, Alp, N_NODES, 256, D_IN, 0);

    for (int l = 0; l < N_LAYERS; l++) {
        k_bmma<<<dim3(GW / 128, (N_NODES + 127) / 128), 256, 81920>>>(
            Ahp, Alp, Wh + (size_t)l * GW * 256, Wl + (size_t)l * GW * 256,
            nullptr, G, nullptr, nullptr, N_NODES, GW, 256, 0);
        k_agg<<<(N_NODES * 32 + 255) / 256, 256>>>(
            gcnB + l * 256, Ahp, Alp, featsB, (l < N_LAYERS - 1) ? 1 : 0);
    }

    k_starts<<<(NUM_M + 256) / 256, 256>>>(batch);
    k_copyHR<<<(NUM_R * DD + 255) / 256, 256>>>(HR);
    k_gmean<<<NUM_M, 256>>>(featsB);

    k_sgemm<<<dim3(4, (N_ALL + 127) / 128), 256>>>(Hall, puW, puB, pu, N_ALL, 512, 256, 1, 0);
    k_sgemm<<<dim3(4, (N_ALL + 127) / 128), 256>>>(Hall, qzW, qzB, qz, N_ALL, 512, 256, 1, 0);

    k_sample_u <<<(N_ALL * DD + 255) / 256, 256>>>(ku0, ku1);
    k_sample_zM<<<(NUM_M * DD + 255) / 256, 256>>>(kzm0, kzm1);
    k_sample_zR<<<(NUM_R * DD + 255) / 256, 256>>>(kzr0, kzr1);

    k_attn<<<NUM_M, 64>>>(pg, yM, ka0, ka1);
    k_pzq<<<NUM_M, 256>>>();

    k_repM<<<(NUM_M * 512 + 255) / 256, 256>>>();
    k_repR<<<(NUM_R * 512 + 255) / 256, 256>>>();
    k_sgemm<<<dim3(2, (NUM_M + 127) / 128), 256>>>(repM, W1, b1, hidM, NUM_M, 256, 512, 0, 1);
    k_sgemm<<<dim3(2, 1), 256>>>(repR, W1, b1, hidR, NUM_R, 256, 512, 0, 1);
    k_head<<<(NUM_M * 32 + 255) / 256, 256>>>(hidM, W2, b2, yM, NUM_M, 0);
    k_head<<<(NUM_R * 32 + 255) / 256, 256>>>(hidR, W2, b2, yR, NUM_R, 2);

    k_final<<<1, 1>>>(out);
}

// round 6
// speedup vs baseline: 1.1250x; 1.1250x over previous
#include <cuda_runtime.h>
#include <cuda_bf16.h>
#include <stdint.h>
#include <math.h>

#define N_NODES 50000
#define N_EDGES 200000
#define D_IN    128
#define DD      256
#define N_LAYERS 4
#define N_RELS  4
#define NUM_M   1024
#define NUM_R   64
#define N_ALL   (NUM_R + NUM_M)
#define GW      1280
#define MPAD    (N_NODES + 128)

__device__ float g_featsB[N_NODES * DD];
__device__ float g_G[(size_t)N_NODES * GW];
__device__ __nv_bfloat16 g_Wh[N_LAYERS * GW * 256];
__device__ __nv_bfloat16 g_Wl[N_LAYERS * GW * 256];
__device__ __nv_bfloat16 g_nWh[256 * D_IN];
__device__ __nv_bfloat16 g_nWl[256 * D_IN];
__device__ __nv_bfloat16 g_xh[(size_t)MPAD * D_IN];
__device__ __nv_bfloat16 g_xl[(size_t)MPAD * D_IN];
__device__ __nv_bfloat16 g_Ah[(size_t)MPAD * DD];
__device__ __nv_bfloat16 g_Al[(size_t)MPAD * DD];
__device__ int   g_cnt[N_RELS * N_NODES];
__device__ int   g_deg[N_NODES];
__device__ int   g_off[N_NODES + 1];
__device__ int   g_cursor[N_NODES];
__device__ uint2 g_epack[N_EDGES];
__device__ int   g_start[NUM_M + 1];
__device__ float g_Hall[N_ALL * DD];
__device__ float g_pu[N_ALL * 512];
__device__ float g_qz[N_ALL * 512];
__device__ float g_u[N_ALL * DD];
__device__ float g_zM[NUM_M * DD];
__device__ float g_zR[NUM_R * DD];
__device__ float g_An[NUM_M * NUM_R];
__device__ float g_repM[NUM_M * 512];
__device__ float g_repR[NUM_R * 512];
__device__ float g_hidM[NUM_M * 256];
__device__ float g_hidR[NUM_R * 256];
__device__ float g_acc[4];

__host__ __device__ __forceinline__ uint32_t rotl32(uint32_t x, int d) {
    return (x << d) | (x >> (32 - d));
}
__host__ __device__ __forceinline__ void tf2x32(uint32_t k0, uint32_t k1,
                                                uint32_t x0, uint32_t x1,
                                                uint32_t& o0, uint32_t& o1) {
    uint32_t ks2 = k0 ^ k1 ^ 0x1BD11BDAu;
    x0 += k0; x1 += k1;
#define TF_RND(R) { x0 += x1; x1 = rotl32(x1, R); x1 ^= x0; }
    TF_RND(13) TF_RND(15) TF_RND(26) TF_RND(6)
    x0 += k1;  x1 += ks2 + 1u;
    TF_RND(17) TF_RND(29) TF_RND(16) TF_RND(24)
    x0 += ks2; x1 += k0 + 2u;
    TF_RND(13) TF_RND(15) TF_RND(26) TF_RND(6)
    x0 += k0;  x1 += k1 + 3u;
    TF_RND(17) TF_RND(29) TF_RND(16) TF_RND(24)
    x0 += k1;  x1 += ks2 + 4u;
    TF_RND(13) TF_RND(15) TF_RND(26) TF_RND(6)
    x0 += ks2; x1 += k0 + 5u;
#undef TF_RND
    o0 = x0; o1 = x1;
}
__device__ __forceinline__ uint32_t rbits(uint32_t k0, uint32_t k1, uint32_t i) {
    uint32_t o0, o1; tf2x32(k0, k1, 0u, i, o0, o1); return o0 ^ o1;
}
__device__ __forceinline__ float erfinv_xla(float x) {
    float w = -log1pf(-x * x), p;
    if (w < 5.0f) {
        w -= 2.5f;
        p = 2.81022636e-08f;
        p = fmaf(p, w, 3.43273939e-07f);  p = fmaf(p, w, -3.5233877e-06f);
        p = fmaf(p, w, -4.39150654e-06f); p = fmaf(p, w, 0.00021858087f);
        p = fmaf(p, w, -0.00125372503f);  p = fmaf(p, w, -0.00417768164f);
        p = fmaf(p, w, 0.246640727f);     p = fmaf(p, w, 1.50140941f);
    } else {
        w = sqrtf(w) - 3.0f;
        p = -0.000200214257f;
        p = fmaf(p, w, 0.000100950558f);  p = fmaf(p, w, 0.00134934322f);
        p = fmaf(p, w, -0.00367342844f);  p = fmaf(p, w, 0.00573950773f);
        p = fmaf(p, w, -0.0076224613f);   p = fmaf(p, w, 0.00943887047f);
        p = fmaf(p, w, 1.00167406f);      p = fmaf(p, w, 2.83297682f);
    }
    return p * x;
}
__device__ __forceinline__ float u01(uint32_t b) {
    return __uint_as_float((b >> 9) | 0x3f800000u) - 1.0f;
}
__device__ __forceinline__ float nrm(uint32_t b) {
    const float LO = -0.99999994f;
    float v = u01(b) * 2.0f + LO;
    v = fmaxf(LO, v);
    return 1.41421356f * erfinv_xla(v);
}
__device__ __forceinline__ float unif(uint32_t b) {
    const float MN = 1e-06f;
    float v = u01(b) * (0.999999f - MN) + MN;
    return fmaxf(MN, v);
}

__global__ void k_zero_init() {
    int i = blockIdx.x * blockDim.x + threadIdx.x;
    if (i < N_RELS * N_NODES) g_cnt[i] = 0;
    if (i < N_NODES) g_deg[i] = 0;
    if (i < 4) g_acc[i] = 0.0f;
}
__global__ void k_count(const int* __restrict__ ei, const int* __restrict__ et) {
    int e = blockIdx.x * blockDim.x + threadIdx.x;
    if (e >= N_EDGES) return;
    int d = ei[N_EDGES + e];
    atomicAdd(&g_cnt[et[e] * N_NODES + d], 1);
    atomicAdd(&g_deg[d], 1);
}
__global__ void k_scan() {
    __shared__ int part[1024];
    int tid = threadIdx.x;
    const int chunk = (N_NODES + 1023) / 1024;
    int lo = tid * chunk, hi = min(lo + chunk, N_NODES);
    int s = 0;
    for (int i = lo; i < hi; i++) s += g_deg[i];
    part[tid] = s;
    __syncthreads();
    for (int o = 1; o < 1024; o <<= 1) {
        int v = (tid >= o) ? part[tid - o] : 0;
        __syncthreads(); part[tid] += v; __syncthreads();
    }
    int run = part[tid] - s;
    for (int i = lo; i < hi; i++) { g_off[i] = run; g_cursor[i] = run; run += g_deg[i]; }
    if (tid == 1023) g_off[N_NODES] = run;
}
__global__ void k_scatter(const int* __restrict__ ei, const int* __restrict__ et) {
    int e = blockIdx.x * blockDim.x + threadIdx.x;
    if (e >= N_EDGES) return;
    int sn = ei[e], d = ei[N_EDGES + e], r = et[e];
    int p = atomicAdd(&g_cursor[d], 1);
    float inv = 1.0f / (float)g_cnt[r * N_NODES + d];
    g_epack[p] = make_uint2((uint32_t)(sn * GW + 256 + (r << 8)), __float_as_uint(inv));
}
__global__ void k_wsplit(const float* __restrict__ Wroot, const float* __restrict__ Wr) {
    int idx = blockIdx.x * blockDim.x + threadIdx.x;
    if (idx >= N_LAYERS * GW * 256) return;
    int l = idx / (GW * 256), rem = idx % (GW * 256);
    int n = rem / 256, k = rem % 256;
    float v;
    if (n < 256) v = Wroot[((size_t)l * 256 + k) * 256 + n];
    else {
        int r = (n >> 8) - 1, h = n & 255;
        v = Wr[(((size_t)l * 4 + r) * 256 + k) * 256 + h];
    }
    __nv_bfloat16 hi = __float2bfloat16(v);
    g_Wh[idx] = hi;
    g_Wl[idx] = __float2bfloat16(v - __bfloat162float(hi));
}
__global__ void k_wsplitN(const float* __restrict__ nodeW) {
    int idx = blockIdx.x * blockDim.x + threadIdx.x;
    if (idx >= 256 * D_IN) return;
    int n = idx / D_IN, k = idx % D_IN;
    float v = nodeW[k * 256 + n];
    __nv_bfloat16 hi = __float2bfloat16(v);
    g_nWh[idx] = hi;
    g_nWl[idx] = __float2bfloat16(v - __bfloat162float(hi));
}
__global__ void k_asplit(const float* __restrict__ src, __nv_bfloat16* __restrict__ h,
                         __nv_bfloat16* __restrict__ l, int n) {
    int i = blockIdx.x * blockDim.x + threadIdx.x;
    if (i >= n) return;
    float v = src[i];
    __nv_bfloat16 hi = __float2bfloat16(v);
    h[i] = hi;
    l[i] = __float2bfloat16(v - __bfloat162float(hi));
}

// ------- pipelined bf16 tensor-core GEMM, BM=BN=128, BK=32, 3 stages, 1 CTA/SM -------
__device__ __forceinline__ void ldm4(uint32_t a, uint32_t& r0, uint32_t& r1,
                                     uint32_t& r2, uint32_t& r3) {
    asm volatile("ldmatrix.sync.aligned.m8n8.x4.shared.b16 {%0,%1,%2,%3}, [%4];"
                 : "=r"(r0), "=r"(r1), "=r"(r2), "=r"(r3) : "r"(a));
}
__device__ __forceinline__ void mma16816(float* c, const uint32_t* a, const uint32_t* b) {
    asm volatile("mma.sync.aligned.m16n8k16.row.col.f32.bf16.bf16.f32 "
                 "{%0,%1,%2,%3},{%4,%5,%6,%7},{%8,%9},{%0,%1,%2,%3};"
                 : "+f"(c[0]), "+f"(c[1]), "+f"(c[2]), "+f"(c[3])
                 : "r"(a[0]), "r"(a[1]), "r"(a[2]), "r"(a[3]), "r"(b[0]), "r"(b[1]));
}
__device__ __forceinline__ void cp16(uint32_t dst, const void* src) {
    asm volatile("cp.async.cg.shared.global [%0], [%1], 16;" :: "r"(dst), "l"(src));
}
// per-stage layout (bytes): Ah 0, Al 10240, Bh 20480, Bl 30720; stage stride 40960
#define LOAD_STAGE(s, kq)                                              \
    do {                                                               \
        uint32_t st_ = sm + (s) * 40960;                               \
        _Pragma("unroll")                                              \
        for (int q_ = 0; q_ < 2; q_++) {                               \
            int col_ = (c0 + q_) * 8;                                  \
            uint32_t dd_ = st_ + (row * 40 + col_) * 2;                \
            cp16(dd_,         Agh + (kq) + col_);                      \
            cp16(dd_ + 10240, Agl + (kq) + col_);                      \
            cp16(dd_ + 20480, Bgh + (kq) + col_);                      \
            cp16(dd_ + 30720, Bgl + (kq) + col_);                      \
        }                                                              \
    } while (0)

__global__ void __launch_bounds__(256, 1)
k_bmma(const __nv_bfloat16* __restrict__ Ah, const __nv_bfloat16* __restrict__ Al,
       const __nv_bfloat16* __restrict__ Bh, const __nv_bfloat16* __restrict__ Bl,
       const float* __restrict__ bias, float* __restrict__ C,
       __nv_bfloat16* __restrict__ oh, __nv_bfloat16* __restrict__ ol,
       int M, int N, int K, int relu_out) {
    extern __shared__ __align__(16) __nv_bfloat16 dsm[];
    uint32_t sm = (uint32_t)__cvta_generic_to_shared(dsm);
    int tid = threadIdx.x, lane = tid & 31, wid = tid >> 5;
    int wm = (wid >> 2) * 64, wn = (wid & 3) * 32;
    int bm = blockIdx.y * 128, bn = blockIdx.x * 128;
    int row = tid >> 1, c0 = (tid & 1) * 2;
    const __nv_bfloat16* Agh = Ah + (size_t)(bm + row) * K;
    const __nv_bfloat16* Agl = Al + (size_t)(bm + row) * K;
    const __nv_bfloat16* Bgh = Bh + (size_t)(bn + row) * K;
    const __nv_bfloat16* Bgl = Bl + (size_t)(bn + row) * K;

    float acc[4][4][4];
#pragma unroll
    for (int i = 0; i < 4; i++)
#pragma unroll
        for (int j = 0; j < 4; j++)
#pragma unroll
            for (int q = 0; q < 4; q++) acc[i][j][q] = 0.f;

    LOAD_STAGE(0, 0);
    asm volatile("cp.async.commit_group;");
    if (32 < K) LOAD_STAGE(1, 32);
    asm volatile("cp.async.commit_group;");

    int cur = 0;
    for (int k0 = 0; k0 < K; k0 += 32) {
        int pre = k0 + 64;
        if (pre < K) {
            int s2 = cur + 2; if (s2 >= 3) s2 -= 3;
            LOAD_STAGE(s2, pre);
        }
        asm volatile("cp.async.commit_group;");
        asm volatile("cp.async.wait_group 2;");
        __syncthreads();
        uint32_t st = sm + cur * 40960;
#pragma unroll
        for (int kk = 0; kk < 32; kk += 16) {
            uint32_t bh[4][2], bl[4][2];
            int brow = wn + (lane & 7) + ((lane >> 4) & 1) * 8;
            int bcol = kk + ((lane >> 3) & 1) * 8;
#pragma unroll
            for (int nb = 0; nb < 2; nb++) {
                uint32_t off = ((brow + nb * 16) * 40 + bcol) * 2;
                ldm4(st + 20480 + off, bh[2 * nb][0], bh[2 * nb][1], bh[2 * nb + 1][0], bh[2 * nb + 1][1]);
                ldm4(st + 30720 + off, bl[2 * nb][0], bl[2 * nb][1], bl[2 * nb + 1][0], bl[2 * nb + 1][1]);
            }
            int arow = wm + (lane & 7) + ((lane >> 3) & 1) * 8;
            int acol = kk + ((lane >> 4) & 1) * 8;
#pragma unroll
            for (int mf = 0; mf < 4; mf++) {
                uint32_t ah[4], al[4];
                uint32_t off = ((arow + mf * 16) * 40 + acol) * 2;
                ldm4(st + off, ah[0], ah[1], ah[2], ah[3]);
                ldm4(st + 10240 + off, al[0], al[1], al[2], al[3]);
#pragma unroll
                for (int nf = 0; nf < 4; nf++) {
                    mma16816(acc[mf][nf], ah, bh[nf]);
                    mma16816(acc[mf][nf], ah, bl[nf]);
                    mma16816(acc[mf][nf], al, bh[nf]);
                }
            }
        }
        __syncthreads();
        cur++; if (cur >= 3) cur = 0;
    }
#pragma unroll
    for (int mf = 0; mf < 4; mf++)
#pragma unroll
        for (int nf = 0; nf < 4; nf++) {
            int r0 = bm + wm + mf * 16 + (lane >> 2);
            int c0o = bn + wn + nf * 8 + (lane & 3) * 2;
#pragma unroll
            for (int h = 0; h < 2; h++) {
                int r = r0 + h * 8;
                if (r >= M) continue;
                float v0 = acc[mf][nf][2 * h], v1 = acc[mf][nf][2 * h + 1];
                if (bias) { v0 += bias[c0o]; v1 += bias[c0o + 1]; }
                if (relu_out) { v0 = fmaxf(v0, 0.f); v1 = fmaxf(v1, 0.f); }
                if (oh) {
                    __nv_bfloat16 h0 = __float2bfloat16(v0), h1 = __float2bfloat16(v1);
                    __nv_bfloat162 hp; hp.x = h0; hp.y = h1;
                    __nv_bfloat162 lp;
                    lp.x = __float2bfloat16(v0 - __bfloat162float(h0));
                    lp.y = __float2bfloat16(v1 - __bfloat162float(h1));
                    *(__nv_bfloat162*)(oh + (size_t)r * N + c0o) = hp;
                    *(__nv_bfloat162*)(ol + (size_t)r * N + c0o) = lp;
                } else {
                    *(float2*)(C + (size_t)r * N + c0o) = make_float2(v0, v1);
                }
            }
        }
}

__global__ void __launch_bounds__(256)
k_sgemm(const float* __restrict__ A, const float* __restrict__ B,
        const float* __restrict__ bias, float* __restrict__ C,
        int M, int N, int K, int relu_in, int relu_out) {
    __shared__ float As[8][128];
    __shared__ float Bs[8][128];
    int bm = blockIdx.y * 128, bn = blockIdx.x * 128;
    int tid = threadIdx.x, tr = tid >> 4, tc = tid & 15;
    float acc[8][8];
#pragma unroll
    for (int i = 0; i < 8; i++)
#pragma unroll
        for (int j = 0; j < 8; j++) acc[i][j] = 0.f;
    int aRow = tid >> 1, aCol = (tid & 1) * 4;
    int bRow = tid >> 5, bCol = (tid & 31) * 4;
    for (int k0 = 0; k0 < K; k0 += 8) {
        float4 av = make_float4(0.f, 0.f, 0.f, 0.f);
        if (bm + aRow < M)
            av = *(const float4*)(A + (size_t)(bm + aRow) * K + k0 + aCol);
        if (relu_in) {
            av.x = fmaxf(av.x, 0.f); av.y = fmaxf(av.y, 0.f);
            av.z = fmaxf(av.z, 0.f); av.w = fmaxf(av.w, 0.f);
        }
        As[aCol + 0][aRow] = av.x; As[aCol + 1][aRow] = av.y;
        As[aCol + 2][aRow] = av.z; As[aCol + 3][aRow] = av.w;
        float4 bv = make_float4(0.f, 0.f, 0.f, 0.f);
        if (bn + bCol < N)
            bv = *(const float4*)(B + (size_t)(k0 + bRow) * N + bn + bCol);
        *(float4*)&Bs[bRow][bCol] = bv;
        __syncthreads();
#pragma unroll
        for (int kk = 0; kk < 8; kk++) {
            float a[8], b[8];
            *(float4*)(a)     = *(const float4*)&As[kk][tr * 8];
            *(float4*)(a + 4) = *(const float4*)&As[kk][tr * 8 + 4];
            *(float4*)(b)     = *(const float4*)&Bs[kk][tc * 8];
            *(float4*)(b + 4) = *(const float4*)&Bs[kk][tc * 8 + 4];
#pragma unroll
            for (int i = 0; i < 8; i++)
#pragma unroll
                for (int j = 0; j < 8; j++) acc[i][j] = fmaf(a[i], b[j], acc[i][j]);
        }
        __syncthreads();
    }
#pragma unroll
    for (int i = 0; i < 8; i++) {
        int row = bm + tr * 8 + i;
        if (row >= M) continue;
#pragma unroll
        for (int j = 0; j < 8; j++) {
            int col = bn + tc * 8 + j;
            if (col >= N) continue;
            float v = acc[i][j];
            if (bias) v += bias[col];
            if (relu_out) v = fmaxf(v, 0.f);
            C[(size_t)row * N + col] = v;
        }
    }
}

__global__ void k_agg(const float* __restrict__ bias,
                      __nv_bfloat16* __restrict__ oh, __nv_bfloat16* __restrict__ ol,
                      float* __restrict__ out32, int relu) {
    int d = (blockIdx.x * blockDim.x + threadIdx.x) >> 5;
    int lane = threadIdx.x & 31;
    if (d >= N_NODES) return;
    float acc[8];
    const float* g0 = g_G + (size_t)d * GW;
#pragma unroll
    for (int j = 0; j < 8; j++) acc[j] = g0[lane + 32 * j] + bias[lane + 32 * j];
    int s = g_off[d], e = g_off[d + 1];
    int i = s;
    for (; i + 2 <= e; i += 2) {
        uint2 p0 = g_epack[i], p1 = g_epack[i + 1];
        const float* gp0 = g_G + p0.x;
        const float* gp1 = g_G + p1.x;
        float inv0 = __uint_as_float(p0.y), inv1 = __uint_as_float(p1.y);
#pragma unroll
        for (int j = 0; j < 8; j++) {
            float a = gp0[lane + 32 * j];
            float b = gp1[lane + 32 * j];
            acc[j] = fmaf(a, inv0, acc[j]);
            acc[j] = fmaf(b, inv1, acc[j]);
        }
    }
    if (i < e) {
        uint2 p0 = g_epack[i];
        const float* gp0 = g_G + p0.x;
        float inv0 = __uint_as_float(p0.y);
#pragma unroll
        for (int j = 0; j < 8; j++) acc[j] = fmaf(gp0[lane + 32 * j], inv0, acc[j]);
    }
    if (relu) {
#pragma unroll
        for (int j = 0; j < 8; j++) {
            float v = fmaxf(acc[j], 0.f);
            __nv_bfloat16 hi = __float2bfloat16(v);
            size_t idx = (size_t)d * DD + lane + 32 * j;
            oh[idx] = hi;
            ol[idx] = __float2bfloat16(v - __bfloat162float(hi));
        }
    } else {
#pragma unroll
        for (int j = 0; j < 8; j++)
            out32[(size_t)d * DD + lane + 32 * j] = acc[j];
    }
}

__global__ void k_starts(const int* __restrict__ batch) {
    int m = blockIdx.x * blockDim.x + threadIdx.x;
    if (m > NUM_M) return;
    int lo = 0, hi = N_NODES;
    while (lo < hi) { int mid = (lo + hi) >> 1; if (batch[mid] < m) lo = mid + 1; else hi = mid; }
    g_start[m] = lo;
}
__global__ void k_copyHR(const float* __restrict__ HR) {
    int i = blockIdx.x * blockDim.x + threadIdx.x;
    if (i < NUM_R * DD) g_Hall[i] = HR[i];
}
__global__ void k_gmean(const float* __restrict__ feats) {
    int m = blockIdx.x, c = threadIdx.x;
    int s = g_start[m], e = g_start[m + 1];
    float acc = 0.f;
    for (int n = s; n < e; n++) acc += feats[(size_t)n * DD + c];
    g_Hall[(size_t)(NUM_R + m) * DD + c] = acc / fmaxf((float)(e - s), 1.0f);
}

__global__ void k_sample_u(unsigned k0, unsigned k1) {
    int i = blockIdx.x * blockDim.x + threadIdx.x;
    if (i >= N_ALL * DD) return;
    int row = i >> 8, col = i & 255;
    g_u[i] = g_pu[row * 512 + col] + expf(g_pu[row * 512 + 256 + col]) * nrm(rbits(k0, k1, i));
}
__global__ void k_sample_zM(unsigned k0, unsigned k1) {
    int i = blockIdx.x * blockDim.x + threadIdx.x;
    if (i >= NUM_M * DD) return;
    int m = i >> 8, col = i & 255;
    int r = (NUM_R + m) * 512;
    g_zM[i] = g_qz[r + col] + expf(g_qz[r + 256 + col]) * nrm(rbits(k0, k1, i));
}
__global__ void k_sample_zR(unsigned k0, unsigned k1) {
    int i = blockIdx.x * blockDim.x + threadIdx.x;
    if (i >= NUM_R * DD) return;
    int r = i >> 8, col = i & 255;
    g_zR[i] = g_qz[r * 512 + col] + expf(g_qz[r * 512 + 256 + col]) * nrm(rbits(k0, k1, i));
}

__global__ void k_attn(const float* __restrict__ pg, const int* __restrict__ yM,
                       unsigned k0, unsigned k1) {
    int m = blockIdx.x, r = threadIdx.x;
    __shared__ float um[DD];
    __shared__ float d2s[NUM_R];
    __shared__ float red[NUM_R];
    for (int i = r; i < DD; i += 64) um[i] = g_u[(size_t)(NUM_R + m) * DD + i];
    __syncthreads();
    float d2 = 0.f;
    const float* ur = g_u + (size_t)r * DD;
    for (int dd = 0; dd < DD; dd++) {
        float t = um[dd] - ur[dd];
        d2 = fmaf(t, t, d2);
    }
    d2s[r] = d2;
    float logp = -0.5f * d2 / expf(pg[0]);
    float logit = logp - logf(fmaxf(-expm1f(logp), 1e-20f));
    float U = unif(rbits(k0, k1, (uint32_t)(m * NUM_R + r)));
    float gn = logf(U) - log1pf(-U);
    float A = 1.0f / (1.0f + expf(-(logit + gn) / 0.3f));
    red[r] = A;
    __syncthreads();
    for (int o = 32; o >= 1; o >>= 1) {
        if (r < o) red[r] += red[r + o];
        __syncthreads();
    }
    g_An[m * NUM_R + r] = A / (red[0] + 1e-8f);
    if (r < 32) {
        int idx = r + (1 - yM[m]) * 32;
        float t = sqrtf(fmaxf(d2s[idx], 1e-12f));
        for (int o = 16; o >= 1; o >>= 1) t += __shfl_down_sync(0xffffffffu, t, o);
        if (r == 0) atomicAdd(&g_acc[3], t);
    }
}

__global__ void k_pzq() {
    int m = blockIdx.x, c = threadIdx.x;
    __shared__ float an[NUM_R];
    if (c < NUM_R) an[c] = g_An[m * NUM_R + c];
    __syncthreads();
    float pm = 0.f, pl = 0.f;
    for (int r = 0; r < NUM_R; r++) {
        float a = an[r];
        pm = fmaf(a, g_qz[r * 512 + c], pm);
        pl = fmaf(a, g_qz[r * 512 + 256 + c], pl);
    }
    float z = g_zM[m * DD + c];
    float qm = g_qz[(NUM_R + m) * 512 + c], ql = g_qz[(NUM_R + m) * 512 + 256 + c];
    float t1 = (z - pm) * expf(-pl);
    float t2 = (z - qm) * expf(-ql);
    float v = (-pl - 0.5f * t1 * t1) - (-ql - 0.5f * t2 * t2);
    __shared__ float red[256];
    red[c] = v;
    __syncthreads();
    for (int o = 128; o >= 1; o >>= 1) {
        if (c < o) red[c] += red[c + o];
        __syncthreads();
    }
    if (c == 0) atomicAdd(&g_acc[1], red[0]);
}

__global__ void k_repM() {
    int i = blockIdx.x * blockDim.x + threadIdx.x;
    if (i >= NUM_M * 512) return;
    int m = i >> 9, c = i & 511;
    g_repM[i] = (c < 256) ? g_zM[m * DD + c] : g_u[(size_t)(NUM_R + m) * DD + (c - 256)];
}
__global__ void k_repR() {
    int i = blockIdx.x * blockDim.x + threadIdx.x;
    if (i >= NUM_R * 512) return;
    int r = i >> 9, c = i & 511;
    g_repR[i] = (c < 256) ? g_zR[r * DD + c] : g_u[(size_t)r * DD + (c - 256)];
}

__global__ void k_head(const float* __restrict__ hid, const float* __restrict__ W2,
                       const float* __restrict__ b2, const int* __restrict__ y,
                       int rows, int accIdx) {
    int gw = (blockIdx.x * blockDim.x + threadIdx.x) >> 5;
    int lane = threadIdx.x & 31;
    if (gw >= rows) return;
    float p0 = 0.f, p1 = 0.f;
#pragma unroll
    for (int j = 0; j < 8; j++) {
        int k = lane + 32 * j;
        float h = hid[(size_t)gw * 256 + k];
        p0 = fmaf(h, W2[k * 2], p0);
        p1 = fmaf(h, W2[k * 2 + 1], p1);
    }
    for (int o = 16; o >= 1; o >>= 1) {
        p0 += __shfl_down_sync(0xffffffffu, p0, o);
        p1 += __shfl_down_sync(0xffffffffu, p1, o);
    }
    if (lane == 0) {
        float l0 = p0 + b2[0], l1 = p1 + b2[1];
        float mx = fmaxf(l0, l1);
        float lse = mx + logf(expf(l0 - mx) + expf(l1 - mx));
        atomicAdd(&g_acc[accIdx], ((y[gw] != 0) ? l1 : l0) - lse);
    }
}

__global__ void k_final(float* __restrict__ out) {
    float pred = -(g_acc[0] + 0.1f * g_acc[1]) / 1024.0f;
    float rat  = -g_acc[2] / 64.0f;
    float reg  = g_acc[3] / 32768.0f;
    out[0] = pred + rat - 0.1f * reg;
}

extern "C" void kernel_launch(void* const* d_in, const int* in_sizes, int n_in,
                              void* d_out, int out_size) {
    (void)in_sizes; (void)n_in; (void)out_size;
    const float* x     = (const float*)d_in[0];
    const int*   ei    = (const int*)  d_in[1];
    const int*   et    = (const int*)  d_in[2];
    const int*   batch = (const int*)  d_in[3];
    const int*   yM    = (const int*)  d_in[4];
    const int*   yR    = (const int*)  d_in[5];
    const float* HR    = (const float*)d_in[6];
    const float* nodeW = (const float*)d_in[7];
    const float* nodeB = (const float*)d_in[8];
    const float* Wr    = (const float*)d_in[9];
    const float* Wroot = (const float*)d_in[10];
    const float* gcnB  = (const float*)d_in[11];
    const float* pg    = (const float*)d_in[12];
    const float* puW   = (const float*)d_in[13];
    const float* puB   = (const float*)d_in[14];
    const float* qzW   = (const float*)d_in[15];
    const float* qzB   = (const float*)d_in[16];
    const float* W1    = (const float*)d_in[17];
    const float* b1    = (const float*)d_in[18];
    const float* W2    = (const float*)d_in[19];
    const float* b2    = (const float*)d_in[20];
    float* out = (float*)d_out;

    uint32_t ku0, ku1, ka0, ka1, kzm0, kzm1, kzr0, kzr1;
    tf2x32(0u, 42u, 0u, 0u, ku0, ku1);
    tf2x32(0u, 42u, 0u, 1u, ka0, ka1);
    tf2x32(0u, 42u, 0u, 2u, kzm0, kzm1);
    tf2x32(0u, 42u, 0u, 3u, kzr0, kzr1);

    void* p;
    cudaGetSymbolAddress(&p, g_featsB); float* featsB = (float*)p;
    cudaGetSymbolAddress(&p, g_G);      float* G      = (float*)p;
    cudaGetSymbolAddress(&p, g_Wh);     __nv_bfloat16* Wh  = (__nv_bfloat16*)p;
    cudaGetSymbolAddress(&p, g_Wl);     __nv_bfloat16* Wl  = (__nv_bfloat16*)p;
    cudaGetSymbolAddress(&p, g_nWh);    __nv_bfloat16* nWh = (__nv_bfloat16*)p;
    cudaGetSymbolAddress(&p, g_nWl);    __nv_bfloat16* nWl = (__nv_bfloat16*)p;
    cudaGetSymbolAddress(&p, g_xh);     __nv_bfloat16* xh  = (__nv_bfloat16*)p;
    cudaGetSymbolAddress(&p, g_xl);     __nv_bfloat16* xl  = (__nv_bfloat16*)p;
    cudaGetSymbolAddress(&p, g_Ah);     __nv_bfloat16* Ahp = (__nv_bfloat16*)p;
    cudaGetSymbolAddress(&p, g_Al);     __nv_bfloat16* Alp = (__nv_bfloat16*)p;
    cudaGetSymbolAddress(&p, g_Hall);   float* Hall   = (float*)p;
    cudaGetSymbolAddress(&p, g_pu);     float* pu     = (float*)p;
    cudaGetSymbolAddress(&p, g_qz);     float* qz     = (float*)p;
    cudaGetSymbolAddress(&p, g_repM);   float* repM   = (float*)p;
    cudaGetSymbolAddress(&p, g_repR);   float* repR   = (float*)p;
    cudaGetSymbolAddress(&p, g_hidM);   float* hidM   = (float*)p;
    cudaGetSymbolAddress(&p, g_hidR);   float* hidR   = (float*)p;

    static int smem_set = 0;
    if (!smem_set) {
        cudaFuncSetAttribute(k_bmma, cudaFuncAttributeMaxDynamicSharedMemorySize, 122880);
        smem_set = 1;
    }

    k_zero_init<<<(N_RELS * N_NODES + 255) / 256, 256>>>();
    k_count<<<(N_EDGES + 255) / 256, 256>>>(ei, et);
    k_scan<<<1, 1024>>>();
    k_scatter<<<(N_EDGES + 255) / 256, 256>>>(ei, et);
    k_wsplit<<<(N_LAYERS * GW * 256 + 255) / 256, 256>>>(Wroot, Wr);
    k_wsplitN<<<(256 * D_IN + 255) / 256, 256>>>(nodeW);
    k_asplit<<<(N_NODES * D_IN + 255) / 256, 256>>>(x, xh, xl, N_NODES * D_IN);

    k_bmma<<<dim3(2, (N_NODES + 127) / 128), 256, 122880>>>(
        xh, xl, nWh, nWl, nodeB, nullptr, Ahp, Alp, N_NODES, 256, D_IN, 0);

    for (int l = 0; l < N_LAYERS; l++) {
        k_bmma<<<dim3(GW / 128, (N_NODES + 127) / 128), 256, 122880>>>(
            Ahp, Alp, Wh + (size_t)l * GW * 256, Wl + (size_t)l * GW * 256,
            nullptr, G, nullptr, nullptr, N_NODES, GW, 256, 0);
        k_agg<<<(N_NODES * 32 + 255) / 256, 256>>>(
            gcnB + l * 256, Ahp, Alp, featsB, (l < N_LAYERS - 1) ? 1 : 0);
    }

    k_starts<<<(NUM_M + 256) / 256, 256>>>(batch);
    k_copyHR<<<(NUM_R * DD + 255) / 256, 256>>>(HR);
    k_gmean<<<NUM_M, 256>>>(featsB);

    k_sgemm<<<dim3(4, (N_ALL + 127) / 128), 256>>>(Hall, puW, puB, pu, N_ALL, 512, 256, 1, 0);
    k_sgemm<<<dim3(4, (N_ALL + 127) / 128), 256>>>(Hall, qzW, qzB, qz, N_ALL, 512, 256, 1, 0);

    k_sample_u <<<(N_ALL * DD + 255) / 256, 256>>>(ku0, ku1);
    k_sample_zM<<<(NUM_M * DD + 255) / 256, 256>>>(kzm0, kzm1);
    k_sample_zR<<<(NUM_R * DD + 255) / 256, 256>>>(kzr0, kzr1);

    k_attn<<<NUM_M, 64>>>(pg, yM, ka0, ka1);
    k_pzq<<<NUM_M, 256>>>();

    k_repM<<<(NUM_M * 512 + 255) / 256, 256>>>();
    k_repR<<<(NUM_R * 512 + 255) / 256, 256>>>();
    k_sgemm<<<dim3(2, (NUM_M + 127) / 128), 256>>>(repM, W1, b1, hidM, NUM_M, 256, 512, 0, 1);
    k_sgemm<<<dim3(2, 1), 256>>>(repR, W1, b1, hidR, NUM_R, 256, 512, 0, 1);
    k_head<<<(NUM_M * 32 + 255) / 256, 256>>>(hidM, W2, b2, yM, NUM_M, 0);
    k_head<<<(NUM_R * 32 + 255) / 256, 256>>>(hidR, W2, b2, yR, NUM_R, 2);

    k_final<<<1, 1>>>(out);
}

// round 8
// speedup vs baseline: 1.2238x; 1.0878x over previous
#include <cuda_runtime.h>
#include <cuda_bf16.h>
#include <stdint.h>
#include <math.h>

#define N_NODES 50000
#define N_EDGES 200000
#define D_IN    128
#define DD      256
#define N_LAYERS 4
#define N_RELS  4
#define NUM_M   1024
#define NUM_R   64
#define N_ALL   (NUM_R + NUM_M)
#define GW      1280
#define MPAD    (N_NODES + 128)
#define HPAD    1152

__device__ float g_featsB[N_NODES * DD];
__device__ float g_G[(size_t)N_NODES * GW];
__device__ __nv_bfloat16 g_Wh[N_LAYERS * GW * 256];
__device__ __nv_bfloat16 g_Wl[N_LAYERS * GW * 256];
__device__ __nv_bfloat16 g_nWh[256 * D_IN];
__device__ __nv_bfloat16 g_nWl[256 * D_IN];
__device__ __nv_bfloat16 g_puWh[512 * 256];
__device__ __nv_bfloat16 g_puWl[512 * 256];
__device__ __nv_bfloat16 g_qzWh[512 * 256];
__device__ __nv_bfloat16 g_qzWl[512 * 256];
__device__ __nv_bfloat16 g_w1h[256 * 512];
__device__ __nv_bfloat16 g_w1l[256 * 512];
__device__ __nv_bfloat16 g_xh[(size_t)MPAD * D_IN];
__device__ __nv_bfloat16 g_xl[(size_t)MPAD * D_IN];
__device__ __nv_bfloat16 g_Ah[(size_t)MPAD * DD];
__device__ __nv_bfloat16 g_Al[(size_t)MPAD * DD];
__device__ __nv_bfloat16 g_Hh[HPAD * DD];
__device__ __nv_bfloat16 g_Hl[HPAD * DD];
__device__ __nv_bfloat16 g_repMh[NUM_M * 512];
__device__ __nv_bfloat16 g_repMl[NUM_M * 512];
__device__ __nv_bfloat16 g_repRh[128 * 512];
__device__ __nv_bfloat16 g_repRl[128 * 512];
__device__ int   g_cnt[N_RELS * N_NODES];
__device__ int   g_deg[N_NODES];
__device__ int   g_off[N_NODES + 1];
__device__ int   g_cursor[N_NODES];
__device__ uint2 g_epack[N_EDGES];
__device__ int   g_start[NUM_M + 1];
__device__ float g_pu[N_ALL * 512];
__device__ float g_qz[N_ALL * 512];
__device__ float g_u[N_ALL * DD];
__device__ float g_zM[NUM_M * DD];
__device__ float g_zR[NUM_R * DD];
__device__ float g_An[NUM_M * NUM_R];
__device__ float g_hidM[NUM_M * 256];
__device__ float g_hidR[NUM_R * 256];
__device__ float g_acc[4];

__host__ __device__ __forceinline__ uint32_t rotl32(uint32_t x, int d) {
    return (x << d) | (x >> (32 - d));
}
__host__ __device__ __forceinline__ void tf2x32(uint32_t k0, uint32_t k1,
                                                uint32_t x0, uint32_t x1,
                                                uint32_t& o0, uint32_t& o1) {
    uint32_t ks2 = k0 ^ k1 ^ 0x1BD11BDAu;
    x0 += k0; x1 += k1;
#define TF_RND(R) { x0 += x1; x1 = rotl32(x1, R); x1 ^= x0; }
    TF_RND(13) TF_RND(15) TF_RND(26) TF_RND(6)
    x0 += k1;  x1 += ks2 + 1u;
    TF_RND(17) TF_RND(29) TF_RND(16) TF_RND(24)
    x0 += ks2; x1 += k0 + 2u;
    TF_RND(13) TF_RND(15) TF_RND(26) TF_RND(6)
    x0 += k0;  x1 += k1 + 3u;
    TF_RND(17) TF_RND(29) TF_RND(16) TF_RND(24)
    x0 += k1;  x1 += ks2 + 4u;
    TF_RND(13) TF_RND(15) TF_RND(26) TF_RND(6)
    x0 += ks2; x1 += k0 + 5u;
#undef TF_RND
    o0 = x0; o1 = x1;
}
__device__ __forceinline__ uint32_t rbits(uint32_t k0, uint32_t k1, uint32_t i) {
    uint32_t o0, o1; tf2x32(k0, k1, 0u, i, o0, o1); return o0 ^ o1;
}
__device__ __forceinline__ float erfinv_xla(float x) {
    float w = -log1pf(-x * x), p;
    if (w < 5.0f) {
        w -= 2.5f;
        p = 2.81022636e-08f;
        p = fmaf(p, w, 3.43273939e-07f);  p = fmaf(p, w, -3.5233877e-06f);
        p = fmaf(p, w, -4.39150654e-06f); p = fmaf(p, w, 0.00021858087f);
        p = fmaf(p, w, -0.00125372503f);  p = fmaf(p, w, -0.00417768164f);
        p = fmaf(p, w, 0.246640727f);     p = fmaf(p, w, 1.50140941f);
    } else {
        w = sqrtf(w) - 3.0f;
        p = -0.000200214257f;
        p = fmaf(p, w, 0.000100950558f);  p = fmaf(p, w, 0.00134934322f);
        p = fmaf(p, w, -0.00367342844f);  p = fmaf(p, w, 0.00573950773f);
        p = fmaf(p, w, -0.0076224613f);   p = fmaf(p, w, 0.00943887047f);
        p = fmaf(p, w, 1.00167406f);      p = fmaf(p, w, 2.83297682f);
    }
    return p * x;
}
__device__ __forceinline__ float u01(uint32_t b) {
    return __uint_as_float((b >> 9) | 0x3f800000u) - 1.0f;
}
__device__ __forceinline__ float nrm(uint32_t b) {
    const float LO = -0.99999994f;
    float v = u01(b) * 2.0f + LO;
    v = fmaxf(LO, v);
    return 1.41421356f * erfinv_xla(v);
}
__device__ __forceinline__ float unif(uint32_t b) {
    const float MN = 1e-06f;
    float v = u01(b) * (0.999999f - MN) + MN;
    return fmaxf(MN, v);
}

__global__ void k_zero_init() {
    int i = blockIdx.x * blockDim.x + threadIdx.x;
    if (i < N_RELS * N_NODES) g_cnt[i] = 0;
    if (i < N_NODES) g_deg[i] = 0;
    if (i < 4) g_acc[i] = 0.0f;
}
__global__ void k_count(const int* __restrict__ ei, const int* __restrict__ et) {
    int e = blockIdx.x * blockDim.x + threadIdx.x;
    if (e >= N_EDGES) return;
    int d = ei[N_EDGES + e];
    atomicAdd(&g_cnt[et[e] * N_NODES + d], 1);
    atomicAdd(&g_deg[d], 1);
}
__global__ void k_scan() {
    __shared__ int part[1024];
    int tid = threadIdx.x;
    const int chunk = (N_NODES + 1023) / 1024;
    int lo = tid * chunk, hi = min(lo + chunk, N_NODES);
    int s = 0;
    for (int i = lo; i < hi; i++) s += g_deg[i];
    part[tid] = s;
    __syncthreads();
    for (int o = 1; o < 1024; o <<= 1) {
        int v = (tid >= o) ? part[tid - o] : 0;
        __syncthreads(); part[tid] += v; __syncthreads();
    }
    int run = part[tid] - s;
    for (int i = lo; i < hi; i++) { g_off[i] = run; g_cursor[i] = run; run += g_deg[i]; }
    if (tid == 1023) g_off[N_NODES] = run;
}
__global__ void k_scatter(const int* __restrict__ ei, const int* __restrict__ et) {
    int e = blockIdx.x * blockDim.x + threadIdx.x;
    if (e >= N_EDGES) return;
    int sn = ei[e], d = ei[N_EDGES + e], r = et[e];
    int p = atomicAdd(&g_cursor[d], 1);
    float inv = 1.0f / (float)g_cnt[r * N_NODES + d];
    g_epack[p] = make_uint2((uint32_t)(sn * GW + 256 + (r << 8)), __float_as_uint(inv));
}
__global__ void k_wsplit(const float* __restrict__ Wroot, const float* __restrict__ Wr) {
    int idx = blockIdx.x * blockDim.x + threadIdx.x;
    if (idx >= N_LAYERS * GW * 256) return;
    int l = idx / (GW * 256), rem = idx % (GW * 256);
    int n = rem / 256, k = rem % 256;
    float v;
    if (n < 256) v = Wroot[((size_t)l * 256 + k) * 256 + n];
    else {
        int r = (n >> 8) - 1, h = n & 255;
        v = Wr[(((size_t)l * 4 + r) * 256 + k) * 256 + h];
    }
    __nv_bfloat16 hi = __float2bfloat16(v);
    g_Wh[idx] = hi;
    g_Wl[idx] = __float2bfloat16(v - __bfloat162float(hi));
}
// transpose-split: src is [K][N] row-major; out [n][k]
__global__ void k_wsplitT(const float* __restrict__ src, __nv_bfloat16* __restrict__ h,
                          __nv_bfloat16* __restrict__ l, int N, int K) {
    int idx = blockIdx.x * blockDim.x + threadIdx.x;
    if (idx >= N * K) return;
    int n = idx / K, k = idx % K;
    float v = src[(size_t)k * N + n];
    __nv_bfloat16 hi = __float2bfloat16(v);
    h[idx] = hi;
    l[idx] = __float2bfloat16(v - __bfloat162float(hi));
}
__global__ void k_asplit(const float* __restrict__ src, __nv_bfloat16* __restrict__ h,
                         __nv_bfloat16* __restrict__ l, int n) {
    int i = blockIdx.x * blockDim.x + threadIdx.x;
    if (i >= n) return;
    float v = src[i];
    __nv_bfloat16 hi = __float2bfloat16(v);
    h[i] = hi;
    l[i] = __float2bfloat16(v - __bfloat162float(hi));
}

// ------- pipelined bf16 tensor-core GEMM, BM=BN=128, BK=32, 3 stages, 1 CTA/SM -------
__device__ __forceinline__ void ldm4(uint32_t a, uint32_t& r0, uint32_t& r1,
                                     uint32_t& r2, uint32_t& r3) {
    asm volatile("ldmatrix.sync.aligned.m8n8.x4.shared.b16 {%0,%1,%2,%3}, [%4];"
                 : "=r"(r0), "=r"(r1), "=r"(r2), "=r"(r3) : "r"(a));
}
__device__ __forceinline__ void mma16816(float* c, const uint32_t* a, const uint32_t* b) {
    asm volatile("mma.sync.aligned.m16n8k16.row.col.f32.bf16.bf16.f32 "
                 "{%0,%1,%2,%3},{%4,%5,%6,%7},{%8,%9},{%0,%1,%2,%3};"
                 : "+f"(c[0]), "+f"(c[1]), "+f"(c[2]), "+f"(c[3])
                 : "r"(a[0]), "r"(a[1]), "r"(a[2]), "r"(a[3]), "r"(b[0]), "r"(b[1]));
}
__device__ __forceinline__ void cp16(uint32_t dst, const void* src) {
    asm volatile("cp.async.cg.shared.global [%0], [%1], 16;" :: "r"(dst), "l"(src));
}
#define LOAD_STAGE(s, kq)                                              \
    do {                                                               \
        uint32_t st_ = sm + (s) * 40960;                               \
        _Pragma("unroll")                                              \
        for (int q_ = 0; q_ < 2; q_++) {                               \
            int col_ = (c0 + q_) * 8;                                  \
            uint32_t dd_ = st_ + (row * 40 + col_) * 2;                \
            cp16(dd_,         Agh + (kq) + col_);                      \
            cp16(dd_ + 10240, Agl + (kq) + col_);                      \
            cp16(dd_ + 20480, Bgh + (kq) + col_);                      \
            cp16(dd_ + 30720, Bgl + (kq) + col_);                      \
        }                                                              \
    } while (0)

__global__ void __launch_bounds__(256, 1)
k_bmma(const __nv_bfloat16* __restrict__ Ah, const __nv_bfloat16* __restrict__ Al,
       const __nv_bfloat16* __restrict__ Bh, const __nv_bfloat16* __restrict__ Bl,
       const float* __restrict__ bias, float* __restrict__ C,
       __nv_bfloat16* __restrict__ oh, __nv_bfloat16* __restrict__ ol,
       int M, int N, int K, int relu_out) {
    extern __shared__ __align__(16) __nv_bfloat16 dsm[];
    uint32_t sm = (uint32_t)__cvta_generic_to_shared(dsm);
    int tid = threadIdx.x, lane = tid & 31, wid = tid >> 5;
    int wm = (wid >> 2) * 64, wn = (wid & 3) * 32;
    int bm = blockIdx.y * 128, bn = blockIdx.x * 128;
    int row = tid >> 1, c0 = (tid & 1) * 2;
    const __nv_bfloat16* Agh = Ah + (size_t)(bm + row) * K;
    const __nv_bfloat16* Agl = Al + (size_t)(bm + row) * K;
    const __nv_bfloat16* Bgh = Bh + (size_t)(bn + row) * K;
    const __nv_bfloat16* Bgl = Bl + (size_t)(bn + row) * K;

    float acc[4][4][4];
#pragma unroll
    for (int i = 0; i < 4; i++)
#pragma unroll
        for (int j = 0; j < 4; j++)
#pragma unroll
            for (int q = 0; q < 4; q++) acc[i][j][q] = 0.f;

    LOAD_STAGE(0, 0);
    asm volatile("cp.async.commit_group;");
    if (32 < K) LOAD_STAGE(1, 32);
    asm volatile("cp.async.commit_group;");

    int cur = 0;
    for (int k0 = 0; k0 < K; k0 += 32) {
        int pre = k0 + 64;
        if (pre < K) {
            int s2 = cur + 2; if (s2 >= 3) s2 -= 3;
            LOAD_STAGE(s2, pre);
        }
        asm volatile("cp.async.commit_group;");
        asm volatile("cp.async.wait_group 2;");
        __syncthreads();
        uint32_t st = sm + cur * 40960;
#pragma unroll
        for (int kk = 0; kk < 32; kk += 16) {
            uint32_t bh[4][2], bl[4][2];
            int brow = wn + (lane & 7) + ((lane >> 4) & 1) * 8;
            int bcol = kk + ((lane >> 3) & 1) * 8;
#pragma unroll
            for (int nb = 0; nb < 2; nb++) {
                uint32_t off = ((brow + nb * 16) * 40 + bcol) * 2;
                ldm4(st + 20480 + off, bh[2 * nb][0], bh[2 * nb][1], bh[2 * nb + 1][0], bh[2 * nb + 1][1]);
                ldm4(st + 30720 + off, bl[2 * nb][0], bl[2 * nb][1], bl[2 * nb + 1][0], bl[2 * nb + 1][1]);
            }
            int arow = wm + (lane & 7) + ((lane >> 3) & 1) * 8;
            int acol = kk + ((lane >> 4) & 1) * 8;
#pragma unroll
            for (int mf = 0; mf < 4; mf++) {
                uint32_t ah[4], al[4];
                uint32_t off = ((arow + mf * 16) * 40 + acol) * 2;
                ldm4(st + off, ah[0], ah[1], ah[2], ah[3]);
                ldm4(st + 10240 + off, al[0], al[1], al[2], al[3]);
#pragma unroll
                for (int nf = 0; nf < 4; nf++) {
                    mma16816(acc[mf][nf], ah, bh[nf]);
                    mma16816(acc[mf][nf], ah, bl[nf]);
                    mma16816(acc[mf][nf], al, bh[nf]);
                }
            }
        }
        __syncthreads();
        cur++; if (cur >= 3) cur = 0;
    }
#pragma unroll
    for (int mf = 0; mf < 4; mf++)
#pragma unroll
        for (int nf = 0; nf < 4; nf++) {
            int r0 = bm + wm + mf * 16 + (lane >> 2);
            int c0o = bn + wn + nf * 8 + (lane & 3) * 2;
#pragma unroll
            for (int h = 0; h < 2; h++) {
                int r = r0 + h * 8;
                if (r >= M) continue;
                float v0 = acc[mf][nf][2 * h], v1 = acc[mf][nf][2 * h + 1];
                if (bias) { v0 += bias[c0o]; v1 += bias[c0o + 1]; }
                if (relu_out) { v0 = fmaxf(v0, 0.f); v1 = fmaxf(v1, 0.f); }
                if (oh) {
                    __nv_bfloat16 h0 = __float2bfloat16(v0), h1 = __float2bfloat16(v1);
                    __nv_bfloat162 hp; hp.x = h0; hp.y = h1;
                    __nv_bfloat162 lp;
                    lp.x = __float2bfloat16(v0 - __bfloat162float(h0));
                    lp.y = __float2bfloat16(v1 - __bfloat162float(h1));
                    *(__nv_bfloat162*)(oh + (size_t)r * N + c0o) = hp;
                    *(__nv_bfloat162*)(ol + (size_t)r * N + c0o) = lp;
                } else {
                    *(float2*)(C + (size_t)r * N + c0o) = make_float2(v0, v1);
                }
            }
        }
}

__global__ void k_agg(const float* __restrict__ bias,
                      __nv_bfloat16* __restrict__ oh, __nv_bfloat16* __restrict__ ol,
                      float* __restrict__ out32, int relu) {
    int d = (blockIdx.x * blockDim.x + threadIdx.x) >> 5;
    int lane = threadIdx.x & 31;
    if (d >= N_NODES) return;
    float acc[8];
    const float* g0 = g_G + (size_t)d * GW;
#pragma unroll
    for (int j = 0; j < 8; j++) acc[j] = g0[lane + 32 * j] + bias[lane + 32 * j];
    int s = g_off[d], e = g_off[d + 1];
    int i = s;
    for (; i + 4 <= e; i += 4) {
        uint2 p0 = g_epack[i],     p1 = g_epack[i + 1];
        uint2 p2 = g_epack[i + 2], p3 = g_epack[i + 3];
        const float* gp0 = g_G + p0.x;
        const float* gp1 = g_G + p1.x;
        const float* gp2 = g_G + p2.x;
        const float* gp3 = g_G + p3.x;
        float inv0 = __uint_as_float(p0.y), inv1 = __uint_as_float(p1.y);
        float inv2 = __uint_as_float(p2.y), inv3 = __uint_as_float(p3.y);
#pragma unroll
        for (int j = 0; j < 8; j++) {
            float a = gp0[lane + 32 * j];
            float b = gp1[lane + 32 * j];
            float c = gp2[lane + 32 * j];
            float dd = gp3[lane + 32 * j];
            acc[j] = fmaf(a, inv0, acc[j]);
            acc[j] = fmaf(b, inv1, acc[j]);
            acc[j] = fmaf(c, inv2, acc[j]);
            acc[j] = fmaf(dd, inv3, acc[j]);
        }
    }
    for (; i < e; i++) {
        uint2 p0 = g_epack[i];
        const float* gp0 = g_G + p0.x;
        float inv0 = __uint_as_float(p0.y);
#pragma unroll
        for (int j = 0; j < 8; j++) acc[j] = fmaf(gp0[lane + 32 * j], inv0, acc[j]);
    }
    if (relu) {
#pragma unroll
        for (int j = 0; j < 8; j++) {
            float v = fmaxf(acc[j], 0.f);
            __nv_bfloat16 hi = __float2bfloat16(v);
            size_t idx = (size_t)d * DD + lane + 32 * j;
            oh[idx] = hi;
            ol[idx] = __float2bfloat16(v - __bfloat162float(hi));
        }
    } else {
#pragma unroll
        for (int j = 0; j < 8; j++)
            out32[(size_t)d * DD + lane + 32 * j] = acc[j];
    }
}

__global__ void k_starts(const int* __restrict__ batch) {
    int m = blockIdx.x * blockDim.x + threadIdx.x;
    if (m > NUM_M) return;
    int lo = 0, hi = N_NODES;
    while (lo < hi) { int mid = (lo + hi) >> 1; if (batch[mid] < m) lo = mid + 1; else hi = mid; }
    g_start[m] = lo;
}
__global__ void k_copyHR(const float* __restrict__ HR) {
    int i = blockIdx.x * blockDim.x + threadIdx.x;
    if (i >= NUM_R * DD) return;
    float v = fmaxf(HR[i], 0.f);
    __nv_bfloat16 hi = __float2bfloat16(v);
    g_Hh[i] = hi;
    g_Hl[i] = __float2bfloat16(v - __bfloat162float(hi));
}
__global__ void k_gmean(const float* __restrict__ feats) {
    int m = blockIdx.x, c = threadIdx.x;
    int s = g_start[m], e = g_start[m + 1];
    float acc = 0.f;
    for (int n = s; n < e; n++) acc += feats[(size_t)n * DD + c];
    float v = fmaxf(acc / fmaxf((float)(e - s), 1.0f), 0.f);
    __nv_bfloat16 hi = __float2bfloat16(v);
    size_t idx = (size_t)(NUM_R + m) * DD + c;
    g_Hh[idx] = hi;
    g_Hl[idx] = __float2bfloat16(v - __bfloat162float(hi));
}

__global__ void k_sample_u(unsigned k0, unsigned k1) {
    int i = blockIdx.x * blockDim.x + threadIdx.x;
    if (i >= N_ALL * DD) return;
    int row = i >> 8, col = i & 255;
    g_u[i] = g_pu[row * 512 + col] + expf(g_pu[row * 512 + 256 + col]) * nrm(rbits(k0, k1, i));
}
__global__ void k_sample_zM(unsigned k0, unsigned k1) {
    int i = blockIdx.x * blockDim.x + threadIdx.x;
    if (i >= NUM_M * DD) return;
    int m = i >> 8, col = i & 255;
    int r = (NUM_R + m) * 512;
    g_zM[i] = g_qz[r + col] + expf(g_qz[r + 256 + col]) * nrm(rbits(k0, k1, i));
}
__global__ void k_sample_zR(unsigned k0, unsigned k1) {
    int i = blockIdx.x * blockDim.x + threadIdx.x;
    if (i >= NUM_R * DD) return;
    int r = i >> 8, col = i & 255;
    g_zR[i] = g_qz[r * 512 + col] + expf(g_qz[r * 512 + 256 + col]) * nrm(rbits(k0, k1, i));
}

__global__ void k_attn(const float* __restrict__ pg, const int* __restrict__ yM,
                       unsigned k0, unsigned k1) {
    int m = blockIdx.x, r = threadIdx.x;
    __shared__ float um[DD];
    __shared__ float d2s[NUM_R];
    __shared__ float red[NUM_R];
    for (int i = r; i < DD; i += 64) um[i] = g_u[(size_t)(NUM_R + m) * DD + i];
    __syncthreads();
    float d2 = 0.f;
    const float* ur = g_u + (size_t)r * DD;
    for (int dd = 0; dd < DD; dd++) {
        float t = um[dd] - ur[dd];
        d2 = fmaf(t, t, d2);
    }
    d2s[r] = d2;
    float logp = -0.5f * d2 / expf(pg[0]);
    float logit = logp - logf(fmaxf(-expm1f(logp), 1e-20f));
    float U = unif(rbits(k0, k1, (uint32_t)(m * NUM_R + r)));
    float gn = logf(U) - log1pf(-U);
    float A = 1.0f / (1.0f + expf(-(logit + gn) / 0.3f));
    red[r] = A;
    __syncthreads();
    for (int o = 32; o >= 1; o >>= 1) {
        if (r < o) red[r] += red[r + o];
        __syncthreads();
    }
    g_An[m * NUM_R + r] = A / (red[0] + 1e-8f);
    if (r < 32) {
        int idx = r + (1 - yM[m]) * 32;
        float t = sqrtf(fmaxf(d2s[idx], 1e-12f));
        for (int o = 16; o >= 1; o >>= 1) t += __shfl_down_sync(0xffffffffu, t, o);
        if (r == 0) atomicAdd(&g_acc[3], t);
    }
}

__global__ void k_pzq() {
    int m = blockIdx.x, c = threadIdx.x;
    __shared__ float an[NUM_R];
    if (c < NUM_R) an[c] = g_An[m * NUM_R + c];
    __syncthreads();
    float pm = 0.f, pl = 0.f;
    for (int r = 0; r < NUM_R; r++) {
        float a = an[r];
        pm = fmaf(a, g_qz[r * 512 + c], pm);
        pl = fmaf(a, g_qz[r * 512 + 256 + c], pl);
    }
    float z = g_zM[m * DD + c];
    float qm = g_qz[(NUM_R + m) * 512 + c], ql = g_qz[(NUM_R + m) * 512 + 256 + c];
    float t1 = (z - pm) * expf(-pl);
    float t2 = (z - qm) * expf(-ql);
    float v = (-pl - 0.5f * t1 * t1) - (-ql - 0.5f * t2 * t2);
    __shared__ float red[256];
    red[c] = v;
    __syncthreads();
    for (int o = 128; o >= 1; o >>= 1) {
        if (c < o) red[c] += red[c + o];
        __syncthreads();
    }
    if (c == 0) atomicAdd(&g_acc[1], red[0]);
}

__global__ void k_repM() {
    int i = blockIdx.x * blockDim.x + threadIdx.x;
    if (i >= NUM_M * 512) return;
    int m = i >> 9, c = i & 511;
    float v = (c < 256) ? g_zM[m * DD + c] : g_u[(size_t)(NUM_R + m) * DD + (c - 256)];
    __nv_bfloat16 hi = __float2bfloat16(v);
    g_repMh[i] = hi;
    g_repMl[i] = __float2bfloat16(v - __bfloat162float(hi));
}
__global__ void k_repR() {
    int i = blockIdx.x * blockDim.x + threadIdx.x;
    if (i >= NUM_R * 512) return;
    int r = i >> 9, c = i & 511;
    float v = (c < 256) ? g_zR[r * DD + c] : g_u[(size_t)r * DD + (c - 256)];
    __nv_bfloat16 hi = __float2bfloat16(v);
    g_repRh[i] = hi;
    g_repRl[i] = __float2bfloat16(v - __bfloat162float(hi));
}

__global__ void k_head(const float* __restrict__ hid, const float* __restrict__ W2,
                       const float* __restrict__ b2, const int* __restrict__ y,
                       int rows, int accIdx) {
    int gw = (blockIdx.x * blockDim.x + threadIdx.x) >> 5;
    int lane = threadIdx.x & 31;
    if (gw >= rows) return;
    float p0 = 0.f, p1 = 0.f;
#pragma unroll
    for (int j = 0; j < 8; j++) {
        int k = lane + 32 * j;
        float h = hid[(size_t)gw * 256 + k];
        p0 = fmaf(h, W2[k * 2], p0);
        p1 = fmaf(h, W2[k * 2 + 1], p1);
    }
    for (int o = 16; o >= 1; o >>= 1) {
        p0 += __shfl_down_sync(0xffffffffu, p0, o);
        p1 += __shfl_down_sync(0xffffffffu, p1, o);
    }
    if (lane == 0) {
        float l0 = p0 + b2[0], l1 = p1 + b2[1];
        float mx = fmaxf(l0, l1);
        float lse = mx + logf(expf(l0 - mx) + expf(l1 - mx));
        atomicAdd(&g_acc[accIdx], ((y[gw] != 0) ? l1 : l0) - lse);
    }
}

__global__ void k_final(float* __restrict__ out) {
    float pred = -(g_acc[0] + 0.1f * g_acc[1]) / 1024.0f;
    float rat  = -g_acc[2] / 64.0f;
    float reg  = g_acc[3] / 32768.0f;
    out[0] = pred + rat - 0.1f * reg;
}

extern "C" void kernel_launch(void* const* d_in, const int* in_sizes, int n_in,
                              void* d_out, int out_size) {
    (void)in_sizes; (void)n_in; (void)out_size;
    const float* x     = (const float*)d_in[0];
    const int*   ei    = (const int*)  d_in[1];
    const int*   et    = (const int*)  d_in[2];
    const int*   batch = (const int*)  d_in[3];
    const int*   yM    = (const int*)  d_in[4];
    const int*   yR    = (const int*)  d_in[5];
    const float* HR    = (const float*)d_in[6];
    const float* nodeW = (const float*)d_in[7];
    const float* nodeB = (const float*)d_in[8];
    const float* Wr    = (const float*)d_in[9];
    const float* Wroot = (const float*)d_in[10];
    const float* gcnB  = (const float*)d_in[11];
    const float* pg    = (const float*)d_in[12];
    const float* puW   = (const float*)d_in[13];
    const float* puB   = (const float*)d_in[14];
    const float* qzW   = (const float*)d_in[15];
    const float* qzB   = (const float*)d_in[16];
    const float* W1    = (const float*)d_in[17];
    const float* b1    = (const float*)d_in[18];
    const float* W2    = (const float*)d_in[19];
    const float* b2    = (const float*)d_in[20];
    float* out = (float*)d_out;

    uint32_t ku0, ku1, ka0, ka1, kzm0, kzm1, kzr0, kzr1;
    tf2x32(0u, 42u, 0u, 0u, ku0, ku1);
    tf2x32(0u, 42u, 0u, 1u, ka0, ka1);
    tf2x32(0u, 42u, 0u, 2u, kzm0, kzm1);
    tf2x32(0u, 42u, 0u, 3u, kzr0, kzr1);

    void* p;
    cudaGetSymbolAddress(&p, g_featsB); float* featsB = (float*)p;
    cudaGetSymbolAddress(&p, g_G);      float* G      = (float*)p;
    cudaGetSymbolAddress(&p, g_Wh);     __nv_bfloat16* Wh  = (__nv_bfloat16*)p;
    cudaGetSymbolAddress(&p, g_Wl);     __nv_bfloat16* Wl  = (__nv_bfloat16*)p;
    cudaGetSymbolAddress(&p, g_nWh);    __nv_bfloat16* nWh = (__nv_bfloat16*)p;
    cudaGetSymbolAddress(&p, g_nWl);    __nv_bfloat16* nWl = (__nv_bfloat16*)p;
    cudaGetSymbolAddress(&p, g_puWh);   __nv_bfloat16* puWh = (__nv_bfloat16*)p;
    cudaGetSymbolAddress(&p, g_puWl);   __nv_bfloat16* puWl = (__nv_bfloat16*)p;
    cudaGetSymbolAddress(&p, g_qzWh);   __nv_bfloat16* qzWh = (__nv_bfloat16*)p;
    cudaGetSymbolAddress(&p, g_qzWl);   __nv_bfloat16* qzWl = (__nv_bfloat16*)p;
    cudaGetSymbolAddress(&p, g_w1h);    __nv_bfloat16* w1h = (__nv_bfloat16*)p;
    cudaGetSymbolAddress(&p, g_w1l);    __nv_bfloat16* w1l = (__nv_bfloat16*)p;
    cudaGetSymbolAddress(&p, g_xh);     __nv_bfloat16* xh  = (__nv_bfloat16*)p;
    cudaGetSymbolAddress(&p, g_xl);     __nv_bfloat16* xl  = (__nv_bfloat16*)p;
    cudaGetSymbolAddress(&p, g_Ah);     __nv_bfloat16* Ahp = (__nv_bfloat16*)p;
    cudaGetSymbolAddress(&p, g_Al);     __nv_bfloat16* Alp = (__nv_bfloat16*)p;
    cudaGetSymbolAddress(&p, g_Hh);     __nv_bfloat16* Hh  = (__nv_bfloat16*)p;
    cudaGetSymbolAddress(&p, g_Hl);     __nv_bfloat16* Hl  = (__nv_bfloat16*)p;
    cudaGetSymbolAddress(&p, g_repMh);  __nv_bfloat16* repMh = (__nv_bfloat16*)p;
    cudaGetSymbolAddress(&p, g_repMl);  __nv_bfloat16* repMl = (__nv_bfloat16*)p;
    cudaGetSymbolAddress(&p, g_repRh);  __nv_bfloat16* repRh = (__nv_bfloat16*)p;
    cudaGetSymbolAddress(&p, g_repRl);  __nv_bfloat16* repRl = (__nv_bfloat16*)p;
    cudaGetSymbolAddress(&p, g_pu);     float* pu     = (float*)p;
    cudaGetSymbolAddress(&p, g_qz);     float* qz     = (float*)p;
    cudaGetSymbolAddress(&p, g_hidM);   float* hidM   = (float*)p;
    cudaGetSymbolAddress(&p, g_hidR);   float* hidR   = (float*)p;

    static int smem_set = 0;
    if (!smem_set) {
        cudaFuncSetAttribute(k_bmma, cudaFuncAttributeMaxDynamicSharedMemorySize, 122880);
        smem_set = 1;
    }

    k_zero_init<<<(N_RELS * N_NODES + 255) / 256, 256>>>();
    k_count<<<(N_EDGES + 255) / 256, 256>>>(ei, et);
    k_scan<<<1, 1024>>>();
    k_scatter<<<(N_EDGES + 255) / 256, 256>>>(ei, et);
    k_wsplit<<<(N_LAYERS * GW * 256 + 255) / 256, 256>>>(Wroot, Wr);
    k_wsplitT<<<(256 * D_IN + 255) / 256, 256>>>(nodeW, nWh, nWl, 256, D_IN);
    k_wsplitT<<<(512 * 256 + 255) / 256, 256>>>(puW, puWh, puWl, 512, 256);
    k_wsplitT<<<(512 * 256 + 255) / 256, 256>>>(qzW, qzWh, qzWl, 512, 256);
    k_wsplitT<<<(256 * 512 + 255) / 256, 256>>>(W1, w1h, w1l, 256, 512);
    k_asplit<<<(N_NODES * D_IN + 255) / 256, 256>>>(x, xh, xl, N_NODES * D_IN);

    // node encoder, bias + bf16 split fused
    k_bmma<<<dim3(2, (N_NODES + 127) / 128), 256, 122880>>>(
        xh, xl, nWh, nWl, nodeB, nullptr, Ahp, Alp, N_NODES, 256, D_IN, 0);

    for (int l = 0; l < N_LAYERS; l++) {
        k_bmma<<<dim3(GW / 128, (N_NODES + 127) / 128), 256, 122880>>>(
            Ahp, Alp, Wh + (size_t)l * GW * 256, Wl + (size_t)l * GW * 256,
            nullptr, G, nullptr, nullptr, N_NODES, GW, 256, 0);
        k_agg<<<(N_NODES * 32 + 255) / 256, 256>>>(
            gcnB + l * 256, Ahp, Alp, featsB, (l < N_LAYERS - 1) ? 1 : 0);
    }

    k_starts<<<(NUM_M + 256) / 256, 256>>>(batch);
    k_copyHR<<<(NUM_R * DD + 255) / 256, 256>>>(HR);
    k_gmean<<<NUM_M, 256>>>(featsB);

    // pu / qz projections on tensor cores (input already relu'd + split)
    k_bmma<<<dim3(4, HPAD / 128), 256, 122880>>>(
        Hh, Hl, puWh, puWl, puB, pu, nullptr, nullptr, N_ALL, 512, 256, 0);
    k_bmma<<<dim3(4, HPAD / 128), 256, 122880>>>(
        Hh, Hl, qzWh, qzWl, qzB, qz, nullptr, nullptr, N_ALL, 512, 256, 0);

    k_sample_u <<<(N_ALL * DD + 255) / 256, 256>>>(ku0, ku1);
    k_sample_zM<<<(NUM_M * DD + 255) / 256, 256>>>(kzm0, kzm1);
    k_sample_zR<<<(NUM_R * DD + 255) / 256, 256>>>(kzr0, kzr1);

    k_attn<<<NUM_M, 64>>>(pg, yM, ka0, ka1);
    k_pzq<<<NUM_M, 256>>>();

    k_repM<<<(NUM_M * 512 + 255) / 256, 256>>>();
    k_repR<<<(NUM_R * 512 + 255) / 256, 256>>>();
    k_bmma<<<dim3(2, NUM_M / 128), 256, 122880>>>(
        repMh, repMl, w1h, w1l, b1, hidM, nullptr, nullptr, NUM_M, 256, 512, 1);
    k_bmma<<<dim3(2, 1), 256, 122880>>>(
        repRh, repRl, w1h, w1l, b1, hidR, nullptr, nullptr, NUM_R, 256, 512, 1);
    k_head<<<(NUM_M * 32 + 255) / 256, 256>>>(hidM, W2, b2, yM, NUM_M, 0);
    k_head<<<(NUM_R * 32 + 255) / 256, 256>>>(hidR, W2, b2, yR, NUM_R, 2);

    k_final<<<1, 1>>>(out);
}

// round 9
// speedup vs baseline: 1.5317x; 1.2516x over previous
#include <cuda_runtime.h>
#include <cuda_bf16.h>
#include <cuda_fp16.h>
#include <stdint.h>
#include <math.h>

#define N_NODES 50000
#define N_EDGES 200000
#define D_IN    128
#define DD      256
#define N_LAYERS 4
#define N_RELS  4
#define NUM_M   1024
#define NUM_R   64
#define N_ALL   (NUM_R + NUM_M)
#define GW      1280
#define MPAD    (N_NODES + 128)
#define HPAD    1152

__device__ float g_featsB[N_NODES * DD];
__device__ float g_G[(size_t)N_NODES * GW];
__device__ __half g_Wfh[N_LAYERS * GW * 256];
__device__ __half g_Wfl[N_LAYERS * GW * 256];
__device__ __half g_nWfh[256 * D_IN];
__device__ __half g_nWfl[256 * D_IN];
__device__ __half g_xf[(size_t)MPAD * D_IN];
__device__ __half g_Af[(size_t)MPAD * DD];
__device__ __nv_bfloat16 g_puWh[512 * 256];
__device__ __nv_bfloat16 g_puWl[512 * 256];
__device__ __nv_bfloat16 g_qzWh[512 * 256];
__device__ __nv_bfloat16 g_qzWl[512 * 256];
__device__ __nv_bfloat16 g_w1h[256 * 512];
__device__ __nv_bfloat16 g_w1l[256 * 512];
__device__ __nv_bfloat16 g_Hh[HPAD * DD];
__device__ __nv_bfloat16 g_Hl[HPAD * DD];
__device__ __nv_bfloat16 g_repMh[NUM_M * 512];
__device__ __nv_bfloat16 g_repMl[NUM_M * 512];
__device__ __nv_bfloat16 g_repRh[128 * 512];
__device__ __nv_bfloat16 g_repRl[128 * 512];
__device__ int   g_cnt[N_RELS * N_NODES];
__device__ int   g_deg[N_NODES];
__device__ int   g_off[N_NODES + 1];
__device__ int   g_cursor[N_NODES];
__device__ uint2 g_epack[N_EDGES];
__device__ int   g_start[NUM_M + 1];
__device__ float g_pu[N_ALL * 512];
__device__ float g_qz[N_ALL * 512];
__device__ float g_u[N_ALL * DD];
__device__ float g_zM[NUM_M * DD];
__device__ float g_zR[NUM_R * DD];
__device__ float g_An[NUM_M * NUM_R];
__device__ float g_hidM[NUM_M * 256];
__device__ float g_hidR[NUM_R * 256];
__device__ float g_acc[4];

__host__ __device__ __forceinline__ uint32_t rotl32(uint32_t x, int d) {
    return (x << d) | (x >> (32 - d));
}
__host__ __device__ __forceinline__ void tf2x32(uint32_t k0, uint32_t k1,
                                                uint32_t x0, uint32_t x1,
                                                uint32_t& o0, uint32_t& o1) {
    uint32_t ks2 = k0 ^ k1 ^ 0x1BD11BDAu;
    x0 += k0; x1 += k1;
#define TF_RND(R) { x0 += x1; x1 = rotl32(x1, R); x1 ^= x0; }
    TF_RND(13) TF_RND(15) TF_RND(26) TF_RND(6)
    x0 += k1;  x1 += ks2 + 1u;
    TF_RND(17) TF_RND(29) TF_RND(16) TF_RND(24)
    x0 += ks2; x1 += k0 + 2u;
    TF_RND(13) TF_RND(15) TF_RND(26) TF_RND(6)
    x0 += k0;  x1 += k1 + 3u;
    TF_RND(17) TF_RND(29) TF_RND(16) TF_RND(24)
    x0 += k1;  x1 += ks2 + 4u;
    TF_RND(13) TF_RND(15) TF_RND(26) TF_RND(6)
    x0 += ks2; x1 += k0 + 5u;
#undef TF_RND
    o0 = x0; o1 = x1;
}
__device__ __forceinline__ uint32_t rbits(uint32_t k0, uint32_t k1, uint32_t i) {
    uint32_t o0, o1; tf2x32(k0, k1, 0u, i, o0, o1); return o0 ^ o1;
}
__device__ __forceinline__ float erfinv_xla(float x) {
    float w = -log1pf(-x * x), p;
    if (w < 5.0f) {
        w -= 2.5f;
        p = 2.81022636e-08f;
        p = fmaf(p, w, 3.43273939e-07f);  p = fmaf(p, w, -3.5233877e-06f);
        p = fmaf(p, w, -4.39150654e-06f); p = fmaf(p, w, 0.00021858087f);
        p = fmaf(p, w, -0.00125372503f);  p = fmaf(p, w, -0.00417768164f);
        p = fmaf(p, w, 0.246640727f);     p = fmaf(p, w, 1.50140941f);
    } else {
        w = sqrtf(w) - 3.0f;
        p = -0.000200214257f;
        p = fmaf(p, w, 0.000100950558f);  p = fmaf(p, w, 0.00134934322f);
        p = fmaf(p, w, -0.00367342844f);  p = fmaf(p, w, 0.00573950773f);
        p = fmaf(p, w, -0.0076224613f);   p = fmaf(p, w, 0.00943887047f);
        p = fmaf(p, w, 1.00167406f);      p = fmaf(p, w, 2.83297682f);
    }
    return p * x;
}
__device__ __forceinline__ float u01(uint32_t b) {
    return __uint_as_float((b >> 9) | 0x3f800000u) - 1.0f;
}
__device__ __forceinline__ float nrm(uint32_t b) {
    const float LO = -0.99999994f;
    float v = u01(b) * 2.0f + LO;
    v = fmaxf(LO, v);
    return 1.41421356f * erfinv_xla(v);
}
__device__ __forceinline__ float unif(uint32_t b) {
    const float MN = 1e-06f;
    float v = u01(b) * (0.999999f - MN) + MN;
    return fmaxf(MN, v);
}

__global__ void k_zero_init() {
    int i = blockIdx.x * blockDim.x + threadIdx.x;
    if (i < N_RELS * N_NODES) g_cnt[i] = 0;
    if (i < N_NODES) g_deg[i] = 0;
    if (i < 4) g_acc[i] = 0.0f;
}
__global__ void k_count(const int* __restrict__ ei, const int* __restrict__ et) {
    int e = blockIdx.x * blockDim.x + threadIdx.x;
    if (e >= N_EDGES) return;
    int d = ei[N_EDGES + e];
    atomicAdd(&g_cnt[et[e] * N_NODES + d], 1);
    atomicAdd(&g_deg[d], 1);
}
__global__ void k_scan() {
    __shared__ int part[1024];
    int tid = threadIdx.x;
    const int chunk = (N_NODES + 1023) / 1024;
    int lo = tid * chunk, hi = min(lo + chunk, N_NODES);
    int s = 0;
    for (int i = lo; i < hi; i++) s += g_deg[i];
    part[tid] = s;
    __syncthreads();
    for (int o = 1; o < 1024; o <<= 1) {
        int v = (tid >= o) ? part[tid - o] : 0;
        __syncthreads(); part[tid] += v; __syncthreads();
    }
    int run = part[tid] - s;
    for (int i = lo; i < hi; i++) { g_off[i] = run; g_cursor[i] = run; run += g_deg[i]; }
    if (tid == 1023) g_off[N_NODES] = run;
}
__global__ void k_scatter(const int* __restrict__ ei, const int* __restrict__ et) {
    int e = blockIdx.x * blockDim.x + threadIdx.x;
    if (e >= N_EDGES) return;
    int sn = ei[e], d = ei[N_EDGES + e], r = et[e];
    int p = atomicAdd(&g_cursor[d], 1);
    float inv = 1.0f / (float)g_cnt[r * N_NODES + d];
    g_epack[p] = make_uint2((uint32_t)(sn * GW + 256 + (r << 8)), __float_as_uint(inv));
}
// fp16 hi/lo layer weights, [l][n][k]
__global__ void k_wsplitF(const float* __restrict__ Wroot, const float* __restrict__ Wr) {
    int idx = blockIdx.x * blockDim.x + threadIdx.x;
    if (idx >= N_LAYERS * GW * 256) return;
    int l = idx / (GW * 256), rem = idx % (GW * 256);
    int n = rem / 256, k = rem % 256;
    float v;
    if (n < 256) v = Wroot[((size_t)l * 256 + k) * 256 + n];
    else {
        int r = (n >> 8) - 1, h = n & 255;
        v = Wr[(((size_t)l * 4 + r) * 256 + k) * 256 + h];
    }
    __half hi = __float2half_rn(v);
    g_Wfh[idx] = hi;
    g_Wfl[idx] = __float2half_rn(v - __half2float(hi));
}
__global__ void k_wsplitTF(const float* __restrict__ src, __half* __restrict__ h,
                           __half* __restrict__ l, int N, int K) {
    int idx = blockIdx.x * blockDim.x + threadIdx.x;
    if (idx >= N * K) return;
    int n = idx / K, k = idx % K;
    float v = src[(size_t)k * N + n];
    __half hi = __float2half_rn(v);
    h[idx] = hi;
    l[idx] = __float2half_rn(v - __half2float(hi));
}
// bf16 hi/lo transpose-split for tail weights
__global__ void k_wsplitT(const float* __restrict__ src, __nv_bfloat16* __restrict__ h,
                          __nv_bfloat16* __restrict__ l, int N, int K) {
    int idx = blockIdx.x * blockDim.x + threadIdx.x;
    if (idx >= N * K) return;
    int n = idx / K, k = idx % K;
    float v = src[(size_t)k * N + n];
    __nv_bfloat16 hi = __float2bfloat16(v);
    h[idx] = hi;
    l[idx] = __float2bfloat16(v - __bfloat162float(hi));
}
__global__ void k_tohalf(const float* __restrict__ src, __half* __restrict__ dst, int n) {
    int i = blockIdx.x * blockDim.x + threadIdx.x;
    if (i < n) dst[i] = __float2half_rn(src[i]);
}

__device__ __forceinline__ void ldm4(uint32_t a, uint32_t& r0, uint32_t& r1,
                                     uint32_t& r2, uint32_t& r3) {
    asm volatile("ldmatrix.sync.aligned.m8n8.x4.shared.b16 {%0,%1,%2,%3}, [%4];"
                 : "=r"(r0), "=r"(r1), "=r"(r2), "=r"(r3) : "r"(a));
}
__device__ __forceinline__ void mma_bf(float* c, const uint32_t* a, const uint32_t* b) {
    asm volatile("mma.sync.aligned.m16n8k16.row.col.f32.bf16.bf16.f32 "
                 "{%0,%1,%2,%3},{%4,%5,%6,%7},{%8,%9},{%0,%1,%2,%3};"
                 : "+f"(c[0]), "+f"(c[1]), "+f"(c[2]), "+f"(c[3])
                 : "r"(a[0]), "r"(a[1]), "r"(a[2]), "r"(a[3]), "r"(b[0]), "r"(b[1]));
}
__device__ __forceinline__ void mma_fp(float* c, const uint32_t* a, const uint32_t* b) {
    asm volatile("mma.sync.aligned.m16n8k16.row.col.f32.f16.f16.f32 "
                 "{%0,%1,%2,%3},{%4,%5,%6,%7},{%8,%9},{%0,%1,%2,%3};"
                 : "+f"(c[0]), "+f"(c[1]), "+f"(c[2]), "+f"(c[3])
                 : "r"(a[0]), "r"(a[1]), "r"(a[2]), "r"(a[3]), "r"(b[0]), "r"(b[1]));
}
__device__ __forceinline__ void cp16(uint32_t dst, const void* src) {
    asm volatile("cp.async.cg.shared.global [%0], [%1], 16;" :: "r"(dst), "l"(src));
}

// ===== fp16 2-term GEMM: A single fp16, B hi/lo fp16. BM=BN=128, BK=32, 3 stages =====
#define LOAD_STAGE_F(s, kq)                                            \
    do {                                                               \
        uint32_t st_ = smq + (s) * 30720;                              \
        _Pragma("unroll")                                              \
        for (int q_ = 0; q_ < 2; q_++) {                               \
            int col_ = (c0 + q_) * 8;                                  \
            uint32_t dd_ = st_ + (row * 40 + col_) * 2;                \
            cp16(dd_,         Agf + (kq) + col_);                      \
            cp16(dd_ + 10240, Bgh + (kq) + col_);                      \
            cp16(dd_ + 20480, Bgl + (kq) + col_);                      \
        }                                                              \
    } while (0)

__global__ void __launch_bounds__(256, 1)
k_fmma(const __half* __restrict__ Af, const __half* __restrict__ Bh,
       const __half* __restrict__ Bl, const float* __restrict__ bias,
       float* __restrict__ C, __half* __restrict__ oF,
       int M, int N, int K, int relu_out) {
    extern __shared__ __align__(16) __half dsmf[];
    uint32_t smq = (uint32_t)__cvta_generic_to_shared(dsmf);
    int tid = threadIdx.x, lane = tid & 31, wid = tid >> 5;
    int wm = (wid >> 2) * 64, wn = (wid & 3) * 32;
    int bm = blockIdx.y * 128, bn = blockIdx.x * 128;
    int row = tid >> 1, c0 = (tid & 1) * 2;
    const __half* Agf = Af + (size_t)(bm + row) * K;
    const __half* Bgh = Bh + (size_t)(bn + row) * K;
    const __half* Bgl = Bl + (size_t)(bn + row) * K;

    float acc[4][4][4];
#pragma unroll
    for (int i = 0; i < 4; i++)
#pragma unroll
        for (int j = 0; j < 4; j++)
#pragma unroll
            for (int q = 0; q < 4; q++) acc[i][j][q] = 0.f;

    LOAD_STAGE_F(0, 0);
    asm volatile("cp.async.commit_group;");
    if (32 < K) LOAD_STAGE_F(1, 32);
    asm volatile("cp.async.commit_group;");

    int cur = 0;
    for (int k0 = 0; k0 < K; k0 += 32) {
        int pre = k0 + 64;
        if (pre < K) {
            int s2 = cur + 2; if (s2 >= 3) s2 -= 3;
            LOAD_STAGE_F(s2, pre);
        }
        asm volatile("cp.async.commit_group;");
        asm volatile("cp.async.wait_group 2;");
        __syncthreads();
        uint32_t st = smq + cur * 30720;
#pragma unroll
        for (int kk = 0; kk < 32; kk += 16) {
            uint32_t bh[4][2], bl[4][2];
            int brow = wn + (lane & 7) + ((lane >> 4) & 1) * 8;
            int bcol = kk + ((lane >> 3) & 1) * 8;
#pragma unroll
            for (int nb = 0; nb < 2; nb++) {
                uint32_t off = ((brow + nb * 16) * 40 + bcol) * 2;
                ldm4(st + 10240 + off, bh[2 * nb][0], bh[2 * nb][1], bh[2 * nb + 1][0], bh[2 * nb + 1][1]);
                ldm4(st + 20480 + off, bl[2 * nb][0], bl[2 * nb][1], bl[2 * nb + 1][0], bl[2 * nb + 1][1]);
            }
            int arow = wm + (lane & 7) + ((lane >> 3) & 1) * 8;
            int acol = kk + ((lane >> 4) & 1) * 8;
#pragma unroll
            for (int mf = 0; mf < 4; mf++) {
                uint32_t a[4];
                uint32_t off = ((arow + mf * 16) * 40 + acol) * 2;
                ldm4(st + off, a[0], a[1], a[2], a[3]);
#pragma unroll
                for (int nf = 0; nf < 4; nf++) {
                    mma_fp(acc[mf][nf], a, bh[nf]);
                    mma_fp(acc[mf][nf], a, bl[nf]);
                }
            }
        }
        __syncthreads();
        cur++; if (cur >= 3) cur = 0;
    }
#pragma unroll
    for (int mf = 0; mf < 4; mf++)
#pragma unroll
        for (int nf = 0; nf < 4; nf++) {
            int r0 = bm + wm + mf * 16 + (lane >> 2);
            int c0o = bn + wn + nf * 8 + (lane & 3) * 2;
#pragma unroll
            for (int h = 0; h < 2; h++) {
                int r = r0 + h * 8;
                if (r >= M) continue;
                float v0 = acc[mf][nf][2 * h], v1 = acc[mf][nf][2 * h + 1];
                if (bias) { v0 += bias[c0o]; v1 += bias[c0o + 1]; }
                if (relu_out) { v0 = fmaxf(v0, 0.f); v1 = fmaxf(v1, 0.f); }
                if (oF) {
                    *(__half2*)(oF + (size_t)r * N + c0o) = __floats2half2_rn(v0, v1);
                } else {
                    *(float2*)(C + (size_t)r * N + c0o) = make_float2(v0, v1);
                }
            }
        }
}

// ===== bf16 3-term GEMM for tail (unchanged from R8) =====
#define LOAD_STAGE(s, kq)                                              \
    do {                                                               \
        uint32_t st_ = sm + (s) * 40960;                               \
        _Pragma("unroll")                                              \
        for (int q_ = 0; q_ < 2; q_++) {                               \
            int col_ = (c0 + q_) * 8;                                  \
            uint32_t dd_ = st_ + (row * 40 + col_) * 2;                \
            cp16(dd_,         Agh + (kq) + col_);                      \
            cp16(dd_ + 10240, Agl + (kq) + col_);                      \
            cp16(dd_ + 20480, Bgh + (kq) + col_);                      \
            cp16(dd_ + 30720, Bgl + (kq) + col_);                      \
        }                                                              \
    } while (0)

__global__ void __launch_bounds__(256, 1)
k_bmma(const __nv_bfloat16* __restrict__ Ah, const __nv_bfloat16* __restrict__ Al,
       const __nv_bfloat16* __restrict__ Bh, const __nv_bfloat16* __restrict__ Bl,
       const float* __restrict__ bias, float* __restrict__ C,
       int M, int N, int K, int relu_out) {
    extern __shared__ __align__(16) __nv_bfloat16 dsm[];
    uint32_t sm = (uint32_t)__cvta_generic_to_shared(dsm);
    int tid = threadIdx.x, lane = tid & 31, wid = tid >> 5;
    int wm = (wid >> 2) * 64, wn = (wid & 3) * 32;
    int bm = blockIdx.y * 128, bn = blockIdx.x * 128;
    int row = tid >> 1, c0 = (tid & 1) * 2;
    const __nv_bfloat16* Agh = Ah + (size_t)(bm + row) * K;
    const __nv_bfloat16* Agl = Al + (size_t)(bm + row) * K;
    const __nv_bfloat16* Bgh = Bh + (size_t)(bn + row) * K;
    const __nv_bfloat16* Bgl = Bl + (size_t)(bn + row) * K;

    float acc[4][4][4];
#pragma unroll
    for (int i = 0; i < 4; i++)
#pragma unroll
        for (int j = 0; j < 4; j++)
#pragma unroll
            for (int q = 0; q < 4; q++) acc[i][j][q] = 0.f;

    LOAD_STAGE(0, 0);
    asm volatile("cp.async.commit_group;");
    if (32 < K) LOAD_STAGE(1, 32);
    asm volatile("cp.async.commit_group;");

    int cur = 0;
    for (int k0 = 0; k0 < K; k0 += 32) {
        int pre = k0 + 64;
        if (pre < K) {
            int s2 = cur + 2; if (s2 >= 3) s2 -= 3;
            LOAD_STAGE(s2, pre);
        }
        asm volatile("cp.async.commit_group;");
        asm volatile("cp.async.wait_group 2;");
        __syncthreads();
        uint32_t st = sm + cur * 40960;
#pragma unroll
        for (int kk = 0; kk < 32; kk += 16) {
            uint32_t bh[4][2], bl[4][2];
            int brow = wn + (lane & 7) + ((lane >> 4) & 1) * 8;
            int bcol = kk + ((lane >> 3) & 1) * 8;
#pragma unroll
            for (int nb = 0; nb < 2; nb++) {
                uint32_t off = ((brow + nb * 16) * 40 + bcol) * 2;
                ldm4(st + 20480 + off, bh[2 * nb][0], bh[2 * nb][1], bh[2 * nb + 1][0], bh[2 * nb + 1][1]);
                ldm4(st + 30720 + off, bl[2 * nb][0], bl[2 * nb][1], bl[2 * nb + 1][0], bl[2 * nb + 1][1]);
            }
            int arow = wm + (lane & 7) + ((lane >> 3) & 1) * 8;
            int acol = kk + ((lane >> 4) & 1) * 8;
#pragma unroll
            for (int mf = 0; mf < 4; mf++) {
                uint32_t ah[4], al[4];
                uint32_t off = ((arow + mf * 16) * 40 + acol) * 2;
                ldm4(st + off, ah[0], ah[1], ah[2], ah[3]);
                ldm4(st + 10240 + off, al[0], al[1], al[2], al[3]);
#pragma unroll
                for (int nf = 0; nf < 4; nf++) {
                    mma_bf(acc[mf][nf], ah, bh[nf]);
                    mma_bf(acc[mf][nf], ah, bl[nf]);
                    mma_bf(acc[mf][nf], al, bh[nf]);
                }
            }
        }
        __syncthreads();
        cur++; if (cur >= 3) cur = 0;
    }
#pragma unroll
    for (int mf = 0; mf < 4; mf++)
#pragma unroll
        for (int nf = 0; nf < 4; nf++) {
            int r0 = bm + wm + mf * 16 + (lane >> 2);
            int c0o = bn + wn + nf * 8 + (lane & 3) * 2;
#pragma unroll
            for (int h = 0; h < 2; h++) {
                int r = r0 + h * 8;
                if (r >= M) continue;
                float v0 = acc[mf][nf][2 * h], v1 = acc[mf][nf][2 * h + 1];
                if (bias) { v0 += bias[c0o]; v1 += bias[c0o + 1]; }
                if (relu_out) { v0 = fmaxf(v0, 0.f); v1 = fmaxf(v1, 0.f); }
                *(float2*)(C + (size_t)r * N + c0o) = make_float2(v0, v1);
            }
        }
}

// aggregation, float4-vectorized; hidden layers emit fp16 single, last emits fp32
__global__ void k_agg(const float* __restrict__ bias, __half* __restrict__ ofh,
                      float* __restrict__ out32, int relu) {
    int d = (blockIdx.x * blockDim.x + threadIdx.x) >> 5;
    int lane = threadIdx.x & 31;
    if (d >= N_NODES) return;
    const float4* g0 = (const float4*)(g_G + (size_t)d * GW);
    const float4* b4 = (const float4*)bias;
    float4 a0 = g0[lane], a1 = g0[32 + lane];
    float4 bb0 = b4[lane], bb1 = b4[32 + lane];
    a0.x += bb0.x; a0.y += bb0.y; a0.z += bb0.z; a0.w += bb0.w;
    a1.x += bb1.x; a1.y += bb1.y; a1.z += bb1.z; a1.w += bb1.w;
    int s = g_off[d], e = g_off[d + 1];
    int i = s;
#define AGG_EDGE(P)                                                     \
    {                                                                   \
        const float4* gp = (const float4*)(g_G + (P).x);                \
        float inv = __uint_as_float((P).y);                             \
        float4 v0 = gp[lane], v1 = gp[32 + lane];                       \
        a0.x = fmaf(v0.x, inv, a0.x); a0.y = fmaf(v0.y, inv, a0.y);     \
        a0.z = fmaf(v0.z, inv, a0.z); a0.w = fmaf(v0.w, inv, a0.w);     \
        a1.x = fmaf(v1.x, inv, a1.x); a1.y = fmaf(v1.y, inv, a1.y);     \
        a1.z = fmaf(v1.z, inv, a1.z); a1.w = fmaf(v1.w, inv, a1.w);     \
    }
    for (; i + 4 <= e; i += 4) {
        uint2 p0 = g_epack[i],     p1 = g_epack[i + 1];
        uint2 p2 = g_epack[i + 2], p3 = g_epack[i + 3];
        AGG_EDGE(p0) AGG_EDGE(p1) AGG_EDGE(p2) AGG_EDGE(p3)
    }
    for (; i < e; i++) {
        uint2 p0 = g_epack[i];
        AGG_EDGE(p0)
    }
#undef AGG_EDGE
    if (relu) {
        a0.x = fmaxf(a0.x, 0.f); a0.y = fmaxf(a0.y, 0.f);
        a0.z = fmaxf(a0.z, 0.f); a0.w = fmaxf(a0.w, 0.f);
        a1.x = fmaxf(a1.x, 0.f); a1.y = fmaxf(a1.y, 0.f);
        a1.z = fmaxf(a1.z, 0.f); a1.w = fmaxf(a1.w, 0.f);
        __half2* o = (__half2*)(ofh + (size_t)d * DD);
        o[lane * 2]          = __floats2half2_rn(a0.x, a0.y);
        o[lane * 2 + 1]      = __floats2half2_rn(a0.z, a0.w);
        o[64 + lane * 2]     = __floats2half2_rn(a1.x, a1.y);
        o[64 + lane * 2 + 1] = __floats2half2_rn(a1.z, a1.w);
    } else {
        float4* o = (float4*)(out32 + (size_t)d * DD);
        o[lane] = a0;
        o[32 + lane] = a1;
    }
}

__global__ void k_starts(const int* __restrict__ batch) {
    int m = blockIdx.x * blockDim.x + threadIdx.x;
    if (m > NUM_M) return;
    int lo = 0, hi = N_NODES;
    while (lo < hi) { int mid = (lo + hi) >> 1; if (batch[mid] < m) lo = mid + 1; else hi = mid; }
    g_start[m] = lo;
}
__global__ void k_copyHR(const float* __restrict__ HR) {
    int i = blockIdx.x * blockDim.x + threadIdx.x;
    if (i >= NUM_R * DD) return;
    float v = fmaxf(HR[i], 0.f);
    __nv_bfloat16 hi = __float2bfloat16(v);
    g_Hh[i] = hi;
    g_Hl[i] = __float2bfloat16(v - __bfloat162float(hi));
}
__global__ void k_gmean(const float* __restrict__ feats) {
    int m = blockIdx.x, c = threadIdx.x;
    int s = g_start[m], e = g_start[m + 1];
    float acc = 0.f;
    for (int n = s; n < e; n++) acc += feats[(size_t)n * DD + c];
    float v = fmaxf(acc / fmaxf((float)(e - s), 1.0f), 0.f);
    __nv_bfloat16 hi = __float2bfloat16(v);
    size_t idx = (size_t)(NUM_R + m) * DD + c;
    g_Hh[idx] = hi;
    g_Hl[idx] = __float2bfloat16(v - __bfloat162float(hi));
}

__global__ void k_sample_u(unsigned k0, unsigned k1) {
    int i = blockIdx.x * blockDim.x + threadIdx.x;
    if (i >= N_ALL * DD) return;
    int row = i >> 8, col = i & 255;
    g_u[i] = g_pu[row * 512 + col] + expf(g_pu[row * 512 + 256 + col]) * nrm(rbits(k0, k1, i));
}
__global__ void k_sample_zM(unsigned k0, unsigned k1) {
    int i = blockIdx.x * blockDim.x + threadIdx.x;
    if (i >= NUM_M * DD) return;
    int m = i >> 8, col = i & 255;
    int r = (NUM_R + m) * 512;
    g_zM[i] = g_qz[r + col] + expf(g_qz[r + 256 + col]) * nrm(rbits(k0, k1, i));
}
__global__ void k_sample_zR(unsigned k0, unsigned k1) {
    int i = blockIdx.x * blockDim.x + threadIdx.x;
    if (i >= NUM_R * DD) return;
    int r = i >> 8, col = i & 255;
    g_zR[i] = g_qz[r * 512 + col] + expf(g_qz[r * 512 + 256 + col]) * nrm(rbits(k0, k1, i));
}

__global__ void k_attn(const float* __restrict__ pg, const int* __restrict__ yM,
                       unsigned k0, unsigned k1) {
    int m = blockIdx.x, r = threadIdx.x;
    __shared__ float um[DD];
    __shared__ float d2s[NUM_R];
    __shared__ float red[NUM_R];
    for (int i = r; i < DD; i += 64) um[i] = g_u[(size_t)(NUM_R + m) * DD + i];
    __syncthreads();
    float d2 = 0.f;
    const float* ur = g_u + (size_t)r * DD;
    for (int dd = 0; dd < DD; dd++) {
        float t = um[dd] - ur[dd];
        d2 = fmaf(t, t, d2);
    }
    d2s[r] = d2;
    float logp = -0.5f * d2 / expf(pg[0]);
    float logit = logp - logf(fmaxf(-expm1f(logp), 1e-20f));
    float U = unif(rbits(k0, k1, (uint32_t)(m * NUM_R + r)));
    float gn = logf(U) - log1pf(-U);
    float A = 1.0f / (1.0f + expf(-(logit + gn) / 0.3f));
    red[r] = A;
    __syncthreads();
    for (int o = 32; o >= 1; o >>= 1) {
        if (r < o) red[r] += red[r + o];
        __syncthreads();
    }
    g_An[m * NUM_R + r] = A / (red[0] + 1e-8f);
    if (r < 32) {
        int idx = r + (1 - yM[m]) * 32;
        float t = sqrtf(fmaxf(d2s[idx], 1e-12f));
        for (int o = 16; o >= 1; o >>= 1) t += __shfl_down_sync(0xffffffffu, t, o);
        if (r == 0) atomicAdd(&g_acc[3], t);
    }
}

__global__ void k_pzq() {
    int m = blockIdx.x, c = threadIdx.x;
    __shared__ float an[NUM_R];
    if (c < NUM_R) an[c] = g_An[m * NUM_R + c];
    __syncthreads();
    float pm = 0.f, pl = 0.f;
    for (int r = 0; r < NUM_R; r++) {
        float a = an[r];
        pm = fmaf(a, g_qz[r * 512 + c], pm);
        pl = fmaf(a, g_qz[r * 512 + 256 + c], pl);
    }
    float z = g_zM[m * DD + c];
    float qm = g_qz[(NUM_R + m) * 512 + c], ql = g_qz[(NUM_R + m) * 512 + 256 + c];
    float t1 = (z - pm) * expf(-pl);
    float t2 = (z - qm) * expf(-ql);
    float v = (-pl - 0.5f * t1 * t1) - (-ql - 0.5f * t2 * t2);
    __shared__ float red[256];
    red[c] = v;
    __syncthreads();
    for (int o = 128; o >= 1; o >>= 1) {
        if (c < o) red[c] += red[c + o];
        __syncthreads();
    }
    if (c == 0) atomicAdd(&g_acc[1], red[0]);
}

__global__ void k_repM() {
    int i = blockIdx.x * blockDim.x + threadIdx.x;
    if (i >= NUM_M * 512) return;
    int m = i >> 9, c = i & 511;
    float v = (c < 256) ? g_zM[m * DD + c] : g_u[(size_t)(NUM_R + m) * DD + (c - 256)];
    __nv_bfloat16 hi = __float2bfloat16(v);
    g_repMh[i] = hi;
    g_repMl[i] = __float2bfloat16(v - __bfloat162float(hi));
}
__global__ void k_repR() {
    int i = blockIdx.x * blockDim.x + threadIdx.x;
    if (i >= NUM_R * 512) return;
    int r = i >> 9, c = i & 511;
    float v = (c < 256) ? g_zR[r * DD + c] : g_u[(size_t)r * DD + (c - 256)];
    __nv_bfloat16 hi = __float2bfloat16(v);
    g_repRh[i] = hi;
    g_repRl[i] = __float2bfloat16(v - __bfloat162float(hi));
}

__global__ void k_head(const float* __restrict__ hid, const float* __restrict__ W2,
                       const float* __restrict__ b2, const int* __restrict__ y,
                       int rows, int accIdx) {
    int gw = (blockIdx.x * blockDim.x + threadIdx.x) >> 5;
    int lane = threadIdx.x & 31;
    if (gw >= rows) return;
    float p0 = 0.f, p1 = 0.f;
#pragma unroll
    for (int j = 0; j < 8; j++) {
        int k = lane + 32 * j;
        float h = hid[(size_t)gw * 256 + k];
        p0 = fmaf(h, W2[k * 2], p0);
        p1 = fmaf(h, W2[k * 2 + 1], p1);
    }
    for (int o = 16; o >= 1; o >>= 1) {
        p0 += __shfl_down_sync(0xffffffffu, p0, o);
        p1 += __shfl_down_sync(0xffffffffu, p1, o);
    }
    if (lane == 0) {
        float l0 = p0 + b2[0], l1 = p1 + b2[1];
        float mx = fmaxf(l0, l1);
        float lse = mx + logf(expf(l0 - mx) + expf(l1 - mx));
        atomicAdd(&g_acc[accIdx], ((y[gw] != 0) ? l1 : l0) - lse);
    }
}

__global__ void k_final(float* __restrict__ out) {
    float pred = -(g_acc[0] + 0.1f * g_acc[1]) / 1024.0f;
    float rat  = -g_acc[2] / 64.0f;
    float reg  = g_acc[3] / 32768.0f;
    out[0] = pred + rat - 0.1f * reg;
}

extern "C" void kernel_launch(void* const* d_in, const int* in_sizes, int n_in,
                              void* d_out, int out_size) {
    (void)in_sizes; (void)n_in; (void)out_size;
    const float* x     = (const float*)d_in[0];
    const int*   ei    = (const int*)  d_in[1];
    const int*   et    = (const int*)  d_in[2];
    const int*   batch = (const int*)  d_in[3];
    const int*   yM    = (const int*)  d_in[4];
    const int*   yR    = (const int*)  d_in[5];
    const float* HR    = (const float*)d_in[6];
    const float* nodeW = (const float*)d_in[7];
    const float* nodeB = (const float*)d_in[8];
    const float* Wr    = (const float*)d_in[9];
    const float* Wroot = (const float*)d_in[10];
    const float* gcnB  = (const float*)d_in[11];
    const float* pg    = (const float*)d_in[12];
    const float* puW   = (const float*)d_in[13];
    const float* puB   = (const float*)d_in[14];
    const float* qzW   = (const float*)d_in[15];
    const float* qzB   = (const float*)d_in[16];
    const float* W1    = (const float*)d_in[17];
    const float* b1    = (const float*)d_in[18];
    const float* W2    = (const float*)d_in[19];
    const float* b2    = (const float*)d_in[20];
    float* out = (float*)d_out;

    uint32_t ku0, ku1, ka0, ka1, kzm0, kzm1, kzr0, kzr1;
    tf2x32(0u, 42u, 0u, 0u, ku0, ku1);
    tf2x32(0u, 42u, 0u, 1u, ka0, ka1);
    tf2x32(0u, 42u, 0u, 2u, kzm0, kzm1);
    tf2x32(0u, 42u, 0u, 3u, kzr0, kzr1);

    void* p;
    cudaGetSymbolAddress(&p, g_featsB); float* featsB = (float*)p;
    cudaGetSymbolAddress(&p, g_G);      float* G      = (float*)p;
    cudaGetSymbolAddress(&p, g_Wfh);    __half* Wfh = (__half*)p;
    cudaGetSymbolAddress(&p, g_Wfl);    __half* Wfl = (__half*)p;
    cudaGetSymbolAddress(&p, g_nWfh);   __half* nWfh = (__half*)p;
    cudaGetSymbolAddress(&p, g_nWfl);   __half* nWfl = (__half*)p;
    cudaGetSymbolAddress(&p, g_xf);     __half* xf = (__half*)p;
    cudaGetSymbolAddress(&p, g_Af);     __half* Af = (__half*)p;
    cudaGetSymbolAddress(&p, g_puWh);   __nv_bfloat16* puWh = (__nv_bfloat16*)p;
    cudaGetSymbolAddress(&p, g_puWl);   __nv_bfloat16* puWl = (__nv_bfloat16*)p;
    cudaGetSymbolAddress(&p, g_qzWh);   __nv_bfloat16* qzWh = (__nv_bfloat16*)p;
    cudaGetSymbolAddress(&p, g_qzWl);   __nv_bfloat16* qzWl = (__nv_bfloat16*)p;
    cudaGetSymbolAddress(&p, g_w1h);    __nv_bfloat16* w1h = (__nv_bfloat16*)p;
    cudaGetSymbolAddress(&p, g_w1l);    __nv_bfloat16* w1l = (__nv_bfloat16*)p;
    cudaGetSymbolAddress(&p, g_Hh);     __nv_bfloat16* Hh  = (__nv_bfloat16*)p;
    cudaGetSymbolAddress(&p, g_Hl);     __nv_bfloat16* Hl  = (__nv_bfloat16*)p;
    cudaGetSymbolAddress(&p, g_repMh);  __nv_bfloat16* repMh = (__nv_bfloat16*)p;
    cudaGetSymbolAddress(&p, g_repMl);  __nv_bfloat16* repMl = (__nv_bfloat16*)p;
    cudaGetSymbolAddress(&p, g_repRh);  __nv_bfloat16* repRh = (__nv_bfloat16*)p;
    cudaGetSymbolAddress(&p, g_repRl);  __nv_bfloat16* repRl = (__nv_bfloat16*)p;
    cudaGetSymbolAddress(&p, g_pu);     float* pu     = (float*)p;
    cudaGetSymbolAddress(&p, g_qz);     float* qz     = (float*)p;
    cudaGetSymbolAddress(&p, g_hidM);   float* hidM   = (float*)p;
    cudaGetSymbolAddress(&p, g_hidR);   float* hidR   = (float*)p;

    static int smem_set = 0;
    if (!smem_set) {
        cudaFuncSetAttribute(k_fmma, cudaFuncAttributeMaxDynamicSharedMemorySize, 92160);
        cudaFuncSetAttribute(k_bmma, cudaFuncAttributeMaxDynamicSharedMemorySize, 122880);
        smem_set = 1;
    }

    k_zero_init<<<(N_RELS * N_NODES + 255) / 256, 256>>>();
    k_count<<<(N_EDGES + 255) / 256, 256>>>(ei, et);
    k_scan<<<1, 1024>>>();
    k_scatter<<<(N_EDGES + 255) / 256, 256>>>(ei, et);
    k_wsplitF<<<(N_LAYERS * GW * 256 + 255) / 256, 256>>>(Wroot, Wr);
    k_wsplitTF<<<(256 * D_IN + 255) / 256, 256>>>(nodeW, nWfh, nWfl, 256, D_IN);
    k_wsplitT<<<(512 * 256 + 255) / 256, 256>>>(puW, puWh, puWl, 512, 256);
    k_wsplitT<<<(512 * 256 + 255) / 256, 256>>>(qzW, qzWh, qzWl, 512, 256);
    k_wsplitT<<<(256 * 512 + 255) / 256, 256>>>(W1, w1h, w1l, 256, 512);
    k_tohalf<<<(N_NODES * D_IN + 255) / 256, 256>>>(x, xf, N_NODES * D_IN);

    // node encoder: fp16 2-term, bias fused, fp16 output
    k_fmma<<<dim3(2, (N_NODES + 127) / 128), 256, 92160>>>(
        xf, nWfh, nWfl, nodeB, nullptr, Af, N_NODES, 256, D_IN, 0);

    for (int l = 0; l < N_LAYERS; l++) {
        k_fmma<<<dim3(GW / 128, (N_NODES + 127) / 128), 256, 92160>>>(
            Af, Wfh + (size_t)l * GW * 256, Wfl + (size_t)l * GW * 256,
            nullptr, G, nullptr, N_NODES, GW, 256, 0);
        k_agg<<<(N_NODES * 32 + 255) / 256, 256>>>(
            gcnB + l * 256, Af, featsB, (l < N_LAYERS - 1) ? 1 : 0);
    }

    k_starts<<<(NUM_M + 256) / 256, 256>>>(batch);
    k_copyHR<<<(NUM_R * DD + 255) / 256, 256>>>(HR);
    k_gmean<<<NUM_M, 256>>>(featsB);

    k_bmma<<<dim3(4, HPAD / 128), 256, 122880>>>(
        Hh, Hl, puWh, puWl, puB, pu, N_ALL, 512, 256, 0);
    k_bmma<<<dim3(4, HPAD / 128), 256, 122880>>>(
        Hh, Hl, qzWh, qzWl, qzB, qz, N_ALL, 512, 256, 0);

    k_sample_u <<<(N_ALL * DD + 255) / 256, 256>>>(ku0, ku1);
    k_sample_zM<<<(NUM_M * DD + 255) / 256, 256>>>(kzm0, kzm1);
    k_sample_zR<<<(NUM_R * DD + 255) / 256, 256>>>(kzr0, kzr1);

    k_attn<<<NUM_M, 64>>>(pg, yM, ka0, ka1);
    k_pzq<<<NUM_M, 256>>>();

    k_repM<<<(NUM_M * 512 + 255) / 256, 256>>>();
    k_repR<<<(NUM_R * 512 + 255) / 256, 256>>>();
    k_bmma<<<dim3(2, NUM_M / 128), 256, 122880>>>(
        repMh, repMl, w1h, w1l, b1, hidM, NUM_M, 256, 512, 1);
    k_bmma<<<dim3(2, 1), 256, 122880>>>(
        repRh, repRl, w1h, w1l, b1, hidR, NUM_R, 256, 512, 1);
    k_head<<<(NUM_M * 32 + 255) / 256, 256>>>(hidM, W2, b2, yM, NUM_M, 0);
    k_head<<<(NUM_R * 32 + 255) / 256, 256>>>(hidR, W2, b2, yR, NUM_R, 2);

    k_final<<<1, 1>>>(out);
}

// round 10
// speedup vs baseline: 1.5948x; 1.0412x over previous
#include <cuda_runtime.h>
#include <cuda_bf16.h>
#include <cuda_fp16.h>
#include <stdint.h>
#include <math.h>

#define N_NODES 50000
#define N_EDGES 200000
#define D_IN    128
#define DD      256
#define N_LAYERS 4
#define N_RELS  4
#define NUM_M   1024
#define NUM_R   64
#define N_ALL   (NUM_R + NUM_M)
#define GW      1280
#define MPAD    (N_NODES + 128)
#define HPAD    1152

__device__ float g_featsB[N_NODES * DD];
__device__ __half g_G[(size_t)N_NODES * GW];
__device__ __half g_Wfh[N_LAYERS * GW * 256];
__device__ __half g_Wfl[N_LAYERS * GW * 256];
__device__ __half g_nWfh[256 * D_IN];
__device__ __half g_nWfl[256 * D_IN];
__device__ __half g_xf[(size_t)MPAD * D_IN];
__device__ __half g_Af[(size_t)MPAD * DD];
__device__ __nv_bfloat16 g_puWh[512 * 256];
__device__ __nv_bfloat16 g_puWl[512 * 256];
__device__ __nv_bfloat16 g_qzWh[512 * 256];
__device__ __nv_bfloat16 g_qzWl[512 * 256];
__device__ __nv_bfloat16 g_w1h[256 * 512];
__device__ __nv_bfloat16 g_w1l[256 * 512];
__device__ __nv_bfloat16 g_Hh[HPAD * DD];
__device__ __nv_bfloat16 g_Hl[HPAD * DD];
__device__ __nv_bfloat16 g_repMh[NUM_M * 512];
__device__ __nv_bfloat16 g_repMl[NUM_M * 512];
__device__ __nv_bfloat16 g_repRh[128 * 512];
__device__ __nv_bfloat16 g_repRl[128 * 512];
__device__ int   g_cnt[N_RELS * N_NODES];
__device__ int   g_deg[N_NODES];
__device__ int   g_off[N_NODES + 1];
__device__ int   g_cursor[N_NODES];
__device__ uint2 g_epack[N_EDGES];
__device__ int   g_start[NUM_M + 1];
__device__ float g_pu[N_ALL * 512];
__device__ float g_qz[N_ALL * 512];
__device__ float g_u[N_ALL * DD];
__device__ float g_zM[NUM_M * DD];
__device__ float g_zR[NUM_R * DD];
__device__ float g_An[NUM_M * NUM_R];
__device__ float g_hidM[NUM_M * 256];
__device__ float g_hidR[NUM_R * 256];
__device__ float g_acc[4];

__host__ __device__ __forceinline__ uint32_t rotl32(uint32_t x, int d) {
    return (x << d) | (x >> (32 - d));
}
__host__ __device__ __forceinline__ void tf2x32(uint32_t k0, uint32_t k1,
                                                uint32_t x0, uint32_t x1,
                                                uint32_t& o0, uint32_t& o1) {
    uint32_t ks2 = k0 ^ k1 ^ 0x1BD11BDAu;
    x0 += k0; x1 += k1;
#define TF_RND(R) { x0 += x1; x1 = rotl32(x1, R); x1 ^= x0; }
    TF_RND(13) TF_RND(15) TF_RND(26) TF_RND(6)
    x0 += k1;  x1 += ks2 + 1u;
    TF_RND(17) TF_RND(29) TF_RND(16) TF_RND(24)
    x0 += ks2; x1 += k0 + 2u;
    TF_RND(13) TF_RND(15) TF_RND(26) TF_RND(6)
    x0 += k0;  x1 += k1 + 3u;
    TF_RND(17) TF_RND(29) TF_RND(16) TF_RND(24)
    x0 += k1;  x1 += ks2 + 4u;
    TF_RND(13) TF_RND(15) TF_RND(26) TF_RND(6)
    x0 += ks2; x1 += k0 + 5u;
#undef TF_RND
    o0 = x0; o1 = x1;
}
__device__ __forceinline__ uint32_t rbits(uint32_t k0, uint32_t k1, uint32_t i) {
    uint32_t o0, o1; tf2x32(k0, k1, 0u, i, o0, o1); return o0 ^ o1;
}
__device__ __forceinline__ float erfinv_xla(float x) {
    float w = -log1pf(-x * x), p;
    if (w < 5.0f) {
        w -= 2.5f;
        p = 2.81022636e-08f;
        p = fmaf(p, w, 3.43273939e-07f);  p = fmaf(p, w, -3.5233877e-06f);
        p = fmaf(p, w, -4.39150654e-06f); p = fmaf(p, w, 0.00021858087f);
        p = fmaf(p, w, -0.00125372503f);  p = fmaf(p, w, -0.00417768164f);
        p = fmaf(p, w, 0.246640727f);     p = fmaf(p, w, 1.50140941f);
    } else {
        w = sqrtf(w) - 3.0f;
        p = -0.000200214257f;
        p = fmaf(p, w, 0.000100950558f);  p = fmaf(p, w, 0.00134934322f);
        p = fmaf(p, w, -0.00367342844f);  p = fmaf(p, w, 0.00573950773f);
        p = fmaf(p, w, -0.0076224613f);   p = fmaf(p, w, 0.00943887047f);
        p = fmaf(p, w, 1.00167406f);      p = fmaf(p, w, 2.83297682f);
    }
    return p * x;
}
__device__ __forceinline__ float u01(uint32_t b) {
    return __uint_as_float((b >> 9) | 0x3f800000u) - 1.0f;
}
__device__ __forceinline__ float nrm(uint32_t b) {
    const float LO = -0.99999994f;
    float v = u01(b) * 2.0f + LO;
    v = fmaxf(LO, v);
    return 1.41421356f * erfinv_xla(v);
}
__device__ __forceinline__ float unif(uint32_t b) {
    const float MN = 1e-06f;
    float v = u01(b) * (0.999999f - MN) + MN;
    return fmaxf(MN, v);
}

__global__ void k_zero_init() {
    int i = blockIdx.x * blockDim.x + threadIdx.x;
    if (i < N_RELS * N_NODES) g_cnt[i] = 0;
    if (i < N_NODES) g_deg[i] = 0;
    if (i < 4) g_acc[i] = 0.0f;
}
__global__ void k_count(const int* __restrict__ ei, const int* __restrict__ et) {
    int e = blockIdx.x * blockDim.x + threadIdx.x;
    if (e >= N_EDGES) return;
    int d = ei[N_EDGES + e];
    atomicAdd(&g_cnt[et[e] * N_NODES + d], 1);
    atomicAdd(&g_deg[d], 1);
}
__global__ void k_scan() {
    __shared__ int part[1024];
    int tid = threadIdx.x;
    const int chunk = (N_NODES + 1023) / 1024;
    int lo = tid * chunk, hi = min(lo + chunk, N_NODES);
    int s = 0;
    for (int i = lo; i < hi; i++) s += g_deg[i];
    part[tid] = s;
    __syncthreads();
    for (int o = 1; o < 1024; o <<= 1) {
        int v = (tid >= o) ? part[tid - o] : 0;
        __syncthreads(); part[tid] += v; __syncthreads();
    }
    int run = part[tid] - s;
    for (int i = lo; i < hi; i++) { g_off[i] = run; g_cursor[i] = run; run += g_deg[i]; }
    if (tid == 1023) g_off[N_NODES] = run;
}
__global__ void k_scatter(const int* __restrict__ ei, const int* __restrict__ et) {
    int e = blockIdx.x * blockDim.x + threadIdx.x;
    if (e >= N_EDGES) return;
    int sn = ei[e], d = ei[N_EDGES + e], r = et[e];
    int p = atomicAdd(&g_cursor[d], 1);
    float inv = 1.0f / (float)g_cnt[r * N_NODES + d];
    g_epack[p] = make_uint2((uint32_t)(sn * GW + 256 + (r << 8)), __float_as_uint(inv));
}
__global__ void k_wsplitF(const float* __restrict__ Wroot, const float* __restrict__ Wr) {
    int idx = blockIdx.x * blockDim.x + threadIdx.x;
    if (idx >= N_LAYERS * GW * 256) return;
    int l = idx / (GW * 256), rem = idx % (GW * 256);
    int n = rem / 256, k = rem % 256;
    float v;
    if (n < 256) v = Wroot[((size_t)l * 256 + k) * 256 + n];
    else {
        int r = (n >> 8) - 1, h = n & 255;
        v = Wr[(((size_t)l * 4 + r) * 256 + k) * 256 + h];
    }
    __half hi = __float2half_rn(v);
    g_Wfh[idx] = hi;
    g_Wfl[idx] = __float2half_rn(v - __half2float(hi));
}
__global__ void k_wsplitTF(const float* __restrict__ src, __half* __restrict__ h,
                           __half* __restrict__ l, int N, int K) {
    int idx = blockIdx.x * blockDim.x + threadIdx.x;
    if (idx >= N * K) return;
    int n = idx / K, k = idx % K;
    float v = src[(size_t)k * N + n];
    __half hi = __float2half_rn(v);
    h[idx] = hi;
    l[idx] = __float2half_rn(v - __half2float(hi));
}
__global__ void k_wsplitT(const float* __restrict__ src, __nv_bfloat16* __restrict__ h,
                          __nv_bfloat16* __restrict__ l, int N, int K) {
    int idx = blockIdx.x * blockDim.x + threadIdx.x;
    if (idx >= N * K) return;
    int n = idx / K, k = idx % K;
    float v = src[(size_t)k * N + n];
    __nv_bfloat16 hi = __float2bfloat16(v);
    h[idx] = hi;
    l[idx] = __float2bfloat16(v - __bfloat162float(hi));
}
__global__ void k_tohalf(const float* __restrict__ src, __half* __restrict__ dst, int n) {
    int i = blockIdx.x * blockDim.x + threadIdx.x;
    if (i < n) dst[i] = __float2half_rn(src[i]);
}

__device__ __forceinline__ void ldm4(uint32_t a, uint32_t& r0, uint32_t& r1,
                                     uint32_t& r2, uint32_t& r3) {
    asm volatile("ldmatrix.sync.aligned.m8n8.x4.shared.b16 {%0,%1,%2,%3}, [%4];"
                 : "=r"(r0), "=r"(r1), "=r"(r2), "=r"(r3) : "r"(a));
}
__device__ __forceinline__ void mma_bf(float* c, const uint32_t* a, const uint32_t* b) {
    asm volatile("mma.sync.aligned.m16n8k16.row.col.f32.bf16.bf16.f32 "
                 "{%0,%1,%2,%3},{%4,%5,%6,%7},{%8,%9},{%0,%1,%2,%3};"
                 : "+f"(c[0]), "+f"(c[1]), "+f"(c[2]), "+f"(c[3])
                 : "r"(a[0]), "r"(a[1]), "r"(a[2]), "r"(a[3]), "r"(b[0]), "r"(b[1]));
}
__device__ __forceinline__ void mma_fp(float* c, const uint32_t* a, const uint32_t* b) {
    asm volatile("mma.sync.aligned.m16n8k16.row.col.f32.f16.f16.f32 "
                 "{%0,%1,%2,%3},{%4,%5,%6,%7},{%8,%9},{%0,%1,%2,%3};"
                 : "+f"(c[0]), "+f"(c[1]), "+f"(c[2]), "+f"(c[3])
                 : "r"(a[0]), "r"(a[1]), "r"(a[2]), "r"(a[3]), "r"(b[0]), "r"(b[1]));
}
__device__ __forceinline__ void cp16(uint32_t dst, const void* src) {
    asm volatile("cp.async.cg.shared.global [%0], [%1], 16;" :: "r"(dst), "l"(src));
}

// ===== fp16 2-term GEMM: A single fp16, B hi/lo fp16. BM=BN=128, BK=32, 3 stages =====
#define LOAD_STAGE_F(s, kq)                                            \
    do {                                                               \
        uint32_t st_ = smq + (s) * 30720;                              \
        _Pragma("unroll")                                              \
        for (int q_ = 0; q_ < 2; q_++) {                               \
            int col_ = (c0 + q_) * 8;                                  \
            uint32_t dd_ = st_ + (row * 40 + col_) * 2;                \
            cp16(dd_,         Agf + (kq) + col_);                      \
            cp16(dd_ + 10240, Bgh + (kq) + col_);                      \
            cp16(dd_ + 20480, Bgl + (kq) + col_);                      \
        }                                                              \
    } while (0)

__global__ void __launch_bounds__(256, 1)
k_fmma(const __half* __restrict__ Af, const __half* __restrict__ Bh,
       const __half* __restrict__ Bl, const float* __restrict__ bias,
       float* __restrict__ C, __half* __restrict__ oF,
       int M, int N, int K, int relu_out) {
    extern __shared__ __align__(16) __half dsmf[];
    uint32_t smq = (uint32_t)__cvta_generic_to_shared(dsmf);
    int tid = threadIdx.x, lane = tid & 31, wid = tid >> 5;
    int wm = (wid >> 2) * 64, wn = (wid & 3) * 32;
    int bm = blockIdx.y * 128, bn = blockIdx.x * 128;
    int row = tid >> 1, c0 = (tid & 1) * 2;
    const __half* Agf = Af + (size_t)(bm + row) * K;
    const __half* Bgh = Bh + (size_t)(bn + row) * K;
    const __half* Bgl = Bl + (size_t)(bn + row) * K;

    float acc[4][4][4];
#pragma unroll
    for (int i = 0; i < 4; i++)
#pragma unroll
        for (int j = 0; j < 4; j++)
#pragma unroll
            for (int q = 0; q < 4; q++) acc[i][j][q] = 0.f;

    LOAD_STAGE_F(0, 0);
    asm volatile("cp.async.commit_group;");
    if (32 < K) LOAD_STAGE_F(1, 32);
    asm volatile("cp.async.commit_group;");

    int cur = 0;
    for (int k0 = 0; k0 < K; k0 += 32) {
        int pre = k0 + 64;
        if (pre < K) {
            int s2 = cur + 2; if (s2 >= 3) s2 -= 3;
            LOAD_STAGE_F(s2, pre);
        }
        asm volatile("cp.async.commit_group;");
        asm volatile("cp.async.wait_group 2;");
        __syncthreads();
        uint32_t st = smq + cur * 30720;
#pragma unroll
        for (int kk = 0; kk < 32; kk += 16) {
            uint32_t bh[4][2], bl[4][2];
            int brow = wn + (lane & 7) + ((lane >> 4) & 1) * 8;
            int bcol = kk + ((lane >> 3) & 1) * 8;
#pragma unroll
            for (int nb = 0; nb < 2; nb++) {
                uint32_t off = ((brow + nb * 16) * 40 + bcol) * 2;
                ldm4(st + 10240 + off, bh[2 * nb][0], bh[2 * nb][1], bh[2 * nb + 1][0], bh[2 * nb + 1][1]);
                ldm4(st + 20480 + off, bl[2 * nb][0], bl[2 * nb][1], bl[2 * nb + 1][0], bl[2 * nb + 1][1]);
            }
            int arow = wm + (lane & 7) + ((lane >> 3) & 1) * 8;
            int acol = kk + ((lane >> 4) & 1) * 8;
#pragma unroll
            for (int mf = 0; mf < 4; mf++) {
                uint32_t a[4];
                uint32_t off = ((arow + mf * 16) * 40 + acol) * 2;
                ldm4(st + off, a[0], a[1], a[2], a[3]);
#pragma unroll
                for (int nf = 0; nf < 4; nf++) {
                    mma_fp(acc[mf][nf], a, bh[nf]);
                    mma_fp(acc[mf][nf], a, bl[nf]);
                }
            }
        }
        __syncthreads();
        cur++; if (cur >= 3) cur = 0;
    }
#pragma unroll
    for (int mf = 0; mf < 4; mf++)
#pragma unroll
        for (int nf = 0; nf < 4; nf++) {
            int r0 = bm + wm + mf * 16 + (lane >> 2);
            int c0o = bn + wn + nf * 8 + (lane & 3) * 2;
#pragma unroll
            for (int h = 0; h < 2; h++) {
                int r = r0 + h * 8;
                if (r >= M) continue;
                float v0 = acc[mf][nf][2 * h], v1 = acc[mf][nf][2 * h + 1];
                if (bias) { v0 += bias[c0o]; v1 += bias[c0o + 1]; }
                if (relu_out) { v0 = fmaxf(v0, 0.f); v1 = fmaxf(v1, 0.f); }
                if (oF) {
                    *(__half2*)(oF + (size_t)r * N + c0o) = __floats2half2_rn(v0, v1);
                } else {
                    *(float2*)(C + (size_t)r * N + c0o) = make_float2(v0, v1);
                }
            }
        }
}

// ===== bf16 3-term GEMM for tail =====
#define LOAD_STAGE(s, kq)                                              \
    do {                                                               \
        uint32_t st_ = sm + (s) * 40960;                               \
        _Pragma("unroll")                                              \
        for (int q_ = 0; q_ < 2; q_++) {                               \
            int col_ = (c0 + q_) * 8;                                  \
            uint32_t dd_ = st_ + (row * 40 + col_) * 2;                \
            cp16(dd_,         Agh + (kq) + col_);                      \
            cp16(dd_ + 10240, Agl + (kq) + col_);                      \
            cp16(dd_ + 20480, Bgh + (kq) + col_);                      \
            cp16(dd_ + 30720, Bgl + (kq) + col_);                      \
        }                                                              \
    } while (0)

__global__ void __launch_bounds__(256, 1)
k_bmma(const __nv_bfloat16* __restrict__ Ah, const __nv_bfloat16* __restrict__ Al,
       const __nv_bfloat16* __restrict__ Bh, const __nv_bfloat16* __restrict__ Bl,
       const float* __restrict__ bias, float* __restrict__ C,
       int M, int N, int K, int relu_out) {
    extern __shared__ __align__(16) __nv_bfloat16 dsm[];
    uint32_t sm = (uint32_t)__cvta_generic_to_shared(dsm);
    int tid = threadIdx.x, lane = tid & 31, wid = tid >> 5;
    int wm = (wid >> 2) * 64, wn = (wid & 3) * 32;
    int bm = blockIdx.y * 128, bn = blockIdx.x * 128;
    int row = tid >> 1, c0 = (tid & 1) * 2;
    const __nv_bfloat16* Agh = Ah + (size_t)(bm + row) * K;
    const __nv_bfloat16* Agl = Al + (size_t)(bm + row) * K;
    const __nv_bfloat16* Bgh = Bh + (size_t)(bn + row) * K;
    const __nv_bfloat16* Bgl = Bl + (size_t)(bn + row) * K;

    float acc[4][4][4];
#pragma unroll
    for (int i = 0; i < 4; i++)
#pragma unroll
        for (int j = 0; j < 4; j++)
#pragma unroll
            for (int q = 0; q < 4; q++) acc[i][j][q] = 0.f;

    LOAD_STAGE(0, 0);
    asm volatile("cp.async.commit_group;");
    if (32 < K) LOAD_STAGE(1, 32);
    asm volatile("cp.async.commit_group;");

    int cur = 0;
    for (int k0 = 0; k0 < K; k0 += 32) {
        int pre = k0 + 64;
        if (pre < K) {
            int s2 = cur + 2; if (s2 >= 3) s2 -= 3;
            LOAD_STAGE(s2, pre);
        }
        asm volatile("cp.async.commit_group;");
        asm volatile("cp.async.wait_group 2;");
        __syncthreads();
        uint32_t st = sm + cur * 40960;
#pragma unroll
        for (int kk = 0; kk < 32; kk += 16) {
            uint32_t bh[4][2], bl[4][2];
            int brow = wn + (lane & 7) + ((lane >> 4) & 1) * 8;
            int bcol = kk + ((lane >> 3) & 1) * 8;
#pragma unroll
            for (int nb = 0; nb < 2; nb++) {
                uint32_t off = ((brow + nb * 16) * 40 + bcol) * 2;
                ldm4(st + 20480 + off, bh[2 * nb][0], bh[2 * nb][1], bh[2 * nb + 1][0], bh[2 * nb + 1][1]);
                ldm4(st + 30720 + off, bl[2 * nb][0], bl[2 * nb][1], bl[2 * nb + 1][0], bl[2 * nb + 1][1]);
            }
            int arow = wm + (lane & 7) + ((lane >> 3) & 1) * 8;
            int acol = kk + ((lane >> 4) & 1) * 8;
#pragma unroll
            for (int mf = 0; mf < 4; mf++) {
                uint32_t ah[4], al[4];
                uint32_t off = ((arow + mf * 16) * 40 + acol) * 2;
                ldm4(st + off, ah[0], ah[1], ah[2], ah[3]);
                ldm4(st + 10240 + off, al[0], al[1], al[2], al[3]);
#pragma unroll
                for (int nf = 0; nf < 4; nf++) {
                    mma_bf(acc[mf][nf], ah, bh[nf]);
                    mma_bf(acc[mf][nf], ah, bl[nf]);
                    mma_bf(acc[mf][nf], al, bh[nf]);
                }
            }
        }
        __syncthreads();
        cur++; if (cur >= 3) cur = 0;
    }
#pragma unroll
    for (int mf = 0; mf < 4; mf++)
#pragma unroll
        for (int nf = 0; nf < 4; nf++) {
            int r0 = bm + wm + mf * 16 + (lane >> 2);
            int c0o = bn + wn + nf * 8 + (lane & 3) * 2;
#pragma unroll
            for (int h = 0; h < 2; h++) {
                int r = r0 + h * 8;
                if (r >= M) continue;
                float v0 = acc[mf][nf][2 * h], v1 = acc[mf][nf][2 * h + 1];
                if (bias) { v0 += bias[c0o]; v1 += bias[c0o + 1]; }
                if (relu_out) { v0 = fmaxf(v0, 0.f); v1 = fmaxf(v1, 0.f); }
                *(float2*)(C + (size_t)r * N + c0o) = make_float2(v0, v1);
            }
        }
}

__device__ __forceinline__ void up8(uint4 v, float* f) {
    __half2* h = (__half2*)&v;
    float2 a0 = __half22float2(h[0]); f[0] = a0.x; f[1] = a0.y;
    float2 a1 = __half22float2(h[1]); f[2] = a1.x; f[3] = a1.y;
    float2 a2 = __half22float2(h[2]); f[4] = a2.x; f[5] = a2.y;
    float2 a3 = __half22float2(h[3]); f[6] = a3.x; f[7] = a3.y;
}

// aggregation over fp16 G; hidden layers emit fp16, last emits fp32
__global__ void k_agg(const float* __restrict__ bias, __half* __restrict__ ofh,
                      float* __restrict__ out32, int relu) {
    int d = (blockIdx.x * blockDim.x + threadIdx.x) >> 5;
    int lane = threadIdx.x & 31;
    if (d >= N_NODES) return;
    float acc[8];
    {
        uint4 base = *(const uint4*)(g_G + (size_t)d * GW + lane * 8);
        up8(base, acc);
        const float4* b4 = (const float4*)bias;
        float4 bb0 = b4[lane * 2], bb1 = b4[lane * 2 + 1];
        acc[0] += bb0.x; acc[1] += bb0.y; acc[2] += bb0.z; acc[3] += bb0.w;
        acc[4] += bb1.x; acc[5] += bb1.y; acc[6] += bb1.z; acc[7] += bb1.w;
    }
    int s = g_off[d], e = g_off[d + 1];
    int i = s;
#define AGG_EDGE(P)                                                     \
    {                                                                   \
        uint4 gv = *(const uint4*)(g_G + (P).x + lane * 8);             \
        float inv = __uint_as_float((P).y);                             \
        float f[8]; up8(gv, f);                                         \
        acc[0] = fmaf(f[0], inv, acc[0]); acc[1] = fmaf(f[1], inv, acc[1]); \
        acc[2] = fmaf(f[2], inv, acc[2]); acc[3] = fmaf(f[3], inv, acc[3]); \
        acc[4] = fmaf(f[4], inv, acc[4]); acc[5] = fmaf(f[5], inv, acc[5]); \
        acc[6] = fmaf(f[6], inv, acc[6]); acc[7] = fmaf(f[7], inv, acc[7]); \
    }
    for (; i + 4 <= e; i += 4) {
        uint2 p0 = g_epack[i],     p1 = g_epack[i + 1];
        uint2 p2 = g_epack[i + 2], p3 = g_epack[i + 3];
        AGG_EDGE(p0) AGG_EDGE(p1) AGG_EDGE(p2) AGG_EDGE(p3)
    }
    for (; i < e; i++) {
        uint2 p0 = g_epack[i];
        AGG_EDGE(p0)
    }
#undef AGG_EDGE
    if (relu) {
#pragma unroll
        for (int j = 0; j < 8; j++) acc[j] = fmaxf(acc[j], 0.f);
        uint4 ov;
        __half2* oh = (__half2*)&ov;
        oh[0] = __floats2half2_rn(acc[0], acc[1]);
        oh[1] = __floats2half2_rn(acc[2], acc[3]);
        oh[2] = __floats2half2_rn(acc[4], acc[5]);
        oh[3] = __floats2half2_rn(acc[6], acc[7]);
        *(uint4*)(ofh + (size_t)d * DD + lane * 8) = ov;
    } else {
        float4* o = (float4*)(out32 + (size_t)d * DD);
        o[lane * 2]     = make_float4(acc[0], acc[1], acc[2], acc[3]);
        o[lane * 2 + 1] = make_float4(acc[4], acc[5], acc[6], acc[7]);
    }
}

__global__ void k_starts(const int* __restrict__ batch) {
    int m = blockIdx.x * blockDim.x + threadIdx.x;
    if (m > NUM_M) return;
    int lo = 0, hi = N_NODES;
    while (lo < hi) { int mid = (lo + hi) >> 1; if (batch[mid] < m) lo = mid + 1; else hi = mid; }
    g_start[m] = lo;
}
__global__ void k_copyHR(const float* __restrict__ HR) {
    int i = blockIdx.x * blockDim.x + threadIdx.x;
    if (i >= NUM_R * DD) return;
    float v = fmaxf(HR[i], 0.f);
    __nv_bfloat16 hi = __float2bfloat16(v);
    g_Hh[i] = hi;
    g_Hl[i] = __float2bfloat16(v - __bfloat162float(hi));
}
__global__ void k_gmean(const float* __restrict__ feats) {
    int m = blockIdx.x, c = threadIdx.x;
    int s = g_start[m], e = g_start[m + 1];
    float acc = 0.f;
    for (int n = s; n < e; n++) acc += feats[(size_t)n * DD + c];
    float v = fmaxf(acc / fmaxf((float)(e - s), 1.0f), 0.f);
    __nv_bfloat16 hi = __float2bfloat16(v);
    size_t idx = (size_t)(NUM_R + m) * DD + c;
    g_Hh[idx] = hi;
    g_Hl[idx] = __float2bfloat16(v - __bfloat162float(hi));
}

__global__ void k_sample_u(unsigned k0, unsigned k1) {
    int i = blockIdx.x * blockDim.x + threadIdx.x;
    if (i >= N_ALL * DD) return;
    int row = i >> 8, col = i & 255;
    g_u[i] = g_pu[row * 512 + col] + expf(g_pu[row * 512 + 256 + col]) * nrm(rbits(k0, k1, i));
}
__global__ void k_sample_zM(unsigned k0, unsigned k1) {
    int i = blockIdx.x * blockDim.x + threadIdx.x;
    if (i >= NUM_M * DD) return;
    int m = i >> 8, col = i & 255;
    int r = (NUM_R + m) * 512;
    g_zM[i] = g_qz[r + col] + expf(g_qz[r + 256 + col]) * nrm(rbits(k0, k1, i));
}
__global__ void k_sample_zR(unsigned k0, unsigned k1) {
    int i = blockIdx.x * blockDim.x + threadIdx.x;
    if (i >= NUM_R * DD) return;
    int r = i >> 8, col = i & 255;
    g_zR[i] = g_qz[r * 512 + col] + expf(g_qz[r * 512 + 256 + col]) * nrm(rbits(k0, k1, i));
}

__global__ void k_attn(const float* __restrict__ pg, const int* __restrict__ yM,
                       unsigned k0, unsigned k1) {
    int m = blockIdx.x, r = threadIdx.x;
    __shared__ float um[DD];
    __shared__ float d2s[NUM_R];
    __shared__ float red[NUM_R];
    for (int i = r; i < DD; i += 64) um[i] = g_u[(size_t)(NUM_R + m) * DD + i];
    __syncthreads();
    float d2 = 0.f;
    const float* ur = g_u + (size_t)r * DD;
    for (int dd = 0; dd < DD; dd++) {
        float t = um[dd] - ur[dd];
        d2 = fmaf(t, t, d2);
    }
    d2s[r] = d2;
    float logp = -0.5f * d2 / expf(pg[0]);
    float logit = logp - logf(fmaxf(-expm1f(logp), 1e-20f));
    float U = unif(rbits(k0, k1, (uint32_t)(m * NUM_R + r)));
    float gn = logf(U) - log1pf(-U);
    float A = 1.0f / (1.0f + expf(-(logit + gn) / 0.3f));
    red[r] = A;
    __syncthreads();
    for (int o = 32; o >= 1; o >>= 1) {
        if (r < o) red[r] += red[r + o];
        __syncthreads();
    }
    g_An[m * NUM_R + r] = A / (red[0] + 1e-8f);
    if (r < 32) {
        int idx = r + (1 - yM[m]) * 32;
        float t = sqrtf(fmaxf(d2s[idx], 1e-12f));
        for (int o = 16; o >= 1; o >>= 1) t += __shfl_down_sync(0xffffffffu, t, o);
        if (r == 0) atomicAdd(&g_acc[3], t);
    }
}

__global__ void k_pzq() {
    int m = blockIdx.x, c = threadIdx.x;
    __shared__ float an[NUM_R];
    if (c < NUM_R) an[c] = g_An[m * NUM_R + c];
    __syncthreads();
    float pm = 0.f, pl = 0.f;
    for (int r = 0; r < NUM_R; r++) {
        float a = an[r];
        pm = fmaf(a, g_qz[r * 512 + c], pm);
        pl = fmaf(a, g_qz[r * 512 + 256 + c], pl);
    }
    float z = g_zM[m * DD + c];
    float qm = g_qz[(NUM_R + m) * 512 + c], ql = g_qz[(NUM_R + m) * 512 + 256 + c];
    float t1 = (z - pm) * expf(-pl);
    float t2 = (z - qm) * expf(-ql);
    float v = (-pl - 0.5f * t1 * t1) - (-ql - 0.5f * t2 * t2);
    __shared__ float red[256];
    red[c] = v;
    __syncthreads();
    for (int o = 128; o >= 1; o >>= 1) {
        if (c < o) red[c] += red[c + o];
        __syncthreads();
    }
    if (c == 0) atomicAdd(&g_acc[1], red[0]);
}

__global__ void k_repM() {
    int i = blockIdx.x * blockDim.x + threadIdx.x;
    if (i >= NUM_M * 512) return;
    int m = i >> 9, c = i & 511;
    float v = (c < 256) ? g_zM[m * DD + c] : g_u[(size_t)(NUM_R + m) * DD + (c - 256)];
    __nv_bfloat16 hi = __float2bfloat16(v);
    g_repMh[i] = hi;
    g_repMl[i] = __float2bfloat16(v - __bfloat162float(hi));
}
__global__ void k_repR() {
    int i = blockIdx.x * blockDim.x + threadIdx.x;
    if (i >= NUM_R * 512) return;
    int r = i >> 9, c = i & 511;
    float v = (c < 256) ? g_zR[r * DD + c] : g_u[(size_t)r * DD + (c - 256)];
    __nv_bfloat16 hi = __float2bfloat16(v);
    g_repRh[i] = hi;
    g_repRl[i] = __float2bfloat16(v - __bfloat162float(hi));
}

__global__ void k_head(const float* __restrict__ hid, const float* __restrict__ W2,
                       const float* __restrict__ b2, const int* __restrict__ y,
                       int rows, int accIdx) {
    int gw = (blockIdx.x * blockDim.x + threadIdx.x) >> 5;
    int lane = threadIdx.x & 31;
    if (gw >= rows) return;
    float p0 = 0.f, p1 = 0.f;
#pragma unroll
    for (int j = 0; j < 8; j++) {
        int k = lane + 32 * j;
        float h = hid[(size_t)gw * 256 + k];
        p0 = fmaf(h, W2[k * 2], p0);
        p1 = fmaf(h, W2[k * 2 + 1], p1);
    }
    for (int o = 16; o >= 1; o >>= 1) {
        p0 += __shfl_down_sync(0xffffffffu, p0, o);
        p1 += __shfl_down_sync(0xffffffffu, p1, o);
    }
    if (lane == 0) {
        float l0 = p0 + b2[0], l1 = p1 + b2[1];
        float mx = fmaxf(l0, l1);
        float lse = mx + logf(expf(l0 - mx) + expf(l1 - mx));
        atomicAdd(&g_acc[accIdx], ((y[gw] != 0) ? l1 : l0) - lse);
    }
}

__global__ void k_final(float* __restrict__ out) {
    float pred = -(g_acc[0] + 0.1f * g_acc[1]) / 1024.0f;
    float rat  = -g_acc[2] / 64.0f;
    float reg  = g_acc[3] / 32768.0f;
    out[0] = pred + rat - 0.1f * reg;
}

extern "C" void kernel_launch(void* const* d_in, const int* in_sizes, int n_in,
                              void* d_out, int out_size) {
    (void)in_sizes; (void)n_in; (void)out_size;
    const float* x     = (const float*)d_in[0];
    const int*   ei    = (const int*)  d_in[1];
    const int*   et    = (const int*)  d_in[2];
    const int*   batch = (const int*)  d_in[3];
    const int*   yM    = (const int*)  d_in[4];
    const int*   yR    = (const int*)  d_in[5];
    const float* HR    = (const float*)d_in[6];
    const float* nodeW = (const float*)d_in[7];
    const float* nodeB = (const float*)d_in[8];
    const float* Wr    = (const float*)d_in[9];
    const float* Wroot = (const float*)d_in[10];
    const float* gcnB  = (const float*)d_in[11];
    const float* pg    = (const float*)d_in[12];
    const float* puW   = (const float*)d_in[13];
    const float* puB   = (const float*)d_in[14];
    const float* qzW   = (const float*)d_in[15];
    const float* qzB   = (const float*)d_in[16];
    const float* W1    = (const float*)d_in[17];
    const float* b1    = (const float*)d_in[18];
    const float* W2    = (const float*)d_in[19];
    const float* b2    = (const float*)d_in[20];
    float* out = (float*)d_out;

    uint32_t ku0, ku1, ka0, ka1, kzm0, kzm1, kzr0, kzr1;
    tf2x32(0u, 42u, 0u, 0u, ku0, ku1);
    tf2x32(0u, 42u, 0u, 1u, ka0, ka1);
    tf2x32(0u, 42u, 0u, 2u, kzm0, kzm1);
    tf2x32(0u, 42u, 0u, 3u, kzr0, kzr1);

    void* p;
    cudaGetSymbolAddress(&p, g_featsB); float* featsB = (float*)p;
    cudaGetSymbolAddress(&p, g_G);      __half* G    = (__half*)p;
    cudaGetSymbolAddress(&p, g_Wfh);    __half* Wfh = (__half*)p;
    cudaGetSymbolAddress(&p, g_Wfl);    __half* Wfl = (__half*)p;
    cudaGetSymbolAddress(&p, g_nWfh);   __half* nWfh = (__half*)p;
    cudaGetSymbolAddress(&p, g_nWfl);   __half* nWfl = (__half*)p;
    cudaGetSymbolAddress(&p, g_xf);     __half* xf = (__half*)p;
    cudaGetSymbolAddress(&p, g_Af);     __half* Af = (__half*)p;
    cudaGetSymbolAddress(&p, g_puWh);   __nv_bfloat16* puWh = (__nv_bfloat16*)p;
    cudaGetSymbolAddress(&p, g_puWl);   __nv_bfloat16* puWl = (__nv_bfloat16*)p;
    cudaGetSymbolAddress(&p, g_qzWh);   __nv_bfloat16* qzWh = (__nv_bfloat16*)p;
    cudaGetSymbolAddress(&p, g_qzWl);   __nv_bfloat16* qzWl = (__nv_bfloat16*)p;
    cudaGetSymbolAddress(&p, g_w1h);    __nv_bfloat16* w1h = (__nv_bfloat16*)p;
    cudaGetSymbolAddress(&p, g_w1l);    __nv_bfloat16* w1l = (__nv_bfloat16*)p;
    cudaGetSymbolAddress(&p, g_Hh);     __nv_bfloat16* Hh  = (__nv_bfloat16*)p;
    cudaGetSymbolAddress(&p, g_Hl);     __nv_bfloat16* Hl  = (__nv_bfloat16*)p;
    cudaGetSymbolAddress(&p, g_repMh);  __nv_bfloat16* repMh = (__nv_bfloat16*)p;
    cudaGetSymbolAddress(&p, g_repMl);  __nv_bfloat16* repMl = (__nv_bfloat16*)p;
    cudaGetSymbolAddress(&p, g_repRh);  __nv_bfloat16* repRh = (__nv_bfloat16*)p;
    cudaGetSymbolAddress(&p, g_repRl);  __nv_bfloat16* repRl = (__nv_bfloat16*)p;
    cudaGetSymbolAddress(&p, g_pu);     float* pu     = (float*)p;
    cudaGetSymbolAddress(&p, g_qz);     float* qz     = (float*)p;
    cudaGetSymbolAddress(&p, g_hidM);   float* hidM   = (float*)p;
    cudaGetSymbolAddress(&p, g_hidR);   float* hidR   = (float*)p;

    static int smem_set = 0;
    if (!smem_set) {
        cudaFuncSetAttribute(k_fmma, cudaFuncAttributeMaxDynamicSharedMemorySize, 92160);
        cudaFuncSetAttribute(k_bmma, cudaFuncAttributeMaxDynamicSharedMemorySize, 122880);
        smem_set = 1;
    }

    k_zero_init<<<(N_RELS * N_NODES + 255) / 256, 256>>>();
    k_count<<<(N_EDGES + 255) / 256, 256>>>(ei, et);
    k_scan<<<1, 1024>>>();
    k_scatter<<<(N_EDGES + 255) / 256, 256>>>(ei, et);
    k_wsplitF<<<(N_LAYERS * GW * 256 + 255) / 256, 256>>>(Wroot, Wr);
    k_wsplitTF<<<(256 * D_IN + 255) / 256, 256>>>(nodeW, nWfh, nWfl, 256, D_IN);
    k_wsplitT<<<(512 * 256 + 255) / 256, 256>>>(puW, puWh, puWl, 512, 256);
    k_wsplitT<<<(512 * 256 + 255) / 256, 256>>>(qzW, qzWh, qzWl, 512, 256);
    k_wsplitT<<<(256 * 512 + 255) / 256, 256>>>(W1, w1h, w1l, 256, 512);
    k_tohalf<<<(N_NODES * D_IN + 255) / 256, 256>>>(x, xf, N_NODES * D_IN);

    k_fmma<<<dim3(2, (N_NODES + 127) / 128), 256, 92160>>>(
        xf, nWfh, nWfl, nodeB, nullptr, Af, N_NODES, 256, D_IN, 0);

    for (int l = 0; l < N_LAYERS; l++) {
        k_fmma<<<dim3(GW / 128, (N_NODES + 127) / 128), 256, 92160>>>(
            Af, Wfh + (size_t)l * GW * 256, Wfl + (size_t)l * GW * 256,
            nullptr, nullptr, G, N_NODES, GW, 256, 0);
        k_agg<<<(N_NODES * 32 + 255) / 256, 256>>>(
            gcnB + l * 256, Af, featsB, (l < N_LAYERS - 1) ? 1 : 0);
    }

    k_starts<<<(NUM_M + 256) / 256, 256>>>(batch);
    k_copyHR<<<(NUM_R * DD + 255) / 256, 256>>>(HR);
    k_gmean<<<NUM_M, 256>>>(featsB);

    k_bmma<<<dim3(4, HPAD / 128), 256, 122880>>>(
        Hh, Hl, puWh, puWl, puB, pu, N_ALL, 512, 256, 0);
    k_bmma<<<dim3(4, HPAD / 128), 256, 122880>>>(
        Hh, Hl, qzWh, qzWl, qzB, qz, N_ALL, 512, 256, 0);

    k_sample_u <<<(N_ALL * DD + 255) / 256, 256>>>(ku0, ku1);
    k_sample_zM<<<(NUM_M * DD + 255) / 256, 256>>>(kzm0, kzm1);
    k_sample_zR<<<(NUM_R * DD + 255) / 256, 256>>>(kzr0, kzr1);

    k_attn<<<NUM_M, 64>>>(pg, yM, ka0, ka1);
    k_pzq<<<NUM_M, 256>>>();

    k_repM<<<(NUM_M * 512 + 255) / 256, 256>>>();
    k_repR<<<(NUM_R * 512 + 255) / 256, 256>>>();
    k_bmma<<<dim3(2, NUM_M / 128), 256, 122880>>>(
        repMh, repMl, w1h, w1l, b1, hidM, NUM_M, 256, 512, 1);
    k_bmma<<<dim3(2, 1), 256, 122880>>>(
        repRh, repRl, w1h, w1l, b1, hidR, NUM_R, 256, 512, 1);
    k_head<<<(NUM_M * 32 + 255) / 256, 256>>>(hidM, W2, b2, yM, NUM_M, 0);
    k_head<<<(NUM_R * 32 + 255) / 256, 256>>>(hidR, W2, b2, yR, NUM_R, 2);

    k_final<<<1, 1>>>(out);
}

// round 11
// speedup vs baseline: 1.8368x; 1.1518x over previous
#include <cuda_runtime.h>
#include <cuda_bf16.h>
#include <cuda_fp16.h>
#include <stdint.h>
#include <math.h>

#define N_NODES 50000
#define N_EDGES 200000
#define D_IN    128
#define DD      256
#define N_LAYERS 4
#define N_RELS  4
#define NUM_M   1024
#define NUM_R   64
#define N_ALL   (NUM_R + NUM_M)
#define GW      1280
#define MPAD    (N_NODES + 128)
#define HPAD    1152

__device__ float g_featsB[N_NODES * DD];
__device__ __half g_G[(size_t)N_NODES * GW];
__device__ __half g_Wfh[N_LAYERS * GW * 256];
__device__ __half g_Wfl[N_LAYERS * GW * 256];
__device__ __half g_nWfh[256 * D_IN];
__device__ __half g_nWfl[256 * D_IN];
__device__ __half g_xf[(size_t)MPAD * D_IN];
__device__ __half g_Af[(size_t)MPAD * DD];
__device__ __nv_bfloat16 g_puWh[512 * 256];
__device__ __nv_bfloat16 g_puWl[512 * 256];
__device__ __nv_bfloat16 g_qzWh[512 * 256];
__device__ __nv_bfloat16 g_qzWl[512 * 256];
__device__ __nv_bfloat16 g_w1h[256 * 512];
__device__ __nv_bfloat16 g_w1l[256 * 512];
__device__ __nv_bfloat16 g_Hh[HPAD * DD];
__device__ __nv_bfloat16 g_Hl[HPAD * DD];
__device__ __nv_bfloat16 g_repMh[NUM_M * 512];
__device__ __nv_bfloat16 g_repMl[NUM_M * 512];
__device__ __nv_bfloat16 g_repRh[128 * 512];
__device__ __nv_bfloat16 g_repRl[128 * 512];
__device__ int   g_cnt[N_RELS * N_NODES];
__device__ int   g_deg[N_NODES];
__device__ int   g_off[N_NODES + 1];
__device__ int   g_cursor[N_NODES];
__device__ uint2 g_epack[N_EDGES];
__device__ int   g_start[NUM_M + 1];
__device__ float g_pu[N_ALL * 512];
__device__ float g_qz[N_ALL * 512];
__device__ float g_u[N_ALL * DD];
__device__ float g_zM[NUM_M * DD];
__device__ float g_zR[NUM_R * DD];
__device__ float g_An[NUM_M * NUM_R];
__device__ float g_hidM[NUM_M * 256];
__device__ float g_hidR[NUM_R * 256];
__device__ float g_acc[4];

__host__ __device__ __forceinline__ uint32_t rotl32(uint32_t x, int d) {
    return (x << d) | (x >> (32 - d));
}
__host__ __device__ __forceinline__ void tf2x32(uint32_t k0, uint32_t k1,
                                                uint32_t x0, uint32_t x1,
                                                uint32_t& o0, uint32_t& o1) {
    uint32_t ks2 = k0 ^ k1 ^ 0x1BD11BDAu;
    x0 += k0; x1 += k1;
#define TF_RND(R) { x0 += x1; x1 = rotl32(x1, R); x1 ^= x0; }
    TF_RND(13) TF_RND(15) TF_RND(26) TF_RND(6)
    x0 += k1;  x1 += ks2 + 1u;
    TF_RND(17) TF_RND(29) TF_RND(16) TF_RND(24)
    x0 += ks2; x1 += k0 + 2u;
    TF_RND(13) TF_RND(15) TF_RND(26) TF_RND(6)
    x0 += k0;  x1 += k1 + 3u;
    TF_RND(17) TF_RND(29) TF_RND(16) TF_RND(24)
    x0 += k1;  x1 += ks2 + 4u;
    TF_RND(13) TF_RND(15) TF_RND(26) TF_RND(6)
    x0 += ks2; x1 += k0 + 5u;
#undef TF_RND
    o0 = x0; o1 = x1;
}
__device__ __forceinline__ uint32_t rbits(uint32_t k0, uint32_t k1, uint32_t i) {
    uint32_t o0, o1; tf2x32(k0, k1, 0u, i, o0, o1); return o0 ^ o1;
}
__device__ __forceinline__ float erfinv_xla(float x) {
    float w = -log1pf(-x * x), p;
    if (w < 5.0f) {
        w -= 2.5f;
        p = 2.81022636e-08f;
        p = fmaf(p, w, 3.43273939e-07f);  p = fmaf(p, w, -3.5233877e-06f);
        p = fmaf(p, w, -4.39150654e-06f); p = fmaf(p, w, 0.00021858087f);
        p = fmaf(p, w, -0.00125372503f);  p = fmaf(p, w, -0.00417768164f);
        p = fmaf(p, w, 0.246640727f);     p = fmaf(p, w, 1.50140941f);
    } else {
        w = sqrtf(w) - 3.0f;
        p = -0.000200214257f;
        p = fmaf(p, w, 0.000100950558f);  p = fmaf(p, w, 0.00134934322f);
        p = fmaf(p, w, -0.00367342844f);  p = fmaf(p, w, 0.00573950773f);
        p = fmaf(p, w, -0.0076224613f);   p = fmaf(p, w, 0.00943887047f);
        p = fmaf(p, w, 1.00167406f);      p = fmaf(p, w, 2.83297682f);
    }
    return p * x;
}
__device__ __forceinline__ float u01(uint32_t b) {
    return __uint_as_float((b >> 9) | 0x3f800000u) - 1.0f;
}
__device__ __forceinline__ float nrm(uint32_t b) {
    const float LO = -0.99999994f;
    float v = u01(b) * 2.0f + LO;
    v = fmaxf(LO, v);
    return 1.41421356f * erfinv_xla(v);
}
__device__ __forceinline__ float unif(uint32_t b) {
    const float MN = 1e-06f;
    float v = u01(b) * (0.999999f - MN) + MN;
    return fmaxf(MN, v);
}

__global__ void k_zero_init() {
    int i = blockIdx.x * blockDim.x + threadIdx.x;
    if (i < N_RELS * N_NODES) g_cnt[i] = 0;
    if (i < N_NODES) g_deg[i] = 0;
    if (i < 4) g_acc[i] = 0.0f;
}
__global__ void k_count(const int* __restrict__ ei, const int* __restrict__ et) {
    int e = blockIdx.x * blockDim.x + threadIdx.x;
    if (e >= N_EDGES) return;
    int d = ei[N_EDGES + e];
    atomicAdd(&g_cnt[et[e] * N_NODES + d], 1);
    atomicAdd(&g_deg[d], 1);
}
__global__ void k_scan() {
    __shared__ int part[1024];
    int tid = threadIdx.x;
    const int chunk = (N_NODES + 1023) / 1024;
    int lo = tid * chunk, hi = min(lo + chunk, N_NODES);
    int s = 0;
    for (int i = lo; i < hi; i++) s += g_deg[i];
    part[tid] = s;
    __syncthreads();
    for (int o = 1; o < 1024; o <<= 1) {
        int v = (tid >= o) ? part[tid - o] : 0;
        __syncthreads(); part[tid] += v; __syncthreads();
    }
    int run = part[tid] - s;
    for (int i = lo; i < hi; i++) { g_off[i] = run; g_cursor[i] = run; run += g_deg[i]; }
    if (tid == 1023) g_off[N_NODES] = run;
}
__global__ void k_scatter(const int* __restrict__ ei, const int* __restrict__ et) {
    int e = blockIdx.x * blockDim.x + threadIdx.x;
    if (e >= N_EDGES) return;
    int sn = ei[e], d = ei[N_EDGES + e], r = et[e];
    int p = atomicAdd(&g_cursor[d], 1);
    float inv = 1.0f / (float)g_cnt[r * N_NODES + d];
    g_epack[p] = make_uint2((uint32_t)(sn * GW + 256 + (r << 8)), __float_as_uint(inv));
}
__global__ void k_wsplitF(const float* __restrict__ Wroot, const float* __restrict__ Wr) {
    int idx = blockIdx.x * blockDim.x + threadIdx.x;
    if (idx >= N_LAYERS * GW * 256) return;
    int l = idx / (GW * 256), rem = idx % (GW * 256);
    int n = rem / 256, k = rem % 256;
    float v;
    if (n < 256) v = Wroot[((size_t)l * 256 + k) * 256 + n];
    else {
        int r = (n >> 8) - 1, h = n & 255;
        v = Wr[(((size_t)l * 4 + r) * 256 + k) * 256 + h];
    }
    __half hi = __float2half_rn(v);
    g_Wfh[idx] = hi;
    g_Wfl[idx] = __float2half_rn(v - __half2float(hi));
}
__global__ void k_wsplitTF(const float* __restrict__ src, __half* __restrict__ h,
                           __half* __restrict__ l, int N, int K) {
    int idx = blockIdx.x * blockDim.x + threadIdx.x;
    if (idx >= N * K) return;
    int n = idx / K, k = idx % K;
    float v = src[(size_t)k * N + n];
    __half hi = __float2half_rn(v);
    h[idx] = hi;
    l[idx] = __float2half_rn(v - __half2float(hi));
}
__global__ void k_wsplitT(const float* __restrict__ src, __nv_bfloat16* __restrict__ h,
                          __nv_bfloat16* __restrict__ l, int N, int K) {
    int idx = blockIdx.x * blockDim.x + threadIdx.x;
    if (idx >= N * K) return;
    int n = idx / K, k = idx % K;
    float v = src[(size_t)k * N + n];
    __nv_bfloat16 hi = __float2bfloat16(v);
    h[idx] = hi;
    l[idx] = __float2bfloat16(v - __bfloat162float(hi));
}
__global__ void k_tohalf(const float* __restrict__ src, __half* __restrict__ dst, int n) {
    int i = blockIdx.x * blockDim.x + threadIdx.x;
    if (i < n) dst[i] = __float2half_rn(src[i]);
}

__device__ __forceinline__ void ldm4(uint32_t a, uint32_t& r0, uint32_t& r1,
                                     uint32_t& r2, uint32_t& r3) {
    asm volatile("ldmatrix.sync.aligned.m8n8.x4.shared.b16 {%0,%1,%2,%3}, [%4];"
                 : "=r"(r0), "=r"(r1), "=r"(r2), "=r"(r3) : "r"(a));
}
__device__ __forceinline__ void mma_bf(float* c, const uint32_t* a, const uint32_t* b) {
    asm volatile("mma.sync.aligned.m16n8k16.row.col.f32.bf16.bf16.f32 "
                 "{%0,%1,%2,%3},{%4,%5,%6,%7},{%8,%9},{%0,%1,%2,%3};"
                 : "+f"(c[0]), "+f"(c[1]), "+f"(c[2]), "+f"(c[3])
                 : "r"(a[0]), "r"(a[1]), "r"(a[2]), "r"(a[3]), "r"(b[0]), "r"(b[1]));
}
__device__ __forceinline__ void mma_fp(float* c, const uint32_t* a, const uint32_t* b) {
    asm volatile("mma.sync.aligned.m16n8k16.row.col.f32.f16.f16.f32 "
                 "{%0,%1,%2,%3},{%4,%5,%6,%7},{%8,%9},{%0,%1,%2,%3};"
                 : "+f"(c[0]), "+f"(c[1]), "+f"(c[2]), "+f"(c[3])
                 : "r"(a[0]), "r"(a[1]), "r"(a[2]), "r"(a[3]), "r"(b[0]), "r"(b[1]));
}
__device__ __forceinline__ void cp16(uint32_t dst, const void* src) {
    asm volatile("cp.async.cg.shared.global [%0], [%1], 16;" :: "r"(dst), "l"(src));
}

// ===== fp16 2-term GEMM: A single fp16, B hi/lo fp16. BM=BN=128, BK=32, 3 stages, 2 CTA/SM =====
#define LOAD_STAGE_F(s, kq)                                            \
    do {                                                               \
        uint32_t st_ = smq + (s) * 30720;                              \
        _Pragma("unroll")                                              \
        for (int q_ = 0; q_ < 2; q_++) {                               \
            int col_ = (c0 + q_) * 8;                                  \
            uint32_t dd_ = st_ + (row * 40 + col_) * 2;                \
            cp16(dd_,         Agf + (kq) + col_);                      \
            cp16(dd_ + 10240, Bgh + (kq) + col_);                      \
            cp16(dd_ + 20480, Bgl + (kq) + col_);                      \
        }                                                              \
    } while (0)

__global__ void __launch_bounds__(256, 2)
k_fmma(const __half* __restrict__ Af, const __half* __restrict__ Bh,
       const __half* __restrict__ Bl, const float* __restrict__ bias,
       float* __restrict__ C, __half* __restrict__ oF,
       int M, int N, int K, int relu_out) {
    extern __shared__ __align__(16) __half dsmf[];
    uint32_t smq = (uint32_t)__cvta_generic_to_shared(dsmf);
    int tid = threadIdx.x, lane = tid & 31, wid = tid >> 5;
    int wm = (wid >> 2) * 64, wn = (wid & 3) * 32;
    int bm = blockIdx.y * 128, bn = blockIdx.x * 128;
    int row = tid >> 1, c0 = (tid & 1) * 2;
    const __half* Agf = Af + (size_t)(bm + row) * K;
    const __half* Bgh = Bh + (size_t)(bn + row) * K;
    const __half* Bgl = Bl + (size_t)(bn + row) * K;

    float acc[4][4][4];
#pragma unroll
    for (int i = 0; i < 4; i++)
#pragma unroll
        for (int j = 0; j < 4; j++)
#pragma unroll
            for (int q = 0; q < 4; q++) acc[i][j][q] = 0.f;

    LOAD_STAGE_F(0, 0);
    asm volatile("cp.async.commit_group;");
    if (32 < K) LOAD_STAGE_F(1, 32);
    asm volatile("cp.async.commit_group;");

    int cur = 0;
    for (int k0 = 0; k0 < K; k0 += 32) {
        int pre = k0 + 64;
        if (pre < K) {
            int s2 = cur + 2; if (s2 >= 3) s2 -= 3;
            LOAD_STAGE_F(s2, pre);
        }
        asm volatile("cp.async.commit_group;");
        asm volatile("cp.async.wait_group 2;");
        __syncthreads();
        uint32_t st = smq + cur * 30720;
#pragma unroll
        for (int kk = 0; kk < 32; kk += 16) {
            uint32_t bh[4][2], bl[4][2];
            int brow = wn + (lane & 7) + ((lane >> 4) & 1) * 8;
            int bcol = kk + ((lane >> 3) & 1) * 8;
#pragma unroll
            for (int nb = 0; nb < 2; nb++) {
                uint32_t off = ((brow + nb * 16) * 40 + bcol) * 2;
                ldm4(st + 10240 + off, bh[2 * nb][0], bh[2 * nb][1], bh[2 * nb + 1][0], bh[2 * nb + 1][1]);
                ldm4(st + 20480 + off, bl[2 * nb][0], bl[2 * nb][1], bl[2 * nb + 1][0], bl[2 * nb + 1][1]);
            }
            int arow = wm + (lane & 7) + ((lane >> 3) & 1) * 8;
            int acol = kk + ((lane >> 4) & 1) * 8;
#pragma unroll
            for (int mf = 0; mf < 4; mf++) {
                uint32_t a[4];
                uint32_t off = ((arow + mf * 16) * 40 + acol) * 2;
                ldm4(st + off, a[0], a[1], a[2], a[3]);
#pragma unroll
                for (int nf = 0; nf < 4; nf++) {
                    mma_fp(acc[mf][nf], a, bh[nf]);
                    mma_fp(acc[mf][nf], a, bl[nf]);
                }
            }
        }
        __syncthreads();
        cur++; if (cur >= 3) cur = 0;
    }
#pragma unroll
    for (int mf = 0; mf < 4; mf++)
#pragma unroll
        for (int nf = 0; nf < 4; nf++) {
            int r0 = bm + wm + mf * 16 + (lane >> 2);
            int c0o = bn + wn + nf * 8 + (lane & 3) * 2;
#pragma unroll
            for (int h = 0; h < 2; h++) {
                int r = r0 + h * 8;
                if (r >= M) continue;
                float v0 = acc[mf][nf][2 * h], v1 = acc[mf][nf][2 * h + 1];
                if (bias) { v0 += bias[c0o]; v1 += bias[c0o + 1]; }
                if (relu_out) { v0 = fmaxf(v0, 0.f); v1 = fmaxf(v1, 0.f); }
                if (oF) {
                    *(__half2*)(oF + (size_t)r * N + c0o) = __floats2half2_rn(v0, v1);
                } else {
                    *(float2*)(C + (size_t)r * N + c0o) = make_float2(v0, v1);
                }
            }
        }
}

// ===== bf16 3-term GEMM for tail =====
#define LOAD_STAGE(s, kq)                                              \
    do {                                                               \
        uint32_t st_ = sm + (s) * 40960;                               \
        _Pragma("unroll")                                              \
        for (int q_ = 0; q_ < 2; q_++) {                               \
            int col_ = (c0 + q_) * 8;                                  \
            uint32_t dd_ = st_ + (row * 40 + col_) * 2;                \
            cp16(dd_,         Agh + (kq) + col_);                      \
            cp16(dd_ + 10240, Agl + (kq) + col_);                      \
            cp16(dd_ + 20480, Bgh + (kq) + col_);                      \
            cp16(dd_ + 30720, Bgl + (kq) + col_);                      \
        }                                                              \
    } while (0)

__global__ void __launch_bounds__(256, 1)
k_bmma(const __nv_bfloat16* __restrict__ Ah, const __nv_bfloat16* __restrict__ Al,
       const __nv_bfloat16* __restrict__ Bh, const __nv_bfloat16* __restrict__ Bl,
       const float* __restrict__ bias, float* __restrict__ C,
       int M, int N, int K, int relu_out) {
    extern __shared__ __align__(16) __nv_bfloat16 dsm[];
    uint32_t sm = (uint32_t)__cvta_generic_to_shared(dsm);
    int tid = threadIdx.x, lane = tid & 31, wid = tid >> 5;
    int wm = (wid >> 2) * 64, wn = (wid & 3) * 32;
    int bm = blockIdx.y * 128, bn = blockIdx.x * 128;
    int row = tid >> 1, c0 = (tid & 1) * 2;
    const __nv_bfloat16* Agh = Ah + (size_t)(bm + row) * K;
    const __nv_bfloat16* Agl = Al + (size_t)(bm + row) * K;
    const __nv_bfloat16* Bgh = Bh + (size_t)(bn + row) * K;
    const __nv_bfloat16* Bgl = Bl + (size_t)(bn + row) * K;

    float acc[4][4][4];
#pragma unroll
    for (int i = 0; i < 4; i++)
#pragma unroll
        for (int j = 0; j < 4; j++)
#pragma unroll
            for (int q = 0; q < 4; q++) acc[i][j][q] = 0.f;

    LOAD_STAGE(0, 0);
    asm volatile("cp.async.commit_group;");
    if (32 < K) LOAD_STAGE(1, 32);
    asm volatile("cp.async.commit_group;");

    int cur = 0;
    for (int k0 = 0; k0 < K; k0 += 32) {
        int pre = k0 + 64;
        if (pre < K) {
            int s2 = cur + 2; if (s2 >= 3) s2 -= 3;
            LOAD_STAGE(s2, pre);
        }
        asm volatile("cp.async.commit_group;");
        asm volatile("cp.async.wait_group 2;");
        __syncthreads();
        uint32_t st = sm + cur * 40960;
#pragma unroll
        for (int kk = 0; kk < 32; kk += 16) {
            uint32_t bh[4][2], bl[4][2];
            int brow = wn + (lane & 7) + ((lane >> 4) & 1) * 8;
            int bcol = kk + ((lane >> 3) & 1) * 8;
#pragma unroll
            for (int nb = 0; nb < 2; nb++) {
                uint32_t off = ((brow + nb * 16) * 40 + bcol) * 2;
                ldm4(st + 20480 + off, bh[2 * nb][0], bh[2 * nb][1], bh[2 * nb + 1][0], bh[2 * nb + 1][1]);
                ldm4(st + 30720 + off, bl[2 * nb][0], bl[2 * nb][1], bl[2 * nb + 1][0], bl[2 * nb + 1][1]);
            }
            int arow = wm + (lane & 7) + ((lane >> 3) & 1) * 8;
            int acol = kk + ((lane >> 4) & 1) * 8;
#pragma unroll
            for (int mf = 0; mf < 4; mf++) {
                uint32_t ah[4], al[4];
                uint32_t off = ((arow + mf * 16) * 40 + acol) * 2;
                ldm4(st + off, ah[0], ah[1], ah[2], ah[3]);
                ldm4(st + 10240 + off, al[0], al[1], al[2], al[3]);
#pragma unroll
                for (int nf = 0; nf < 4; nf++) {
                    mma_bf(acc[mf][nf], ah, bh[nf]);
                    mma_bf(acc[mf][nf], ah, bl[nf]);
                    mma_bf(acc[mf][nf], al, bh[nf]);
                }
            }
        }
        __syncthreads();
        cur++; if (cur >= 3) cur = 0;
    }
#pragma unroll
    for (int mf = 0; mf < 4; mf++)
#pragma unroll
        for (int nf = 0; nf < 4; nf++) {
            int r0 = bm + wm + mf * 16 + (lane >> 2);
            int c0o = bn + wn + nf * 8 + (lane & 3) * 2;
#pragma unroll
            for (int h = 0; h < 2; h++) {
                int r = r0 + h * 8;
                if (r >= M) continue;
                float v0 = acc[mf][nf][2 * h], v1 = acc[mf][nf][2 * h + 1];
                if (bias) { v0 += bias[c0o]; v1 += bias[c0o + 1]; }
                if (relu_out) { v0 = fmaxf(v0, 0.f); v1 = fmaxf(v1, 0.f); }
                *(float2*)(C + (size_t)r * N + c0o) = make_float2(v0, v1);
            }
        }
}

__device__ __forceinline__ void up4(uint2 v, float* f) {
    __half2* h = (__half2*)&v;
    float2 a0 = __half22float2(h[0]); f[0] = a0.x; f[1] = a0.y;
    float2 a1 = __half22float2(h[1]); f[2] = a1.x; f[3] = a1.y;
}

// aggregation over fp16 G, 2 warps per node (each owns 128 of 256 cols)
__global__ void k_agg(const float* __restrict__ bias, __half* __restrict__ ofh,
                      float* __restrict__ out32, int relu) {
    int gw = (blockIdx.x * blockDim.x + threadIdx.x) >> 5;
    int lane = threadIdx.x & 31;
    int d = gw >> 1;
    int half = gw & 1;
    if (d >= N_NODES) return;
    int cb = half * 128 + lane * 4;   // column base for this lane (4 cols)
    float acc[4];
    {
        uint2 base = *(const uint2*)(g_G + (size_t)d * GW + cb);
        up4(base, acc);
        float4 bb = *(const float4*)(bias + cb);
        acc[0] += bb.x; acc[1] += bb.y; acc[2] += bb.z; acc[3] += bb.w;
    }
    int s = g_off[d], e = g_off[d + 1];
    int i = s;
#define AGG_EDGE(P)                                                     \
    {                                                                   \
        uint2 gv = *(const uint2*)(g_G + (P).x + cb);                   \
        float inv = __uint_as_float((P).y);                             \
        float f[4]; up4(gv, f);                                         \
        acc[0] = fmaf(f[0], inv, acc[0]); acc[1] = fmaf(f[1], inv, acc[1]); \
        acc[2] = fmaf(f[2], inv, acc[2]); acc[3] = fmaf(f[3], inv, acc[3]); \
    }
    for (; i + 4 <= e; i += 4) {
        uint2 p0 = g_epack[i],     p1 = g_epack[i + 1];
        uint2 p2 = g_epack[i + 2], p3 = g_epack[i + 3];
        AGG_EDGE(p0) AGG_EDGE(p1) AGG_EDGE(p2) AGG_EDGE(p3)
    }
    for (; i < e; i++) {
        uint2 p0 = g_epack[i];
        AGG_EDGE(p0)
    }
#undef AGG_EDGE
    if (relu) {
#pragma unroll
        for (int j = 0; j < 4; j++) acc[j] = fmaxf(acc[j], 0.f);
        uint2 ov;
        __half2* oh = (__half2*)&ov;
        oh[0] = __floats2half2_rn(acc[0], acc[1]);
        oh[1] = __floats2half2_rn(acc[2], acc[3]);
        *(uint2*)(ofh + (size_t)d * DD + cb) = ov;
    } else {
        *(float4*)(out32 + (size_t)d * DD + cb) =
            make_float4(acc[0], acc[1], acc[2], acc[3]);
    }
}

__global__ void k_starts(const int* __restrict__ batch) {
    int m = blockIdx.x * blockDim.x + threadIdx.x;
    if (m > NUM_M) return;
    int lo = 0, hi = N_NODES;
    while (lo < hi) { int mid = (lo + hi) >> 1; if (batch[mid] < m) lo = mid + 1; else hi = mid; }
    g_start[m] = lo;
}
__global__ void k_copyHR(const float* __restrict__ HR) {
    int i = blockIdx.x * blockDim.x + threadIdx.x;
    if (i >= NUM_R * DD) return;
    float v = fmaxf(HR[i], 0.f);
    __nv_bfloat16 hi = __float2bfloat16(v);
    g_Hh[i] = hi;
    g_Hl[i] = __float2bfloat16(v - __bfloat162float(hi));
}
__global__ void k_gmean(const float* __restrict__ feats) {
    int m = blockIdx.x, c = threadIdx.x;
    int s = g_start[m], e = g_start[m + 1];
    float acc = 0.f;
    for (int n = s; n < e; n++) acc += feats[(size_t)n * DD + c];
    float v = fmaxf(acc / fmaxf((float)(e - s), 1.0f), 0.f);
    __nv_bfloat16 hi = __float2bfloat16(v);
    size_t idx = (size_t)(NUM_R + m) * DD + c;
    g_Hh[idx] = hi;
    g_Hl[idx] = __float2bfloat16(v - __bfloat162float(hi));
}

// merged sampling: u (278528), zM (262144), zR (16384)
__global__ void k_sample_all(unsigned ku0, unsigned ku1, unsigned kzm0, unsigned kzm1,
                             unsigned kzr0, unsigned kzr1) {
    int i = blockIdx.x * blockDim.x + threadIdx.x;
    const int NU = N_ALL * DD, NZM = NUM_M * DD, NZR = NUM_R * DD;
    if (i < NU) {
        int row = i >> 8, col = i & 255;
        g_u[i] = g_pu[row * 512 + col] + expf(g_pu[row * 512 + 256 + col]) * nrm(rbits(ku0, ku1, i));
    } else if (i < NU + NZM) {
        int j = i - NU;
        int m = j >> 8, col = j & 255;
        int r = (NUM_R + m) * 512;
        g_zM[j] = g_qz[r + col] + expf(g_qz[r + 256 + col]) * nrm(rbits(kzm0, kzm1, j));
    } else if (i < NU + NZM + NZR) {
        int j = i - NU - NZM;
        int r = j >> 8, col = j & 255;
        g_zR[j] = g_qz[r * 512 + col] + expf(g_qz[r * 512 + 256 + col]) * nrm(rbits(kzr0, kzr1, j));
    }
}

__global__ void k_attn(const float* __restrict__ pg, const int* __restrict__ yM,
                       unsigned k0, unsigned k1) {
    int m = blockIdx.x, r = threadIdx.x;
    __shared__ float um[DD];
    __shared__ float d2s[NUM_R];
    __shared__ float red[NUM_R];
    for (int i = r; i < DD; i += 64) um[i] = g_u[(size_t)(NUM_R + m) * DD + i];
    __syncthreads();
    float d2 = 0.f;
    const float* ur = g_u + (size_t)r * DD;
    for (int dd = 0; dd < DD; dd++) {
        float t = um[dd] - ur[dd];
        d2 = fmaf(t, t, d2);
    }
    d2s[r] = d2;
    float logp = -0.5f * d2 / expf(pg[0]);
    float logit = logp - logf(fmaxf(-expm1f(logp), 1e-20f));
    float U = unif(rbits(k0, k1, (uint32_t)(m * NUM_R + r)));
    float gn = logf(U) - log1pf(-U);
    float A = 1.0f / (1.0f + expf(-(logit + gn) / 0.3f));
    red[r] = A;
    __syncthreads();
    for (int o = 32; o >= 1; o >>= 1) {
        if (r < o) red[r] += red[r + o];
        __syncthreads();
    }
    g_An[m * NUM_R + r] = A / (red[0] + 1e-8f);
    if (r < 32) {
        int idx = r + (1 - yM[m]) * 32;
        float t = sqrtf(fmaxf(d2s[idx], 1e-12f));
        for (int o = 16; o >= 1; o >>= 1) t += __shfl_down_sync(0xffffffffu, t, o);
        if (r == 0) atomicAdd(&g_acc[3], t);
    }
}

__global__ void k_pzq() {
    int m = blockIdx.x, c = threadIdx.x;
    __shared__ float an[NUM_R];
    if (c < NUM_R) an[c] = g_An[m * NUM_R + c];
    __syncthreads();
    float pm = 0.f, pl = 0.f;
    for (int r = 0; r < NUM_R; r++) {
        float a = an[r];
        pm = fmaf(a, g_qz[r * 512 + c], pm);
        pl = fmaf(a, g_qz[r * 512 + 256 + c], pl);
    }
    float z = g_zM[m * DD + c];
    float qm = g_qz[(NUM_R + m) * 512 + c], ql = g_qz[(NUM_R + m) * 512 + 256 + c];
    float t1 = (z - pm) * expf(-pl);
    float t2 = (z - qm) * expf(-ql);
    float v = (-pl - 0.5f * t1 * t1) - (-ql - 0.5f * t2 * t2);
    __shared__ float red[256];
    red[c] = v;
    __syncthreads();
    for (int o = 128; o >= 1; o >>= 1) {
        if (c < o) red[c] += red[c + o];
        __syncthreads();
    }
    if (c == 0) atomicAdd(&g_acc[1], red[0]);
}

__global__ void k_reps() {
    int i = blockIdx.x * blockDim.x + threadIdx.x;
    const int NM = NUM_M * 512;
    if (i < NM) {
        int m = i >> 9, c = i & 511;
        float v = (c < 256) ? g_zM[m * DD + c] : g_u[(size_t)(NUM_R + m) * DD + (c - 256)];
        __nv_bfloat16 hi = __float2bfloat16(v);
        g_repMh[i] = hi;
        g_repMl[i] = __float2bfloat16(v - __bfloat162float(hi));
    } else if (i < NM + NUM_R * 512) {
        int j = i - NM;
        int r = j >> 9, c = j & 511;
        float v = (c < 256) ? g_zR[r * DD + c] : g_u[(size_t)r * DD + (c - 256)];
        __nv_bfloat16 hi = __float2bfloat16(v);
        g_repRh[j] = hi;
        g_repRl[j] = __float2bfloat16(v - __bfloat162float(hi));
    }
}

__global__ void k_head(const float* __restrict__ hid, const float* __restrict__ W2,
                       const float* __restrict__ b2, const int* __restrict__ y,
                       int rows, int accIdx) {
    int gw = (blockIdx.x * blockDim.x + threadIdx.x) >> 5;
    int lane = threadIdx.x & 31;
    if (gw >= rows) return;
    float p0 = 0.f, p1 = 0.f;
#pragma unroll
    for (int j = 0; j < 8; j++) {
        int k = lane + 32 * j;
        float h = hid[(size_t)gw * 256 + k];
        p0 = fmaf(h, W2[k * 2], p0);
        p1 = fmaf(h, W2[k * 2 + 1], p1);
    }
    for (int o = 16; o >= 1; o >>= 1) {
        p0 += __shfl_down_sync(0xffffffffu, p0, o);
        p1 += __shfl_down_sync(0xffffffffu, p1, o);
    }
    if (lane == 0) {
        float l0 = p0 + b2[0], l1 = p1 + b2[1];
        float mx = fmaxf(l0, l1);
        float lse = mx + logf(expf(l0 - mx) + expf(l1 - mx));
        atomicAdd(&g_acc[accIdx], ((y[gw] != 0) ? l1 : l0) - lse);
    }
}

__global__ void k_final(float* __restrict__ out) {
    float pred = -(g_acc[0] + 0.1f * g_acc[1]) / 1024.0f;
    float rat  = -g_acc[2] / 64.0f;
    float reg  = g_acc[3] / 32768.0f;
    out[0] = pred + rat - 0.1f * reg;
}

extern "C" void kernel_launch(void* const* d_in, const int* in_sizes, int n_in,
                              void* d_out, int out_size) {
    (void)in_sizes; (void)n_in; (void)out_size;
    const float* x     = (const float*)d_in[0];
    const int*   ei    = (const int*)  d_in[1];
    const int*   et    = (const int*)  d_in[2];
    const int*   batch = (const int*)  d_in[3];
    const int*   yM    = (const int*)  d_in[4];
    const int*   yR    = (const int*)  d_in[5];
    const float* HR    = (const float*)d_in[6];
    const float* nodeW = (const float*)d_in[7];
    const float* nodeB = (const float*)d_in[8];
    const float* Wr    = (const float*)d_in[9];
    const float* Wroot = (const float*)d_in[10];
    const float* gcnB  = (const float*)d_in[11];
    const float* pg    = (const float*)d_in[12];
    const float* puW   = (const float*)d_in[13];
    const float* puB   = (const float*)d_in[14];
    const float* qzW   = (const float*)d_in[15];
    const float* qzB   = (const float*)d_in[16];
    const float* W1    = (const float*)d_in[17];
    const float* b1    = (const float*)d_in[18];
    const float* W2    = (const float*)d_in[19];
    const float* b2    = (const float*)d_in[20];
    float* out = (float*)d_out;

    uint32_t ku0, ku1, ka0, ka1, kzm0, kzm1, kzr0, kzr1;
    tf2x32(0u, 42u, 0u, 0u, ku0, ku1);
    tf2x32(0u, 42u, 0u, 1u, ka0, ka1);
    tf2x32(0u, 42u, 0u, 2u, kzm0, kzm1);
    tf2x32(0u, 42u, 0u, 3u, kzr0, kzr1);

    void* p;
    cudaGetSymbolAddress(&p, g_featsB); float* featsB = (float*)p;
    cudaGetSymbolAddress(&p, g_G);      __half* G    = (__half*)p;
    cudaGetSymbolAddress(&p, g_Wfh);    __half* Wfh = (__half*)p;
    cudaGetSymbolAddress(&p, g_Wfl);    __half* Wfl = (__half*)p;
    cudaGetSymbolAddress(&p, g_nWfh);   __half* nWfh = (__half*)p;
    cudaGetSymbolAddress(&p, g_nWfl);   __half* nWfl = (__half*)p;
    cudaGetSymbolAddress(&p, g_xf);     __half* xf = (__half*)p;
    cudaGetSymbolAddress(&p, g_Af);     __half* Af = (__half*)p;
    cudaGetSymbolAddress(&p, g_puWh);   __nv_bfloat16* puWh = (__nv_bfloat16*)p;
    cudaGetSymbolAddress(&p, g_puWl);   __nv_bfloat16* puWl = (__nv_bfloat16*)p;
    cudaGetSymbolAddress(&p, g_qzWh);   __nv_bfloat16* qzWh = (__nv_bfloat16*)p;
    cudaGetSymbolAddress(&p, g_qzWl);   __nv_bfloat16* qzWl = (__nv_bfloat16*)p;
    cudaGetSymbolAddress(&p, g_w1h);    __nv_bfloat16* w1h = (__nv_bfloat16*)p;
    cudaGetSymbolAddress(&p, g_w1l);    __nv_bfloat16* w1l = (__nv_bfloat16*)p;
    cudaGetSymbolAddress(&p, g_Hh);     __nv_bfloat16* Hh  = (__nv_bfloat16*)p;
    cudaGetSymbolAddress(&p, g_Hl);     __nv_bfloat16* Hl  = (__nv_bfloat16*)p;
    cudaGetSymbolAddress(&p, g_repMh);  __nv_bfloat16* repMh = (__nv_bfloat16*)p;
    cudaGetSymbolAddress(&p, g_repMl);  __nv_bfloat16* repMl = (__nv_bfloat16*)p;
    cudaGetSymbolAddress(&p, g_repRh);  __nv_bfloat16* repRh = (__nv_bfloat16*)p;
    cudaGetSymbolAddress(&p, g_repRl);  __nv_bfloat16* repRl = (__nv_bfloat16*)p;
    cudaGetSymbolAddress(&p, g_pu);     float* pu     = (float*)p;
    cudaGetSymbolAddress(&p, g_qz);     float* qz     = (float*)p;
    cudaGetSymbolAddress(&p, g_hidM);   float* hidM   = (float*)p;
    cudaGetSymbolAddress(&p, g_hidR);   float* hidR   = (float*)p;

    static int smem_set = 0;
    if (!smem_set) {
        cudaFuncSetAttribute(k_fmma, cudaFuncAttributeMaxDynamicSharedMemorySize, 92160);
        cudaFuncSetAttribute(k_bmma, cudaFuncAttributeMaxDynamicSharedMemorySize, 122880);
        smem_set = 1;
    }

    k_zero_init<<<(N_RELS * N_NODES + 255) / 256, 256>>>();
    k_count<<<(N_EDGES + 255) / 256, 256>>>(ei, et);
    k_scan<<<1, 1024>>>();
    k_scatter<<<(N_EDGES + 255) / 256, 256>>>(ei, et);
    k_wsplitF<<<(N_LAYERS * GW * 256 + 255) / 256, 256>>>(Wroot, Wr);
    k_wsplitTF<<<(256 * D_IN + 255) / 256, 256>>>(nodeW, nWfh, nWfl, 256, D_IN);
    k_wsplitT<<<(512 * 256 + 255) / 256, 256>>>(puW, puWh, puWl, 512, 256);
    k_wsplitT<<<(512 * 256 + 255) / 256, 256>>>(qzW, qzWh, qzWl, 512, 256);
    k_wsplitT<<<(256 * 512 + 255) / 256, 256>>>(W1, w1h, w1l, 256, 512);
    k_tohalf<<<(N_NODES * D_IN + 255) / 256, 256>>>(x, xf, N_NODES * D_IN);

    k_fmma<<<dim3(2, (N_NODES + 127) / 128), 256, 92160>>>(
        xf, nWfh, nWfl, nodeB, nullptr, Af, N_NODES, 256, D_IN, 0);

    for (int l = 0; l < N_LAYERS; l++) {
        k_fmma<<<dim3(GW / 128, (N_NODES + 127) / 128), 256, 92160>>>(
            Af, Wfh + (size_t)l * GW * 256, Wfl + (size_t)l * GW * 256,
            nullptr, nullptr, G, N_NODES, GW, 256, 0);
        k_agg<<<(N_NODES * 2 * 32 + 255) / 256, 256>>>(
            gcnB + l * 256, Af, featsB, (l < N_LAYERS - 1) ? 1 : 0);
    }

    k_starts<<<(NUM_M + 256) / 256, 256>>>(batch);
    k_copyHR<<<(NUM_R * DD + 255) / 256, 256>>>(HR);
    k_gmean<<<NUM_M, 256>>>(featsB);

    k_bmma<<<dim3(4, HPAD / 128), 256, 122880>>>(
        Hh, Hl, puWh, puWl, puB, pu, N_ALL, 512, 256, 0);
    k_bmma<<<dim3(4, HPAD / 128), 256, 122880>>>(
        Hh, Hl, qzWh, qzWl, qzB, qz, N_ALL, 512, 256, 0);

    k_sample_all<<<((N_ALL + NUM_M + NUM_R) * DD + 255) / 256, 256>>>(
        ku0, ku1, kzm0, kzm1, kzr0, kzr1);

    k_attn<<<NUM_M, 64>>>(pg, yM, ka0, ka1);
    k_pzq<<<NUM_M, 256>>>();

    k_reps<<<((NUM_M + NUM_R) * 512 + 255) / 256, 256>>>();
    k_bmma<<<dim3(2, NUM_M / 128), 256, 122880>>>(
        repMh, repMl, w1h, w1l, b1, hidM, NUM_M, 256, 512, 1);
    k_bmma<<<dim3(2, 1), 256, 122880>>>(
        repRh, repRl, w1h, w1l, b1, hidR, NUM_R, 256, 512, 1);
    k_head<<<(NUM_M * 32 + 255) / 256, 256>>>(hidM, W2, b2, yM, NUM_M, 0);
    k_head<<<(NUM_R * 32 + 255) / 256, 256>>>(hidR, W2, b2, yR, NUM_R, 2);

    k_final<<<1, 1>>>(out);
}

// round 12
// speedup vs baseline: 2.3160x; 1.2609x over previous
#include <cuda_runtime.h>
#include <cuda_bf16.h>
#include <cuda_fp16.h>
#include <stdint.h>
#include <math.h>

#define N_NODES 50000
#define N_EDGES 200000
#define D_IN    128
#define DD      256
#define N_LAYERS 4
#define N_RELS  4
#define NUM_M   1024
#define NUM_R   64
#define N_ALL   (NUM_R + NUM_M)
#define GW      1280
#define MPAD    (N_NODES + 128)
#define HPAD    1152

__device__ float g_featsB[N_NODES * DD];
__device__ __half g_G[(size_t)N_NODES * GW];
__device__ __half g_Wfh[N_LAYERS * GW * 256];
__device__ __half g_nWfh[256 * D_IN];
__device__ __half g_xf[(size_t)MPAD * D_IN];
__device__ __half g_Af[(size_t)MPAD * DD];
__device__ __nv_bfloat16 g_puWh[512 * 256];
__device__ __nv_bfloat16 g_puWl[512 * 256];
__device__ __nv_bfloat16 g_qzWh[512 * 256];
__device__ __nv_bfloat16 g_qzWl[512 * 256];
__device__ __nv_bfloat16 g_w1h[256 * 512];
__device__ __nv_bfloat16 g_w1l[256 * 512];
__device__ __nv_bfloat16 g_Hh[HPAD * DD];
__device__ __nv_bfloat16 g_Hl[HPAD * DD];
__device__ __nv_bfloat16 g_repMh[NUM_M * 512];
__device__ __nv_bfloat16 g_repMl[NUM_M * 512];
__device__ __nv_bfloat16 g_repRh[128 * 512];
__device__ __nv_bfloat16 g_repRl[128 * 512];
__device__ int   g_cnt[N_RELS * N_NODES];
__device__ int   g_deg[N_NODES];
__device__ int   g_off[N_NODES + 1];
__device__ int   g_cursor[N_NODES];
__device__ uint2 g_epack[N_EDGES];
__device__ int   g_start[NUM_M + 1];
__device__ float g_pu[N_ALL * 512];
__device__ float g_qz[N_ALL * 512];
__device__ float g_u[N_ALL * DD];
__device__ float g_zM[NUM_M * DD];
__device__ float g_zR[NUM_R * DD];
__device__ float g_An[NUM_M * NUM_R];
__device__ float g_hidM[NUM_M * 256];
__device__ float g_hidR[NUM_R * 256];
__device__ float g_acc[4];

__host__ __device__ __forceinline__ uint32_t rotl32(uint32_t x, int d) {
    return (x << d) | (x >> (32 - d));
}
__host__ __device__ __forceinline__ void tf2x32(uint32_t k0, uint32_t k1,
                                                uint32_t x0, uint32_t x1,
                                                uint32_t& o0, uint32_t& o1) {
    uint32_t ks2 = k0 ^ k1 ^ 0x1BD11BDAu;
    x0 += k0; x1 += k1;
#define TF_RND(R) { x0 += x1; x1 = rotl32(x1, R); x1 ^= x0; }
    TF_RND(13) TF_RND(15) TF_RND(26) TF_RND(6)
    x0 += k1;  x1 += ks2 + 1u;
    TF_RND(17) TF_RND(29) TF_RND(16) TF_RND(24)
    x0 += ks2; x1 += k0 + 2u;
    TF_RND(13) TF_RND(15) TF_RND(26) TF_RND(6)
    x0 += k0;  x1 += k1 + 3u;
    TF_RND(17) TF_RND(29) TF_RND(16) TF_RND(24)
    x0 += k1;  x1 += ks2 + 4u;
    TF_RND(13) TF_RND(15) TF_RND(26) TF_RND(6)
    x0 += ks2; x1 += k0 + 5u;
#undef TF_RND
    o0 = x0; o1 = x1;
}
__device__ __forceinline__ uint32_t rbits(uint32_t k0, uint32_t k1, uint32_t i) {
    uint32_t o0, o1; tf2x32(k0, k1, 0u, i, o0, o1); return o0 ^ o1;
}
__device__ __forceinline__ float erfinv_xla(float x) {
    float w = -log1pf(-x * x), p;
    if (w < 5.0f) {
        w -= 2.5f;
        p = 2.81022636e-08f;
        p = fmaf(p, w, 3.43273939e-07f);  p = fmaf(p, w, -3.5233877e-06f);
        p = fmaf(p, w, -4.39150654e-06f); p = fmaf(p, w, 0.00021858087f);
        p = fmaf(p, w, -0.00125372503f);  p = fmaf(p, w, -0.00417768164f);
        p = fmaf(p, w, 0.246640727f);     p = fmaf(p, w, 1.50140941f);
    } else {
        w = sqrtf(w) - 3.0f;
        p = -0.000200214257f;
        p = fmaf(p, w, 0.000100950558f);  p = fmaf(p, w, 0.00134934322f);
        p = fmaf(p, w, -0.00367342844f);  p = fmaf(p, w, 0.00573950773f);
        p = fmaf(p, w, -0.0076224613f);   p = fmaf(p, w, 0.00943887047f);
        p = fmaf(p, w, 1.00167406f);      p = fmaf(p, w, 2.83297682f);
    }
    return p * x;
}
__device__ __forceinline__ float u01(uint32_t b) {
    return __uint_as_float((b >> 9) | 0x3f800000u) - 1.0f;
}
__device__ __forceinline__ float nrm(uint32_t b) {
    const float LO = -0.99999994f;
    float v = u01(b) * 2.0f + LO;
    v = fmaxf(LO, v);
    return 1.41421356f * erfinv_xla(v);
}
__device__ __forceinline__ float unif(uint32_t b) {
    const float MN = 1e-06f;
    float v = u01(b) * (0.999999f - MN) + MN;
    return fmaxf(MN, v);
}

__global__ void k_zero_init() {
    int i = blockIdx.x * blockDim.x + threadIdx.x;
    if (i < N_RELS * N_NODES) g_cnt[i] = 0;
    if (i < N_NODES) g_deg[i] = 0;
    if (i < 4) g_acc[i] = 0.0f;
}
__global__ void k_count(const int* __restrict__ ei, const int* __restrict__ et) {
    int e = blockIdx.x * blockDim.x + threadIdx.x;
    if (e >= N_EDGES) return;
    int d = ei[N_EDGES + e];
    atomicAdd(&g_cnt[et[e] * N_NODES + d], 1);
    atomicAdd(&g_deg[d], 1);
}
__global__ void k_scan() {
    __shared__ int part[1024];
    int tid = threadIdx.x;
    const int chunk = (N_NODES + 1023) / 1024;
    int lo = tid * chunk, hi = min(lo + chunk, N_NODES);
    int s = 0;
    for (int i = lo; i < hi; i++) s += g_deg[i];
    part[tid] = s;
    __syncthreads();
    for (int o = 1; o < 1024; o <<= 1) {
        int v = (tid >= o) ? part[tid - o] : 0;
        __syncthreads(); part[tid] += v; __syncthreads();
    }
    int run = part[tid] - s;
    for (int i = lo; i < hi; i++) { g_off[i] = run; g_cursor[i] = run; run += g_deg[i]; }
    if (tid == 1023) g_off[N_NODES] = run;
}
__global__ void k_scatter(const int* __restrict__ ei, const int* __restrict__ et) {
    int e = blockIdx.x * blockDim.x + threadIdx.x;
    if (e >= N_EDGES) return;
    int sn = ei[e], d = ei[N_EDGES + e], r = et[e];
    int p = atomicAdd(&g_cursor[d], 1);
    float inv = 1.0f / (float)g_cnt[r * N_NODES + d];
    g_epack[p] = make_uint2((uint32_t)(sn * GW + 256 + (r << 8)), __float_as_uint(inv));
}
__global__ void k_wsplitF(const float* __restrict__ Wroot, const float* __restrict__ Wr) {
    int idx = blockIdx.x * blockDim.x + threadIdx.x;
    if (idx >= N_LAYERS * GW * 256) return;
    int l = idx / (GW * 256), rem = idx % (GW * 256);
    int n = rem / 256, k = rem % 256;
    float v;
    if (n < 256) v = Wroot[((size_t)l * 256 + k) * 256 + n];
    else {
        int r = (n >> 8) - 1, h = n & 255;
        v = Wr[(((size_t)l * 4 + r) * 256 + k) * 256 + h];
    }
    g_Wfh[idx] = __float2half_rn(v);
}
__global__ void k_wsplitTF(const float* __restrict__ src, __half* __restrict__ h,
                           int N, int K) {
    int idx = blockIdx.x * blockDim.x + threadIdx.x;
    if (idx >= N * K) return;
    int n = idx / K, k = idx % K;
    h[idx] = __float2half_rn(src[(size_t)k * N + n]);
}
__global__ void k_wsplitT(const float* __restrict__ src, __nv_bfloat16* __restrict__ h,
                          __nv_bfloat16* __restrict__ l, int N, int K) {
    int idx = blockIdx.x * blockDim.x + threadIdx.x;
    if (idx >= N * K) return;
    int n = idx / K, k = idx % K;
    float v = src[(size_t)k * N + n];
    __nv_bfloat16 hi = __float2bfloat16(v);
    h[idx] = hi;
    l[idx] = __float2bfloat16(v - __bfloat162float(hi));
}
__global__ void k_tohalf(const float* __restrict__ src, __half* __restrict__ dst, int n) {
    int i = blockIdx.x * blockDim.x + threadIdx.x;
    if (i < n) dst[i] = __float2half_rn(src[i]);
}

__device__ __forceinline__ void ldm4(uint32_t a, uint32_t& r0, uint32_t& r1,
                                     uint32_t& r2, uint32_t& r3) {
    asm volatile("ldmatrix.sync.aligned.m8n8.x4.shared.b16 {%0,%1,%2,%3}, [%4];"
                 : "=r"(r0), "=r"(r1), "=r"(r2), "=r"(r3) : "r"(a));
}
__device__ __forceinline__ void mma_bf(float* c, const uint32_t* a, const uint32_t* b) {
    asm volatile("mma.sync.aligned.m16n8k16.row.col.f32.bf16.bf16.f32 "
                 "{%0,%1,%2,%3},{%4,%5,%6,%7},{%8,%9},{%0,%1,%2,%3};"
                 : "+f"(c[0]), "+f"(c[1]), "+f"(c[2]), "+f"(c[3])
                 : "r"(a[0]), "r"(a[1]), "r"(a[2]), "r"(a[3]), "r"(b[0]), "r"(b[1]));
}
__device__ __forceinline__ void mma_fp(float* c, const uint32_t* a, const uint32_t* b) {
    asm volatile("mma.sync.aligned.m16n8k16.row.col.f32.f16.f16.f32 "
                 "{%0,%1,%2,%3},{%4,%5,%6,%7},{%8,%9},{%0,%1,%2,%3};"
                 : "+f"(c[0]), "+f"(c[1]), "+f"(c[2]), "+f"(c[3])
                 : "r"(a[0]), "r"(a[1]), "r"(a[2]), "r"(a[3]), "r"(b[0]), "r"(b[1]));
}
__device__ __forceinline__ void cp16(uint32_t dst, const void* src) {
    asm volatile("cp.async.cg.shared.global [%0], [%1], 16;" :: "r"(dst), "l"(src));
}

// ===== fp16 1-term GEMM: A fp16, B fp16. BM=BN=128, BK=32, 3 stages, 2 CTA/SM =====
// stage: A 10240 B, B 10240 B; stride 20480
#define LOAD_STAGE_F(s, kq)                                            \
    do {                                                               \
        uint32_t st_ = smq + (s) * 20480;                              \
        _Pragma("unroll")                                              \
        for (int q_ = 0; q_ < 2; q_++) {                               \
            int col_ = (c0 + q_) * 8;                                  \
            uint32_t dd_ = st_ + (row * 40 + col_) * 2;                \
            cp16(dd_,         Agf + (kq) + col_);                      \
            cp16(dd_ + 10240, Bgh + (kq) + col_);                      \
        }                                                              \
    } while (0)

__global__ void __launch_bounds__(256, 2)
k_fmma(const __half* __restrict__ Af, const __half* __restrict__ Bh,
       const float* __restrict__ bias, float* __restrict__ C,
       __half* __restrict__ oF, int M, int N, int K, int relu_out) {
    extern __shared__ __align__(16) __half dsmf[];
    uint32_t smq = (uint32_t)__cvta_generic_to_shared(dsmf);
    int tid = threadIdx.x, lane = tid & 31, wid = tid >> 5;
    int wm = (wid >> 2) * 64, wn = (wid & 3) * 32;
    int bm = blockIdx.y * 128, bn = blockIdx.x * 128;
    int row = tid >> 1, c0 = (tid & 1) * 2;
    const __half* Agf = Af + (size_t)(bm + row) * K;
    const __half* Bgh = Bh + (size_t)(bn + row) * K;

    float acc[4][4][4];
#pragma unroll
    for (int i = 0; i < 4; i++)
#pragma unroll
        for (int j = 0; j < 4; j++)
#pragma unroll
            for (int q = 0; q < 4; q++) acc[i][j][q] = 0.f;

    LOAD_STAGE_F(0, 0);
    asm volatile("cp.async.commit_group;");
    if (32 < K) LOAD_STAGE_F(1, 32);
    asm volatile("cp.async.commit_group;");

    int cur = 0;
    for (int k0 = 0; k0 < K; k0 += 32) {
        int pre = k0 + 64;
        if (pre < K) {
            int s2 = cur + 2; if (s2 >= 3) s2 -= 3;
            LOAD_STAGE_F(s2, pre);
        }
        asm volatile("cp.async.commit_group;");
        asm volatile("cp.async.wait_group 2;");
        __syncthreads();
        uint32_t st = smq + cur * 20480;
#pragma unroll
        for (int kk = 0; kk < 32; kk += 16) {
            uint32_t bh[4][2];
            int brow = wn + (lane & 7) + ((lane >> 4) & 1) * 8;
            int bcol = kk + ((lane >> 3) & 1) * 8;
#pragma unroll
            for (int nb = 0; nb < 2; nb++) {
                uint32_t off = ((brow + nb * 16) * 40 + bcol) * 2;
                ldm4(st + 10240 + off, bh[2 * nb][0], bh[2 * nb][1], bh[2 * nb + 1][0], bh[2 * nb + 1][1]);
            }
            int arow = wm + (lane & 7) + ((lane >> 3) & 1) * 8;
            int acol = kk + ((lane >> 4) & 1) * 8;
#pragma unroll
            for (int mf = 0; mf < 4; mf++) {
                uint32_t a[4];
                uint32_t off = ((arow + mf * 16) * 40 + acol) * 2;
                ldm4(st + off, a[0], a[1], a[2], a[3]);
#pragma unroll
                for (int nf = 0; nf < 4; nf++)
                    mma_fp(acc[mf][nf], a, bh[nf]);
            }
        }
        __syncthreads();
        cur++; if (cur >= 3) cur = 0;
    }
#pragma unroll
    for (int mf = 0; mf < 4; mf++)
#pragma unroll
        for (int nf = 0; nf < 4; nf++) {
            int r0 = bm + wm + mf * 16 + (lane >> 2);
            int c0o = bn + wn + nf * 8 + (lane & 3) * 2;
#pragma unroll
            for (int h = 0; h < 2; h++) {
                int r = r0 + h * 8;
                if (r >= M) continue;
                float v0 = acc[mf][nf][2 * h], v1 = acc[mf][nf][2 * h + 1];
                if (bias) { v0 += bias[c0o]; v1 += bias[c0o + 1]; }
                if (relu_out) { v0 = fmaxf(v0, 0.f); v1 = fmaxf(v1, 0.f); }
                if (oF) {
                    *(__half2*)(oF + (size_t)r * N + c0o) = __floats2half2_rn(v0, v1);
                } else {
                    *(float2*)(C + (size_t)r * N + c0o) = make_float2(v0, v1);
                }
            }
        }
}

// ===== bf16 3-term GEMM for tail =====
#define LOAD_STAGE(s, kq)                                              \
    do {                                                               \
        uint32_t st_ = sm + (s) * 40960;                               \
        _Pragma("unroll")                                              \
        for (int q_ = 0; q_ < 2; q_++) {                               \
            int col_ = (c0 + q_) * 8;                                  \
            uint32_t dd_ = st_ + (row * 40 + col_) * 2;                \
            cp16(dd_,         Agh + (kq) + col_);                      \
            cp16(dd_ + 10240, Agl + (kq) + col_);                      \
            cp16(dd_ + 20480, Bgh + (kq) + col_);                      \
            cp16(dd_ + 30720, Bgl + (kq) + col_);                      \
        }                                                              \
    } while (0)

__global__ void __launch_bounds__(256, 1)
k_bmma(const __nv_bfloat16* __restrict__ Ah, const __nv_bfloat16* __restrict__ Al,
       const __nv_bfloat16* __restrict__ Bh, const __nv_bfloat16* __restrict__ Bl,
       const float* __restrict__ bias, float* __restrict__ C,
       int M, int N, int K, int relu_out) {
    extern __shared__ __align__(16) __nv_bfloat16 dsm[];
    uint32_t sm = (uint32_t)__cvta_generic_to_shared(dsm);
    int tid = threadIdx.x, lane = tid & 31, wid = tid >> 5;
    int wm = (wid >> 2) * 64, wn = (wid & 3) * 32;
    int bm = blockIdx.y * 128, bn = blockIdx.x * 128;
    int row = tid >> 1, c0 = (tid & 1) * 2;
    const __nv_bfloat16* Agh = Ah + (size_t)(bm + row) * K;
    const __nv_bfloat16* Agl = Al + (size_t)(bm + row) * K;
    const __nv_bfloat16* Bgh = Bh + (size_t)(bn + row) * K;
    const __nv_bfloat16* Bgl = Bl + (size_t)(bn + row) * K;

    float acc[4][4][4];
#pragma unroll
    for (int i = 0; i < 4; i++)
#pragma unroll
        for (int j = 0; j < 4; j++)
#pragma unroll
            for (int q = 0; q < 4; q++) acc[i][j][q] = 0.f;

    LOAD_STAGE(0, 0);
    asm volatile("cp.async.commit_group;");
    if (32 < K) LOAD_STAGE(1, 32);
    asm volatile("cp.async.commit_group;");

    int cur = 0;
    for (int k0 = 0; k0 < K; k0 += 32) {
        int pre = k0 + 64;
        if (pre < K) {
            int s2 = cur + 2; if (s2 >= 3) s2 -= 3;
            LOAD_STAGE(s2, pre);
        }
        asm volatile("cp.async.commit_group;");
        asm volatile("cp.async.wait_group 2;");
        __syncthreads();
        uint32_t st = sm + cur * 40960;
#pragma unroll
        for (int kk = 0; kk < 32; kk += 16) {
            uint32_t bh[4][2], bl[4][2];
            int brow = wn + (lane & 7) + ((lane >> 4) & 1) * 8;
            int bcol = kk + ((lane >> 3) & 1) * 8;
#pragma unroll
            for (int nb = 0; nb < 2; nb++) {
                uint32_t off = ((brow + nb * 16) * 40 + bcol) * 2;
                ldm4(st + 20480 + off, bh[2 * nb][0], bh[2 * nb][1], bh[2 * nb + 1][0], bh[2 * nb + 1][1]);
                ldm4(st + 30720 + off, bl[2 * nb][0], bl[2 * nb][1], bl[2 * nb + 1][0], bl[2 * nb + 1][1]);
            }
            int arow = wm + (lane & 7) + ((lane >> 3) & 1) * 8;
            int acol = kk + ((lane >> 4) & 1) * 8;
#pragma unroll
            for (int mf = 0; mf < 4; mf++) {
                uint32_t ah[4], al[4];
                uint32_t off = ((arow + mf * 16) * 40 + acol) * 2;
                ldm4(st + off, ah[0], ah[1], ah[2], ah[3]);
                ldm4(st + 10240 + off, al[0], al[1], al[2], al[3]);
#pragma unroll
                for (int nf = 0; nf < 4; nf++) {
                    mma_bf(acc[mf][nf], ah, bh[nf]);
                    mma_bf(acc[mf][nf], ah, bl[nf]);
                    mma_bf(acc[mf][nf], al, bh[nf]);
                }
            }
        }
        __syncthreads();
        cur++; if (cur >= 3) cur = 0;
    }
#pragma unroll
    for (int mf = 0; mf < 4; mf++)
#pragma unroll
        for (int nf = 0; nf < 4; nf++) {
            int r0 = bm + wm + mf * 16 + (lane >> 2);
            int c0o = bn + wn + nf * 8 + (lane & 3) * 2;
#pragma unroll
            for (int h = 0; h < 2; h++) {
                int r = r0 + h * 8;
                if (r >= M) continue;
                float v0 = acc[mf][nf][2 * h], v1 = acc[mf][nf][2 * h + 1];
                if (bias) { v0 += bias[c0o]; v1 += bias[c0o + 1]; }
                if (relu_out) { v0 = fmaxf(v0, 0.f); v1 = fmaxf(v1, 0.f); }
                *(float2*)(C + (size_t)r * N + c0o) = make_float2(v0, v1);
            }
        }
}

__device__ __forceinline__ void up4(uint2 v, float* f) {
    __half2* h = (__half2*)&v;
    float2 a0 = __half22float2(h[0]); f[0] = a0.x; f[1] = a0.y;
    float2 a1 = __half22float2(h[1]); f[2] = a1.x; f[3] = a1.y;
}

__global__ void k_agg(const float* __restrict__ bias, __half* __restrict__ ofh,
                      float* __restrict__ out32, int relu) {
    int gw = (blockIdx.x * blockDim.x + threadIdx.x) >> 5;
    int lane = threadIdx.x & 31;
    int d = gw >> 1;
    int half = gw & 1;
    if (d >= N_NODES) return;
    int cb = half * 128 + lane * 4;
    float acc[4];
    {
        uint2 base = *(const uint2*)(g_G + (size_t)d * GW + cb);
        up4(base, acc);
        float4 bb = *(const float4*)(bias + cb);
        acc[0] += bb.x; acc[1] += bb.y; acc[2] += bb.z; acc[3] += bb.w;
    }
    int s = g_off[d], e = g_off[d + 1];
    int i = s;
#define AGG_EDGE(P)                                                     \
    {                                                                   \
        uint2 gv = *(const uint2*)(g_G + (P).x + cb);                   \
        float inv = __uint_as_float((P).y);                             \
        float f[4]; up4(gv, f);                                         \
        acc[0] = fmaf(f[0], inv, acc[0]); acc[1] = fmaf(f[1], inv, acc[1]); \
        acc[2] = fmaf(f[2], inv, acc[2]); acc[3] = fmaf(f[3], inv, acc[3]); \
    }
    for (; i + 4 <= e; i += 4) {
        uint2 p0 = g_epack[i],     p1 = g_epack[i + 1];
        uint2 p2 = g_epack[i + 2], p3 = g_epack[i + 3];
        AGG_EDGE(p0) AGG_EDGE(p1) AGG_EDGE(p2) AGG_EDGE(p3)
    }
    for (; i < e; i++) {
        uint2 p0 = g_epack[i];
        AGG_EDGE(p0)
    }
#undef AGG_EDGE
    if (relu) {
#pragma unroll
        for (int j = 0; j < 4; j++) acc[j] = fmaxf(acc[j], 0.f);
        uint2 ov;
        __half2* oh = (__half2*)&ov;
        oh[0] = __floats2half2_rn(acc[0], acc[1]);
        oh[1] = __floats2half2_rn(acc[2], acc[3]);
        *(uint2*)(ofh + (size_t)d * DD + cb) = ov;
    } else {
        *(float4*)(out32 + (size_t)d * DD + cb) =
            make_float4(acc[0], acc[1], acc[2], acc[3]);
    }
}

__global__ void k_starts(const int* __restrict__ batch) {
    int m = blockIdx.x * blockDim.x + threadIdx.x;
    if (m > NUM_M) return;
    int lo = 0, hi = N_NODES;
    while (lo < hi) { int mid = (lo + hi) >> 1; if (batch[mid] < m) lo = mid + 1; else hi = mid; }
    g_start[m] = lo;
}
__global__ void k_copyHR(const float* __restrict__ HR) {
    int i = blockIdx.x * blockDim.x + threadIdx.x;
    if (i >= NUM_R * DD) return;
    float v = fmaxf(HR[i], 0.f);
    __nv_bfloat16 hi = __float2bfloat16(v);
    g_Hh[i] = hi;
    g_Hl[i] = __float2bfloat16(v - __bfloat162float(hi));
}
__global__ void k_gmean(const float* __restrict__ feats) {
    int m = blockIdx.x, c = threadIdx.x;
    int s = g_start[m], e = g_start[m + 1];
    float acc = 0.f;
    for (int n = s; n < e; n++) acc += feats[(size_t)n * DD + c];
    float v = fmaxf(acc / fmaxf((float)(e - s), 1.0f), 0.f);
    __nv_bfloat16 hi = __float2bfloat16(v);
    size_t idx = (size_t)(NUM_R + m) * DD + c;
    g_Hh[idx] = hi;
    g_Hl[idx] = __float2bfloat16(v - __bfloat162float(hi));
}

__global__ void k_sample_all(unsigned ku0, unsigned ku1, unsigned kzm0, unsigned kzm1,
                             unsigned kzr0, unsigned kzr1) {
    int i = blockIdx.x * blockDim.x + threadIdx.x;
    const int NU = N_ALL * DD, NZM = NUM_M * DD, NZR = NUM_R * DD;
    if (i < NU) {
        int row = i >> 8, col = i & 255;
        g_u[i] = g_pu[row * 512 + col] + expf(g_pu[row * 512 + 256 + col]) * nrm(rbits(ku0, ku1, i));
    } else if (i < NU + NZM) {
        int j = i - NU;
        int m = j >> 8, col = j & 255;
        int r = (NUM_R + m) * 512;
        g_zM[j] = g_qz[r + col] + expf(g_qz[r + 256 + col]) * nrm(rbits(kzm0, kzm1, j));
    } else if (i < NU + NZM + NZR) {
        int j = i - NU - NZM;
        int r = j >> 8, col = j & 255;
        g_zR[j] = g_qz[r * 512 + col] + expf(g_qz[r * 512 + 256 + col]) * nrm(rbits(kzr0, kzr1, j));
    }
}

__global__ void k_attn(const float* __restrict__ pg, const int* __restrict__ yM,
                       unsigned k0, unsigned k1) {
    int m = blockIdx.x, r = threadIdx.x;
    __shared__ float um[DD];
    __shared__ float d2s[NUM_R];
    __shared__ float red[NUM_R];
    for (int i = r; i < DD; i += 64) um[i] = g_u[(size_t)(NUM_R + m) * DD + i];
    __syncthreads();
    float d2 = 0.f;
    const float* ur = g_u + (size_t)r * DD;
    for (int dd = 0; dd < DD; dd++) {
        float t = um[dd] - ur[dd];
        d2 = fmaf(t, t, d2);
    }
    d2s[r] = d2;
    float logp = -0.5f * d2 / expf(pg[0]);
    float logit = logp - logf(fmaxf(-expm1f(logp), 1e-20f));
    float U = unif(rbits(k0, k1, (uint32_t)(m * NUM_R + r)));
    float gn = logf(U) - log1pf(-U);
    float A = 1.0f / (1.0f + expf(-(logit + gn) / 0.3f));
    red[r] = A;
    __syncthreads();
    for (int o = 32; o >= 1; o >>= 1) {
        if (r < o) red[r] += red[r + o];
        __syncthreads();
    }
    g_An[m * NUM_R + r] = A / (red[0] + 1e-8f);
    if (r < 32) {
        int idx = r + (1 - yM[m]) * 32;
        float t = sqrtf(fmaxf(d2s[idx], 1e-12f));
        for (int o = 16; o >= 1; o >>= 1) t += __shfl_down_sync(0xffffffffu, t, o);
        if (r == 0) atomicAdd(&g_acc[3], t);
    }
}

__global__ void k_pzq() {
    int m = blockIdx.x, c = threadIdx.x;
    __shared__ float an[NUM_R];
    if (c < NUM_R) an[c] = g_An[m * NUM_R + c];
    __syncthreads();
    float pm = 0.f, pl = 0.f;
    for (int r = 0; r < NUM_R; r++) {
        float a = an[r];
        pm = fmaf(a, g_qz[r * 512 + c], pm);
        pl = fmaf(a, g_qz[r * 512 + 256 + c], pl);
    }
    float z = g_zM[m * DD + c];
    float qm = g_qz[(NUM_R + m) * 512 + c], ql = g_qz[(NUM_R + m) * 512 + 256 + c];
    float t1 = (z - pm) * expf(-pl);
    float t2 = (z - qm) * expf(-ql);
    float v = (-pl - 0.5f * t1 * t1) - (-ql - 0.5f * t2 * t2);
    __shared__ float red[256];
    red[c] = v;
    __syncthreads();
    for (int o = 128; o >= 1; o >>= 1) {
        if (c < o) red[c] += red[c + o];
        __syncthreads();
    }
    if (c == 0) atomicAdd(&g_acc[1], red[0]);
}

__global__ void k_reps() {
    int i = blockIdx.x * blockDim.x + threadIdx.x;
    const int NM = NUM_M * 512;
    if (i < NM) {
        int m = i >> 9, c = i & 511;
        float v = (c < 256) ? g_zM[m * DD + c] : g_u[(size_t)(NUM_R + m) * DD + (c - 256)];
        __nv_bfloat16 hi = __float2bfloat16(v);
        g_repMh[i] = hi;
        g_repMl[i] = __float2bfloat16(v - __bfloat162float(hi));
    } else if (i < NM + NUM_R * 512) {
        int j = i - NM;
        int r = j >> 9, c = j & 511;
        float v = (c < 256) ? g_zR[r * DD + c] : g_u[(size_t)r * DD + (c - 256)];
        __nv_bfloat16 hi = __float2bfloat16(v);
        g_repRh[j] = hi;
        g_repRl[j] = __float2bfloat16(v - __bfloat162float(hi));
    }
}

__global__ void k_head(const float* __restrict__ hid, const float* __restrict__ W2,
                       const float* __restrict__ b2, const int* __restrict__ y,
                       int rows, int accIdx) {
    int gw = (blockIdx.x * blockDim.x + threadIdx.x) >> 5;
    int lane = threadIdx.x & 31;
    if (gw >= rows) return;
    float p0 = 0.f, p1 = 0.f;
#pragma unroll
    for (int j = 0; j < 8; j++) {
        int k = lane + 32 * j;
        float h = hid[(size_t)gw * 256 + k];
        p0 = fmaf(h, W2[k * 2], p0);
        p1 = fmaf(h, W2[k * 2 + 1], p1);
    }
    for (int o = 16; o >= 1; o >>= 1) {
        p0 += __shfl_down_sync(0xffffffffu, p0, o);
        p1 += __shfl_down_sync(0xffffffffu, p1, o);
    }
    if (lane == 0) {
        float l0 = p0 + b2[0], l1 = p1 + b2[1];
        float mx = fmaxf(l0, l1);
        float lse = mx + logf(expf(l0 - mx) + expf(l1 - mx));
        atomicAdd(&g_acc[accIdx], ((y[gw] != 0) ? l1 : l0) - lse);
    }
}

__global__ void k_final(float* __restrict__ out) {
    float pred = -(g_acc[0] + 0.1f * g_acc[1]) / 1024.0f;
    float rat  = -g_acc[2] / 64.0f;
    float reg  = g_acc[3] / 32768.0f;
    out[0] = pred + rat - 0.1f * reg;
}

extern "C" void kernel_launch(void* const* d_in, const int* in_sizes, int n_in,
                              void* d_out, int out_size) {
    (void)in_sizes; (void)n_in; (void)out_size;
    const float* x     = (const float*)d_in[0];
    const int*   ei    = (const int*)  d_in[1];
    const int*   et    = (const int*)  d_in[2];
    const int*   batch = (const int*)  d_in[3];
    const int*   yM    = (const int*)  d_in[4];
    const int*   yR    = (const int*)  d_in[5];
    const float* HR    = (const float*)d_in[6];
    const float* nodeW = (const float*)d_in[7];
    const float* nodeB = (const float*)d_in[8];
    const float* Wr    = (const float*)d_in[9];
    const float* Wroot = (const float*)d_in[10];
    const float* gcnB  = (const float*)d_in[11];
    const float* pg    = (const float*)d_in[12];
    const float* puW   = (const float*)d_in[13];
    const float* puB   = (const float*)d_in[14];
    const float* qzW   = (const float*)d_in[15];
    const float* qzB   = (const float*)d_in[16];
    const float* W1    = (const float*)d_in[17];
    const float* b1    = (const float*)d_in[18];
    const float* W2    = (const float*)d_in[19];
    const float* b2    = (const float*)d_in[20];
    float* out = (float*)d_out;

    uint32_t ku0, ku1, ka0, ka1, kzm0, kzm1, kzr0, kzr1;
    tf2x32(0u, 42u, 0u, 0u, ku0, ku1);
    tf2x32(0u, 42u, 0u, 1u, ka0, ka1);
    tf2x32(0u, 42u, 0u, 2u, kzm0, kzm1);
    tf2x32(0u, 42u, 0u, 3u, kzr0, kzr1);

    void* p;
    cudaGetSymbolAddress(&p, g_featsB); float* featsB = (float*)p;
    cudaGetSymbolAddress(&p, g_G);      __half* G    = (__half*)p;
    cudaGetSymbolAddress(&p, g_Wfh);    __half* Wfh = (__half*)p;
    cudaGetSymbolAddress(&p, g_nWfh);   __half* nWfh = (__half*)p;
    cudaGetSymbolAddress(&p, g_xf);     __half* xf = (__half*)p;
    cudaGetSymbolAddress(&p, g_Af);     __half* Af = (__half*)p;
    cudaGetSymbolAddress(&p, g_puWh);   __nv_bfloat16* puWh = (__nv_bfloat16*)p;
    cudaGetSymbolAddress(&p, g_puWl);   __nv_bfloat16* puWl = (__nv_bfloat16*)p;
    cudaGetSymbolAddress(&p, g_qzWh);   __nv_bfloat16* qzWh = (__nv_bfloat16*)p;
    cudaGetSymbolAddress(&p, g_qzWl);   __nv_bfloat16* qzWl = (__nv_bfloat16*)p;
    cudaGetSymbolAddress(&p, g_w1h);    __nv_bfloat16* w1h = (__nv_bfloat16*)p;
    cudaGetSymbolAddress(&p, g_w1l);    __nv_bfloat16* w1l = (__nv_bfloat16*)p;
    cudaGetSymbolAddress(&p, g_Hh);     __nv_bfloat16* Hh  = (__nv_bfloat16*)p;
    cudaGetSymbolAddress(&p, g_Hl);     __nv_bfloat16* Hl  = (__nv_bfloat16*)p;
    cudaGetSymbolAddress(&p, g_repMh);  __nv_bfloat16* repMh = (__nv_bfloat16*)p;
    cudaGetSymbolAddress(&p, g_repMl);  __nv_bfloat16* repMl = (__nv_bfloat16*)p;
    cudaGetSymbolAddress(&p, g_repRh);  __nv_bfloat16* repRh = (__nv_bfloat16*)p;
    cudaGetSymbolAddress(&p, g_repRl);  __nv_bfloat16* repRl = (__nv_bfloat16*)p;
    cudaGetSymbolAddress(&p, g_pu);     float* pu     = (float*)p;
    cudaGetSymbolAddress(&p, g_qz);     float* qz     = (float*)p;
    cudaGetSymbolAddress(&p, g_hidM);   float* hidM   = (float*)p;
    cudaGetSymbolAddress(&p, g_hidR);   float* hidR   = (float*)p;

    static int smem_set = 0;
    if (!smem_set) {
        cudaFuncSetAttribute(k_fmma, cudaFuncAttributeMaxDynamicSharedMemorySize, 61440);
        cudaFuncSetAttribute(k_bmma, cudaFuncAttributeMaxDynamicSharedMemorySize, 122880);
        smem_set = 1;
    }

    k_zero_init<<<(N_RELS * N_NODES + 255) / 256, 256>>>();
    k_count<<<(N_EDGES + 255) / 256, 256>>>(ei, et);
    k_scan<<<1, 1024>>>();
    k_scatter<<<(N_EDGES + 255) / 256, 256>>>(ei, et);
    k_wsplitF<<<(N_LAYERS * GW * 256 + 255) / 256, 256>>>(Wroot, Wr);
    k_wsplitTF<<<(256 * D_IN + 255) / 256, 256>>>(nodeW, nWfh, 256, D_IN);
    k_wsplitT<<<(512 * 256 + 255) / 256, 256>>>(puW, puWh, puWl, 512, 256);
    k_wsplitT<<<(512 * 256 + 255) / 256, 256>>>(qzW, qzWh, qzWl, 512, 256);
    k_wsplitT<<<(256 * 512 + 255) / 256, 256>>>(W1, w1h, w1l, 256, 512);
    k_tohalf<<<(N_NODES * D_IN + 255) / 256, 256>>>(x, xf, N_NODES * D_IN);

    k_fmma<<<dim3(2, (N_NODES + 127) / 128), 256, 61440>>>(
        xf, nWfh, nodeB, nullptr, Af, N_NODES, 256, D_IN, 0);

    for (int l = 0; l < N_LAYERS; l++) {
        k_fmma<<<dim3(GW / 128, (N_NODES + 127) / 128), 256, 61440>>>(
            Af, Wfh + (size_t)l * GW * 256, nullptr, nullptr, G, N_NODES, GW, 256, 0);
        k_agg<<<(N_NODES * 2 * 32 + 255) / 256, 256>>>(
            gcnB + l * 256, Af, featsB, (l < N_LAYERS - 1) ? 1 : 0);
    }

    k_starts<<<(NUM_M + 256) / 256, 256>>>(batch);
    k_copyHR<<<(NUM_R * DD + 255) / 256, 256>>>(HR);
    k_gmean<<<NUM_M, 256>>>(featsB);

    k_bmma<<<dim3(4, HPAD / 128), 256, 122880>>>(
        Hh, Hl, puWh, puWl, puB, pu, N_ALL, 512, 256, 0);
    k_bmma<<<dim3(4, HPAD / 128), 256, 122880>>>(
        Hh, Hl, qzWh, qzWl, qzB, qz, N_ALL, 512, 256, 0);

    k_sample_all<<<((N_ALL + NUM_M + NUM_R) * DD + 255) / 256, 256>>>(
        ku0, ku1, kzm0, kzm1, kzr0, kzr1);

    k_attn<<<NUM_M, 64>>>(pg, yM, ka0, ka1);
    k_pzq<<<NUM_M, 256>>>();

    k_reps<<<((NUM_M + NUM_R) * 512 + 255) / 256, 256>>>();
    k_bmma<<<dim3(2, NUM_M / 128), 256, 122880>>>(
        repMh, repMl, w1h, w1l, b1, hidM, NUM_M, 256, 512, 1);
    k_bmma<<<dim3(2, 1), 256, 122880>>>(
        repRh, repRl, w1h, w1l, b1, hidR, NUM_R, 256, 512, 1);
    k_head<<<(NUM_M * 32 + 255) / 256, 256>>>(hidM, W2, b2, yM, NUM_M, 0);
    k_head<<<(NUM_R * 32 + 255) / 256, 256>>>(hidR, W2, b2, yR, NUM_R, 2);

    k_final<<<1, 1>>>(out);
}

// round 13
// speedup vs baseline: 2.4491x; 1.0575x over previous
#include <cuda_runtime.h>
#include <cuda_bf16.h>
#include <cuda_fp16.h>
#include <stdint.h>
#include <math.h>

#define N_NODES 50000
#define N_EDGES 200000
#define D_IN    128
#define DD      256
#define N_LAYERS 4
#define N_RELS  4
#define NUM_M   1024
#define NUM_R   64
#define N_ALL   (NUM_R + NUM_M)
#define GW      1280
#define MPAD    (N_NODES + 128)
#define HPAD    1152

__device__ __half g_G[(size_t)N_NODES * GW];
__device__ __half g_Wfh[N_LAYERS * GW * 256];
__device__ __half g_nWfh[256 * D_IN];
__device__ __half g_xf[(size_t)MPAD * D_IN];
__device__ __half g_Af[(size_t)MPAD * DD];
__device__ __nv_bfloat16 g_pqWh[1024 * 256];
__device__ __nv_bfloat16 g_pqWl[1024 * 256];
__device__ __nv_bfloat16 g_w1h[256 * 512];
__device__ __nv_bfloat16 g_w1l[256 * 512];
__device__ __nv_bfloat16 g_Hh[HPAD * DD];
__device__ __nv_bfloat16 g_Hl[HPAD * DD];
__device__ __nv_bfloat16 g_reph[HPAD * 512];
__device__ __nv_bfloat16 g_repl[HPAD * 512];
__device__ float g_bcat[1024];
__device__ int   g_cnt[N_RELS * N_NODES];
__device__ int   g_deg[N_NODES];
__device__ int   g_off[N_NODES + 1];
__device__ int   g_cursor[N_NODES];
__device__ uint2 g_epack[N_EDGES];
__device__ int   g_start[NUM_M + 1];
__device__ float g_puqz[N_ALL * 1024];
__device__ float g_u[N_ALL * DD];
__device__ float g_zM[NUM_M * DD];
__device__ float g_zR[NUM_R * DD];
__device__ float g_An[NUM_M * NUM_R];
__device__ float g_hid[HPAD * 256];
__device__ float g_acc[4];

__host__ __device__ __forceinline__ uint32_t rotl32(uint32_t x, int d) {
    return (x << d) | (x >> (32 - d));
}
__host__ __device__ __forceinline__ void tf2x32(uint32_t k0, uint32_t k1,
                                                uint32_t x0, uint32_t x1,
                                                uint32_t& o0, uint32_t& o1) {
    uint32_t ks2 = k0 ^ k1 ^ 0x1BD11BDAu;
    x0 += k0; x1 += k1;
#define TF_RND(R) { x0 += x1; x1 = rotl32(x1, R); x1 ^= x0; }
    TF_RND(13) TF_RND(15) TF_RND(26) TF_RND(6)
    x0 += k1;  x1 += ks2 + 1u;
    TF_RND(17) TF_RND(29) TF_RND(16) TF_RND(24)
    x0 += ks2; x1 += k0 + 2u;
    TF_RND(13) TF_RND(15) TF_RND(26) TF_RND(6)
    x0 += k0;  x1 += k1 + 3u;
    TF_RND(17) TF_RND(29) TF_RND(16) TF_RND(24)
    x0 += k1;  x1 += ks2 + 4u;
    TF_RND(13) TF_RND(15) TF_RND(26) TF_RND(6)
    x0 += ks2; x1 += k0 + 5u;
#undef TF_RND
    o0 = x0; o1 = x1;
}
__device__ __forceinline__ uint32_t rbits(uint32_t k0, uint32_t k1, uint32_t i) {
    uint32_t o0, o1; tf2x32(k0, k1, 0u, i, o0, o1); return o0 ^ o1;
}
__device__ __forceinline__ float erfinv_xla(float x) {
    float w = -log1pf(-x * x), p;
    if (w < 5.0f) {
        w -= 2.5f;
        p = 2.81022636e-08f;
        p = fmaf(p, w, 3.43273939e-07f);  p = fmaf(p, w, -3.5233877e-06f);
        p = fmaf(p, w, -4.39150654e-06f); p = fmaf(p, w, 0.00021858087f);
        p = fmaf(p, w, -0.00125372503f);  p = fmaf(p, w, -0.00417768164f);
        p = fmaf(p, w, 0.246640727f);     p = fmaf(p, w, 1.50140941f);
    } else {
        w = sqrtf(w) - 3.0f;
        p = -0.000200214257f;
        p = fmaf(p, w, 0.000100950558f);  p = fmaf(p, w, 0.00134934322f);
        p = fmaf(p, w, -0.00367342844f);  p = fmaf(p, w, 0.00573950773f);
        p = fmaf(p, w, -0.0076224613f);   p = fmaf(p, w, 0.00943887047f);
        p = fmaf(p, w, 1.00167406f);      p = fmaf(p, w, 2.83297682f);
    }
    return p * x;
}
__device__ __forceinline__ float u01(uint32_t b) {
    return __uint_as_float((b >> 9) | 0x3f800000u) - 1.0f;
}
__device__ __forceinline__ float nrm(uint32_t b) {
    const float LO = -0.99999994f;
    float v = u01(b) * 2.0f + LO;
    v = fmaxf(LO, v);
    return 1.41421356f * erfinv_xla(v);
}
__device__ __forceinline__ float unif(uint32_t b) {
    const float MN = 1e-06f;
    float v = u01(b) * (0.999999f - MN) + MN;
    return fmaxf(MN, v);
}

__global__ void k_zero_init() {
    int i = blockIdx.x * blockDim.x + threadIdx.x;
    if (i < N_RELS * N_NODES) g_cnt[i] = 0;
    if (i < N_NODES) g_deg[i] = 0;
    if (i < 4) g_acc[i] = 0.0f;
}
__global__ void k_count(const int* __restrict__ ei, const int* __restrict__ et) {
    int e = blockIdx.x * blockDim.x + threadIdx.x;
    if (e >= N_EDGES) return;
    int d = ei[N_EDGES + e];
    atomicAdd(&g_cnt[et[e] * N_NODES + d], 1);
    atomicAdd(&g_deg[d], 1);
}
__global__ void k_scan() {
    __shared__ int part[1024];
    int tid = threadIdx.x;
    const int chunk = (N_NODES + 1023) / 1024;
    int lo = tid * chunk, hi = min(lo + chunk, N_NODES);
    int s = 0;
    for (int i = lo; i < hi; i++) s += g_deg[i];
    part[tid] = s;
    __syncthreads();
    for (int o = 1; o < 1024; o <<= 1) {
        int v = (tid >= o) ? part[tid - o] : 0;
        __syncthreads(); part[tid] += v; __syncthreads();
    }
    int run = part[tid] - s;
    for (int i = lo; i < hi; i++) { g_off[i] = run; g_cursor[i] = run; run += g_deg[i]; }
    if (tid == 1023) g_off[N_NODES] = run;
}
__global__ void k_scatter(const int* __restrict__ ei, const int* __restrict__ et) {
    int e = blockIdx.x * blockDim.x + threadIdx.x;
    if (e >= N_EDGES) return;
    int sn = ei[e], d = ei[N_EDGES + e], r = et[e];
    int p = atomicAdd(&g_cursor[d], 1);
    float inv = 1.0f / (float)g_cnt[r * N_NODES + d];
    g_epack[p] = make_uint2((uint32_t)(sn * GW + 256 + (r << 8)), __float_as_uint(inv));
}

// fused weight/activation prep
__global__ void k_prep(const float* __restrict__ x, const float* __restrict__ nodeW,
                       const float* __restrict__ Wroot, const float* __restrict__ Wr,
                       const float* __restrict__ puW, const float* __restrict__ qzW,
                       const float* __restrict__ W1, const float* __restrict__ puB,
                       const float* __restrict__ qzB) {
    const int nF = N_NODES * D_IN;                  // x -> fp16
    const int nA = N_LAYERS * GW * 256;             // layer weights
    const int nB = 256 * D_IN;                      // node encoder W
    const int nC = 1024 * 256;                      // pu|qz stacked
    const int nE = 256 * 512;                       // W1
    int i = blockIdx.x * blockDim.x + threadIdx.x;
    if (i < nF) {
        g_xf[i] = __float2half_rn(x[i]);
        return;
    }
    i -= nF;
    if (i < nA) {
        int l = i / (GW * 256), rem = i % (GW * 256);
        int n = rem / 256, k = rem % 256;
        float v;
        if (n < 256) v = Wroot[((size_t)l * 256 + k) * 256 + n];
        else {
            int r = (n >> 8) - 1, h = n & 255;
            v = Wr[(((size_t)l * 4 + r) * 256 + k) * 256 + h];
        }
        g_Wfh[i] = __float2half_rn(v);
        return;
    }
    i -= nA;
    if (i < nB) {
        int n = i / D_IN, k = i % D_IN;
        g_nWfh[i] = __float2half_rn(nodeW[(size_t)k * 256 + n]);
        return;
    }
    i -= nB;
    if (i < nC) {
        int n = i / 256, k = i % 256;
        float v = (n < 512) ? puW[(size_t)k * 512 + n] : qzW[(size_t)k * 512 + (n - 512)];
        __nv_bfloat16 hi = __float2bfloat16(v);
        g_pqWh[i] = hi;
        g_pqWl[i] = __float2bfloat16(v - __bfloat162float(hi));
        return;
    }
    i -= nC;
    if (i < nE) {
        int n = i / 512, k = i % 512;
        float v = W1[(size_t)k * 256 + n];
        __nv_bfloat16 hi = __float2bfloat16(v);
        g_w1h[i] = hi;
        g_w1l[i] = __float2bfloat16(v - __bfloat162float(hi));
        return;
    }
    i -= nE;
    if (i < 1024) g_bcat[i] = (i < 512) ? puB[i] : qzB[i - 512];
}

__device__ __forceinline__ void ldm4(uint32_t a, uint32_t& r0, uint32_t& r1,
                                     uint32_t& r2, uint32_t& r3) {
    asm volatile("ldmatrix.sync.aligned.m8n8.x4.shared.b16 {%0,%1,%2,%3}, [%4];"
                 : "=r"(r0), "=r"(r1), "=r"(r2), "=r"(r3) : "r"(a));
}
__device__ __forceinline__ void mma_bf(float* c, const uint32_t* a, const uint32_t* b) {
    asm volatile("mma.sync.aligned.m16n8k16.row.col.f32.bf16.bf16.f32 "
                 "{%0,%1,%2,%3},{%4,%5,%6,%7},{%8,%9},{%0,%1,%2,%3};"
                 : "+f"(c[0]), "+f"(c[1]), "+f"(c[2]), "+f"(c[3])
                 : "r"(a[0]), "r"(a[1]), "r"(a[2]), "r"(a[3]), "r"(b[0]), "r"(b[1]));
}
__device__ __forceinline__ void mma_fp(float* c, const uint32_t* a, const uint32_t* b) {
    asm volatile("mma.sync.aligned.m16n8k16.row.col.f32.f16.f16.f32 "
                 "{%0,%1,%2,%3},{%4,%5,%6,%7},{%8,%9},{%0,%1,%2,%3};"
                 : "+f"(c[0]), "+f"(c[1]), "+f"(c[2]), "+f"(c[3])
                 : "r"(a[0]), "r"(a[1]), "r"(a[2]), "r"(a[3]), "r"(b[0]), "r"(b[1]));
}
__device__ __forceinline__ void cp16(uint32_t dst, const void* src) {
    asm volatile("cp.async.cg.shared.global [%0], [%1], 16;" :: "r"(dst), "l"(src));
}

// ===== fp16 1-term GEMM, BM=BN=128, BK=32, 3 stages, 2 CTA/SM =====
#define LOAD_STAGE_F(s, kq)                                            \
    do {                                                               \
        uint32_t st_ = smq + (s) * 20480;                              \
        _Pragma("unroll")                                              \
        for (int q_ = 0; q_ < 2; q_++) {                               \
            int col_ = (c0 + q_) * 8;                                  \
            uint32_t dd_ = st_ + (row * 40 + col_) * 2;                \
            cp16(dd_,         Agf + (kq) + col_);                      \
            cp16(dd_ + 10240, Bgh + (kq) + col_);                      \
        }                                                              \
    } while (0)

__global__ void __launch_bounds__(256, 2)
k_fmma(const __half* __restrict__ Af, const __half* __restrict__ Bh,
       const float* __restrict__ bias, float* __restrict__ C,
       __half* __restrict__ oF, int M, int N, int K, int relu_out) {
    extern __shared__ __align__(16) __half dsmf[];
    uint32_t smq = (uint32_t)__cvta_generic_to_shared(dsmf);
    int tid = threadIdx.x, lane = tid & 31, wid = tid >> 5;
    int wm = (wid >> 2) * 64, wn = (wid & 3) * 32;
    int bm = blockIdx.y * 128, bn = blockIdx.x * 128;
    int row = tid >> 1, c0 = (tid & 1) * 2;
    const __half* Agf = Af + (size_t)(bm + row) * K;
    const __half* Bgh = Bh + (size_t)(bn + row) * K;

    float acc[4][4][4];
#pragma unroll
    for (int i = 0; i < 4; i++)
#pragma unroll
        for (int j = 0; j < 4; j++)
#pragma unroll
            for (int q = 0; q < 4; q++) acc[i][j][q] = 0.f;

    LOAD_STAGE_F(0, 0);
    asm volatile("cp.async.commit_group;");
    if (32 < K) LOAD_STAGE_F(1, 32);
    asm volatile("cp.async.commit_group;");

    int cur = 0;
    for (int k0 = 0; k0 < K; k0 += 32) {
        int pre = k0 + 64;
        if (pre < K) {
            int s2 = cur + 2; if (s2 >= 3) s2 -= 3;
            LOAD_STAGE_F(s2, pre);
        }
        asm volatile("cp.async.commit_group;");
        asm volatile("cp.async.wait_group 2;");
        __syncthreads();
        uint32_t st = smq + cur * 20480;
#pragma unroll
        for (int kk = 0; kk < 32; kk += 16) {
            uint32_t bh[4][2];
            int brow = wn + (lane & 7) + ((lane >> 4) & 1) * 8;
            int bcol = kk + ((lane >> 3) & 1) * 8;
#pragma unroll
            for (int nb = 0; nb < 2; nb++) {
                uint32_t off = ((brow + nb * 16) * 40 + bcol) * 2;
                ldm4(st + 10240 + off, bh[2 * nb][0], bh[2 * nb][1], bh[2 * nb + 1][0], bh[2 * nb + 1][1]);
            }
            int arow = wm + (lane & 7) + ((lane >> 3) & 1) * 8;
            int acol = kk + ((lane >> 4) & 1) * 8;
#pragma unroll
            for (int mf = 0; mf < 4; mf++) {
                uint32_t a[4];
                uint32_t off = ((arow + mf * 16) * 40 + acol) * 2;
                ldm4(st + off, a[0], a[1], a[2], a[3]);
#pragma unroll
                for (int nf = 0; nf < 4; nf++)
                    mma_fp(acc[mf][nf], a, bh[nf]);
            }
        }
        __syncthreads();
        cur++; if (cur >= 3) cur = 0;
    }
#pragma unroll
    for (int mf = 0; mf < 4; mf++)
#pragma unroll
        for (int nf = 0; nf < 4; nf++) {
            int r0 = bm + wm + mf * 16 + (lane >> 2);
            int c0o = bn + wn + nf * 8 + (lane & 3) * 2;
#pragma unroll
            for (int h = 0; h < 2; h++) {
                int r = r0 + h * 8;
                if (r >= M) continue;
                float v0 = acc[mf][nf][2 * h], v1 = acc[mf][nf][2 * h + 1];
                if (bias) { v0 += bias[c0o]; v1 += bias[c0o + 1]; }
                if (relu_out) { v0 = fmaxf(v0, 0.f); v1 = fmaxf(v1, 0.f); }
                if (oF) {
                    *(__half2*)(oF + (size_t)r * N + c0o) = __floats2half2_rn(v0, v1);
                } else {
                    *(float2*)(C + (size_t)r * N + c0o) = make_float2(v0, v1);
                }
            }
        }
}

// ===== bf16 3-term GEMM for tail =====
#define LOAD_STAGE(s, kq)                                              \
    do {                                                               \
        uint32_t st_ = sm + (s) * 40960;                               \
        _Pragma("unroll")                                              \
        for (int q_ = 0; q_ < 2; q_++) {                               \
            int col_ = (c0 + q_) * 8;                                  \
            uint32_t dd_ = st_ + (row * 40 + col_) * 2;                \
            cp16(dd_,         Agh + (kq) + col_);                      \
            cp16(dd_ + 10240, Agl + (kq) + col_);                      \
            cp16(dd_ + 20480, Bgh + (kq) + col_);                      \
            cp16(dd_ + 30720, Bgl + (kq) + col_);                      \
        }                                                              \
    } while (0)

__global__ void __launch_bounds__(256, 1)
k_bmma(const __nv_bfloat16* __restrict__ Ah, const __nv_bfloat16* __restrict__ Al,
       const __nv_bfloat16* __restrict__ Bh, const __nv_bfloat16* __restrict__ Bl,
       const float* __restrict__ bias, float* __restrict__ C,
       int M, int N, int K, int relu_out) {
    extern __shared__ __align__(16) __nv_bfloat16 dsm[];
    uint32_t sm = (uint32_t)__cvta_generic_to_shared(dsm);
    int tid = threadIdx.x, lane = tid & 31, wid = tid >> 5;
    int wm = (wid >> 2) * 64, wn = (wid & 3) * 32;
    int bm = blockIdx.y * 128, bn = blockIdx.x * 128;
    int row = tid >> 1, c0 = (tid & 1) * 2;
    const __nv_bfloat16* Agh = Ah + (size_t)(bm + row) * K;
    const __nv_bfloat16* Agl = Al + (size_t)(bm + row) * K;
    const __nv_bfloat16* Bgh = Bh + (size_t)(bn + row) * K;
    const __nv_bfloat16* Bgl = Bl + (size_t)(bn + row) * K;

    float acc[4][4][4];
#pragma unroll
    for (int i = 0; i < 4; i++)
#pragma unroll
        for (int j = 0; j < 4; j++)
#pragma unroll
            for (int q = 0; q < 4; q++) acc[i][j][q] = 0.f;

    LOAD_STAGE(0, 0);
    asm volatile("cp.async.commit_group;");
    if (32 < K) LOAD_STAGE(1, 32);
    asm volatile("cp.async.commit_group;");

    int cur = 0;
    for (int k0 = 0; k0 < K; k0 += 32) {
        int pre = k0 + 64;
        if (pre < K) {
            int s2 = cur + 2; if (s2 >= 3) s2 -= 3;
            LOAD_STAGE(s2, pre);
        }
        asm volatile("cp.async.commit_group;");
        asm volatile("cp.async.wait_group 2;");
        __syncthreads();
        uint32_t st = sm + cur * 40960;
#pragma unroll
        for (int kk = 0; kk < 32; kk += 16) {
            uint32_t bh[4][2], bl[4][2];
            int brow = wn + (lane & 7) + ((lane >> 4) & 1) * 8;
            int bcol = kk + ((lane >> 3) & 1) * 8;
#pragma unroll
            for (int nb = 0; nb < 2; nb++) {
                uint32_t off = ((brow + nb * 16) * 40 + bcol) * 2;
                ldm4(st + 20480 + off, bh[2 * nb][0], bh[2 * nb][1], bh[2 * nb + 1][0], bh[2 * nb + 1][1]);
                ldm4(st + 30720 + off, bl[2 * nb][0], bl[2 * nb][1], bl[2 * nb + 1][0], bl[2 * nb + 1][1]);
            }
            int arow = wm + (lane & 7) + ((lane >> 3) & 1) * 8;
            int acol = kk + ((lane >> 4) & 1) * 8;
#pragma unroll
            for (int mf = 0; mf < 4; mf++) {
                uint32_t ah[4], al[4];
                uint32_t off = ((arow + mf * 16) * 40 + acol) * 2;
                ldm4(st + off, ah[0], ah[1], ah[2], ah[3]);
                ldm4(st + 10240 + off, al[0], al[1], al[2], al[3]);
#pragma unroll
                for (int nf = 0; nf < 4; nf++) {
                    mma_bf(acc[mf][nf], ah, bh[nf]);
                    mma_bf(acc[mf][nf], ah, bl[nf]);
                    mma_bf(acc[mf][nf], al, bh[nf]);
                }
            }
        }
        __syncthreads();
        cur++; if (cur >= 3) cur = 0;
    }
#pragma unroll
    for (int mf = 0; mf < 4; mf++)
#pragma unroll
        for (int nf = 0; nf < 4; nf++) {
            int r0 = bm + wm + mf * 16 + (lane >> 2);
            int c0o = bn + wn + nf * 8 + (lane & 3) * 2;
#pragma unroll
            for (int h = 0; h < 2; h++) {
                int r = r0 + h * 8;
                if (r >= M) continue;
                float v0 = acc[mf][nf][2 * h], v1 = acc[mf][nf][2 * h + 1];
                if (bias) { v0 += bias[c0o]; v1 += bias[c0o + 1]; }
                if (relu_out) { v0 = fmaxf(v0, 0.f); v1 = fmaxf(v1, 0.f); }
                *(float2*)(C + (size_t)r * N + c0o) = make_float2(v0, v1);
            }
        }
}

__device__ __forceinline__ void up4(uint2 v, float* f) {
    __half2* h = (__half2*)&v;
    float2 a0 = __half22float2(h[0]); f[0] = a0.x; f[1] = a0.y;
    float2 a1 = __half22float2(h[1]); f[2] = a1.x; f[3] = a1.y;
}

// aggregation over fp16 G, 2 warps per node; always writes fp16
__global__ void k_agg(const float* __restrict__ bias, __half* __restrict__ ofh, int relu) {
    int gw = (blockIdx.x * blockDim.x + threadIdx.x) >> 5;
    int lane = threadIdx.x & 31;
    int d = gw >> 1;
    int half = gw & 1;
    if (d >= N_NODES) return;
    int cb = half * 128 + lane * 4;
    float acc[4];
    {
        uint2 base = *(const uint2*)(g_G + (size_t)d * GW + cb);
        up4(base, acc);
        float4 bb = *(const float4*)(bias + cb);
        acc[0] += bb.x; acc[1] += bb.y; acc[2] += bb.z; acc[3] += bb.w;
    }
    int s = g_off[d], e = g_off[d + 1];
    int i = s;
#define AGG_EDGE(P)                                                     \
    {                                                                   \
        uint2 gv = *(const uint2*)(g_G + (P).x + cb);                   \
        float inv = __uint_as_float((P).y);                             \
        float f[4]; up4(gv, f);                                         \
        acc[0] = fmaf(f[0], inv, acc[0]); acc[1] = fmaf(f[1], inv, acc[1]); \
        acc[2] = fmaf(f[2], inv, acc[2]); acc[3] = fmaf(f[3], inv, acc[3]); \
    }
    for (; i + 8 <= e; i += 8) {
        uint2 p0 = g_epack[i],     p1 = g_epack[i + 1];
        uint2 p2 = g_epack[i + 2], p3 = g_epack[i + 3];
        uint2 p4 = g_epack[i + 4], p5 = g_epack[i + 5];
        uint2 p6 = g_epack[i + 6], p7 = g_epack[i + 7];
        AGG_EDGE(p0) AGG_EDGE(p1) AGG_EDGE(p2) AGG_EDGE(p3)
        AGG_EDGE(p4) AGG_EDGE(p5) AGG_EDGE(p6) AGG_EDGE(p7)
    }
    for (; i < e; i++) {
        uint2 p0 = g_epack[i];
        AGG_EDGE(p0)
    }
#undef AGG_EDGE
    if (relu) {
#pragma unroll
        for (int j = 0; j < 4; j++) acc[j] = fmaxf(acc[j], 0.f);
    }
    uint2 ov;
    __half2* oh = (__half2*)&ov;
    oh[0] = __floats2half2_rn(acc[0], acc[1]);
    oh[1] = __floats2half2_rn(acc[2], acc[3]);
    *(uint2*)(ofh + (size_t)d * DD + cb) = ov;
}

// starts + copyHR fused
__global__ void k_misc(const int* __restrict__ batch, const float* __restrict__ HR) {
    int i = blockIdx.x * blockDim.x + threadIdx.x;
    if (i <= NUM_M) {
        int lo = 0, hi = N_NODES;
        while (lo < hi) { int mid = (lo + hi) >> 1; if (batch[mid] < i) lo = mid + 1; else hi = mid; }
        g_start[i] = lo;
    }
    int j = i - (NUM_M + 1);
    if (j >= 0 && j < NUM_R * DD) {
        float v = fmaxf(HR[j], 0.f);
        __nv_bfloat16 hi = __float2bfloat16(v);
        g_Hh[j] = hi;
        g_Hl[j] = __float2bfloat16(v - __bfloat162float(hi));
    }
}
__global__ void k_gmean() {
    int m = blockIdx.x, c = threadIdx.x;
    int s = g_start[m], e = g_start[m + 1];
    float acc = 0.f;
    for (int n = s; n < e; n++) acc += __half2float(g_Af[(size_t)n * DD + c]);
    float v = fmaxf(acc / fmaxf((float)(e - s), 1.0f), 0.f);
    __nv_bfloat16 hi = __float2bfloat16(v);
    size_t idx = (size_t)(NUM_R + m) * DD + c;
    g_Hh[idx] = hi;
    g_Hl[idx] = __float2bfloat16(v - __bfloat162float(hi));
}

// sampling over fused puqz: pu(row,c)=puqz[row*1024+c]; qz(row,c)=puqz[row*1024+512+c]
__global__ void k_sample_all(unsigned ku0, unsigned ku1, unsigned kzm0, unsigned kzm1,
                             unsigned kzr0, unsigned kzr1) {
    int i = blockIdx.x * blockDim.x + threadIdx.x;
    const int NU = N_ALL * DD, NZM = NUM_M * DD, NZR = NUM_R * DD;
    if (i < NU) {
        int row = i >> 8, col = i & 255;
        g_u[i] = g_puqz[row * 1024 + col] +
                 expf(g_puqz[row * 1024 + 256 + col]) * nrm(rbits(ku0, ku1, i));
    } else if (i < NU + NZM) {
        int j = i - NU;
        int m = j >> 8, col = j & 255;
        int r = (NUM_R + m) * 1024 + 512;
        g_zM[j] = g_puqz[r + col] + expf(g_puqz[r + 256 + col]) * nrm(rbits(kzm0, kzm1, j));
    } else if (i < NU + NZM + NZR) {
        int j = i - NU - NZM;
        int r = (j >> 8) * 1024 + 512, col = j & 255;
        g_zR[j] = g_puqz[r + col] + expf(g_puqz[r + 256 + col]) * nrm(rbits(kzr0, kzr1, j));
    }
}

__global__ void k_attn(const float* __restrict__ pg, const int* __restrict__ yM,
                       unsigned k0, unsigned k1) {
    int m = blockIdx.x, r = threadIdx.x;
    __shared__ float um[DD];
    __shared__ float d2s[NUM_R];
    __shared__ float red[NUM_R];
    for (int i = r; i < DD; i += 64) um[i] = g_u[(size_t)(NUM_R + m) * DD + i];
    __syncthreads();
    float d2 = 0.f;
    const float* ur = g_u + (size_t)r * DD;
    for (int dd = 0; dd < DD; dd++) {
        float t = um[dd] - ur[dd];
        d2 = fmaf(t, t, d2);
    }
    d2s[r] = d2;
    float logp = -0.5f * d2 / expf(pg[0]);
    float logit = logp - logf(fmaxf(-expm1f(logp), 1e-20f));
    float U = unif(rbits(k0, k1, (uint32_t)(m * NUM_R + r)));
    float gn = logf(U) - log1pf(-U);
    float A = 1.0f / (1.0f + expf(-(logit + gn) / 0.3f));
    red[r] = A;
    __syncthreads();
    for (int o = 32; o >= 1; o >>= 1) {
        if (r < o) red[r] += red[r + o];
        __syncthreads();
    }
    g_An[m * NUM_R + r] = A / (red[0] + 1e-8f);
    if (r < 32) {
        int idx = r + (1 - yM[m]) * 32;
        float t = sqrtf(fmaxf(d2s[idx], 1e-12f));
        for (int o = 16; o >= 1; o >>= 1) t += __shfl_down_sync(0xffffffffu, t, o);
        if (r == 0) atomicAdd(&g_acc[3], t);
    }
}

__global__ void k_pzq() {
    int m = blockIdx.x, c = threadIdx.x;
    __shared__ float an[NUM_R];
    if (c < NUM_R) an[c] = g_An[m * NUM_R + c];
    __syncthreads();
    float pm = 0.f, pl = 0.f;
    for (int r = 0; r < NUM_R; r++) {
        float a = an[r];
        pm = fmaf(a, g_puqz[r * 1024 + 512 + c], pm);
        pl = fmaf(a, g_puqz[r * 1024 + 768 + c], pl);
    }
    float z = g_zM[m * DD + c];
    int q = (NUM_R + m) * 1024 + 512;
    float qm = g_puqz[q + c], ql = g_puqz[q + 256 + c];
    float t1 = (z - pm) * expf(-pl);
    float t2 = (z - qm) * expf(-ql);
    float v = (-pl - 0.5f * t1 * t1) - (-ql - 0.5f * t2 * t2);
    __shared__ float red[256];
    red[c] = v;
    __syncthreads();
    for (int o = 128; o >= 1; o >>= 1) {
        if (c < o) red[c] += red[c + o];
        __syncthreads();
    }
    if (c == 0) atomicAdd(&g_acc[1], red[0]);
}

// reps packed: rows 0..1023 = M, rows 1024..1087 = R
__global__ void k_reps() {
    int i = blockIdx.x * blockDim.x + threadIdx.x;
    if (i >= (NUM_M + NUM_R) * 512) return;
    int rowp = i >> 9, c = i & 511;
    float v;
    if (rowp < NUM_M) {
        v = (c < 256) ? g_zM[rowp * DD + c] : g_u[(size_t)(NUM_R + rowp) * DD + (c - 256)];
    } else {
        int r = rowp - NUM_M;
        v = (c < 256) ? g_zR[r * DD + c] : g_u[(size_t)r * DD + (c - 256)];
    }
    __nv_bfloat16 hi = __float2bfloat16(v);
    g_reph[i] = hi;
    g_repl[i] = __float2bfloat16(v - __bfloat162float(hi));
}

__global__ void k_head(const float* __restrict__ hid, const float* __restrict__ W2,
                       const float* __restrict__ b2, const int* __restrict__ y,
                       int rows, int accIdx) {
    int gw = (blockIdx.x * blockDim.x + threadIdx.x) >> 5;
    int lane = threadIdx.x & 31;
    if (gw >= rows) return;
    float p0 = 0.f, p1 = 0.f;
#pragma unroll
    for (int j = 0; j < 8; j++) {
        int k = lane + 32 * j;
        float h = hid[(size_t)gw * 256 + k];
        p0 = fmaf(h, W2[k * 2], p0);
        p1 = fmaf(h, W2[k * 2 + 1], p1);
    }
    for (int o = 16; o >= 1; o >>= 1) {
        p0 += __shfl_down_sync(0xffffffffu, p0, o);
        p1 += __shfl_down_sync(0xffffffffu, p1, o);
    }
    if (lane == 0) {
        float l0 = p0 + b2[0], l1 = p1 + b2[1];
        float mx = fmaxf(l0, l1);
        float lse = mx + logf(expf(l0 - mx) + expf(l1 - mx));
        atomicAdd(&g_acc[accIdx], ((y[gw] != 0) ? l1 : l0) - lse);
    }
}

__global__ void k_final(float* __restrict__ out) {
    float pred = -(g_acc[0] + 0.1f * g_acc[1]) / 1024.0f;
    float rat  = -g_acc[2] / 64.0f;
    float reg  = g_acc[3] / 32768.0f;
    out[0] = pred + rat - 0.1f * reg;
}

extern "C" void kernel_launch(void* const* d_in, const int* in_sizes, int n_in,
                              void* d_out, int out_size) {
    (void)in_sizes; (void)n_in; (void)out_size;
    const float* x     = (const float*)d_in[0];
    const int*   ei    = (const int*)  d_in[1];
    const int*   et    = (const int*)  d_in[2];
    const int*   batch = (const int*)  d_in[3];
    const int*   yM    = (const int*)  d_in[4];
    const int*   yR    = (const int*)  d_in[5];
    const float* HR    = (const float*)d_in[6];
    const float* nodeW = (const float*)d_in[7];
    const float* nodeB = (const float*)d_in[8];
    const float* Wr    = (const float*)d_in[9];
    const float* Wroot = (const float*)d_in[10];
    const float* gcnB  = (const float*)d_in[11];
    const float* pg    = (const float*)d_in[12];
    const float* puW   = (const float*)d_in[13];
    const float* puB   = (const float*)d_in[14];
    const float* qzW   = (const float*)d_in[15];
    const float* qzB   = (const float*)d_in[16];
    const float* W1    = (const float*)d_in[17];
    const float* b1    = (const float*)d_in[18];
    const float* W2    = (const float*)d_in[19];
    const float* b2    = (const float*)d_in[20];
    float* out = (float*)d_out;

    uint32_t ku0, ku1, ka0, ka1, kzm0, kzm1, kzr0, kzr1;
    tf2x32(0u, 42u, 0u, 0u, ku0, ku1);
    tf2x32(0u, 42u, 0u, 1u, ka0, ka1);
    tf2x32(0u, 42u, 0u, 2u, kzm0, kzm1);
    tf2x32(0u, 42u, 0u, 3u, kzr0, kzr1);

    void* p;
    cudaGetSymbolAddress(&p, g_G);      __half* G    = (__half*)p;
    cudaGetSymbolAddress(&p, g_Wfh);    __half* Wfh = (__half*)p;
    cudaGetSymbolAddress(&p, g_nWfh);   __half* nWfh = (__half*)p;
    cudaGetSymbolAddress(&p, g_xf);     __half* xf = (__half*)p;
    cudaGetSymbolAddress(&p, g_Af);     __half* Af = (__half*)p;
    cudaGetSymbolAddress(&p, g_pqWh);   __nv_bfloat16* pqWh = (__nv_bfloat16*)p;
    cudaGetSymbolAddress(&p, g_pqWl);   __nv_bfloat16* pqWl = (__nv_bfloat16*)p;
    cudaGetSymbolAddress(&p, g_w1h);    __nv_bfloat16* w1h = (__nv_bfloat16*)p;
    cudaGetSymbolAddress(&p, g_w1l);    __nv_bfloat16* w1l = (__nv_bfloat16*)p;
    cudaGetSymbolAddress(&p, g_Hh);     __nv_bfloat16* Hh  = (__nv_bfloat16*)p;
    cudaGetSymbolAddress(&p, g_Hl);     __nv_bfloat16* Hl  = (__nv_bfloat16*)p;
    cudaGetSymbolAddress(&p, g_reph);   __nv_bfloat16* reph = (__nv_bfloat16*)p;
    cudaGetSymbolAddress(&p, g_repl);   __nv_bfloat16* repl = (__nv_bfloat16*)p;
    cudaGetSymbolAddress(&p, g_bcat);   float* bcat = (float*)p;
    cudaGetSymbolAddress(&p, g_puqz);   float* puqz = (float*)p;
    cudaGetSymbolAddress(&p, g_hid);    float* hid  = (float*)p;

    static int smem_set = 0;
    if (!smem_set) {
        cudaFuncSetAttribute(k_fmma, cudaFuncAttributeMaxDynamicSharedMemorySize, 61440);
        cudaFuncSetAttribute(k_bmma, cudaFuncAttributeMaxDynamicSharedMemorySize, 122880);
        smem_set = 1;
    }

    const int PREP_TOTAL = N_NODES * D_IN + N_LAYERS * GW * 256 + 256 * D_IN +
                           1024 * 256 + 256 * 512 + 1024;

    k_zero_init<<<(N_RELS * N_NODES + 255) / 256, 256>>>();
    k_count<<<(N_EDGES + 255) / 256, 256>>>(ei, et);
    k_scan<<<1, 1024>>>();
    k_scatter<<<(N_EDGES + 255) / 256, 256>>>(ei, et);
    k_prep<<<(PREP_TOTAL + 255) / 256, 256>>>(x, nodeW, Wroot, Wr, puW, qzW, W1, puB, qzB);

    k_fmma<<<dim3(2, (N_NODES + 127) / 128), 256, 61440>>>(
        xf, nWfh, nodeB, nullptr, Af, N_NODES, 256, D_IN, 0);

    for (int l = 0; l < N_LAYERS; l++) {
        k_fmma<<<dim3(GW / 128, (N_NODES + 127) / 128), 256, 61440>>>(
            Af, Wfh + (size_t)l * GW * 256, nullptr, nullptr, G, N_NODES, GW, 256, 0);
        k_agg<<<(N_NODES * 2 * 32 + 255) / 256, 256>>>(
            gcnB + l * 256, Af, (l < N_LAYERS - 1) ? 1 : 0);
    }

    k_misc<<<(NUM_M + 1 + NUM_R * DD + 255) / 256, 256>>>(batch, HR);
    k_gmean<<<NUM_M, 256>>>();

    // fused pu|qz projection
    k_bmma<<<dim3(8, HPAD / 128), 256, 122880>>>(
        Hh, Hl, pqWh, pqWl, bcat, puqz, N_ALL, 1024, 256, 0);

    k_sample_all<<<((N_ALL + NUM_M + NUM_R) * DD + 255) / 256, 256>>>(
        ku0, ku1, kzm0, kzm1, kzr0, kzr1);

    k_attn<<<NUM_M, 64>>>(pg, yM, ka0, ka1);
    k_pzq<<<NUM_M, 256>>>();

    k_reps<<<((NUM_M + NUM_R) * 512 + 255) / 256, 256>>>();
    k_bmma<<<dim3(2, HPAD / 128), 256, 122880>>>(
        reph, repl, w1h, w1l, b1, hid, NUM_M + NUM_R, 256, 512, 1);
    k_head<<<(NUM_M * 32 + 255) / 256, 256>>>(hid, W2, b2, yM, NUM_M, 0);
    k_head<<<(NUM_R * 32 + 255) / 256, 256>>>(hid + (size_t)NUM_M * 256, W2, b2, yR, NUM_R, 2);

    k_final<<<1, 1>>>(out);
}